// round 12
// baseline (speedup 1.0000x reference)
#include <cuda_runtime.h>
#include <cuda_fp16.h>
#include <math.h>
#include <stdint.h>

#define NTOK 8192
#define DM   768
#define NE   8
#define NKA  16384
#define HF   2048
#define CAPC 4096
#define MROW 24576
#define QKVW 2304
#define MAXT 136

#define NSTG  4
#define STGH  5120                 // 128*40 halves per matrix per stage
#define SMEMB (2 * NSTG * STGH * 2)  // 81920 bytes

// ---------------- scratch ----------------
__device__ float g_router_sum[NE];
__device__ float g_assign_sum[NE];
__device__ float g_z2;
__device__ int   g_counts[NE];
__device__ int   g_fill[NE];
__device__ int   g_offsets[NE];
__device__ int   g_keepcnt;
__device__ int   g_te[NKA];
__device__ float g_prio[NKA];
__device__ float g_tpk[NKA];
__device__ float g_keep[NKA];
__device__ int   g_idx_list[NKA];
__device__ int   g_tile_e[MAXT];
__device__ int   g_tile_r0[MAXT];
__device__ int   g_tile_rows[MAXT];
__device__ int   g_ntiles;

__device__ float  g_tokens[(size_t)MROW * DM];
__device__ __half g_tokh[(size_t)MROW * DM];
__device__ __half g_acth[(size_t)(NKA + 128) * HF];
__device__ __half g_qkvh[(size_t)MROW * QKVW];
__device__ __half g_attnh[(size_t)MROW * DM];
__device__ __half g_uh[(size_t)MROW * DM];
__device__ __half g_hh[(size_t)MROW * DM];
__device__ __half g_fmh[(size_t)NTOK * DM];

__device__ __half g_xh[(size_t)NTOK * DM];              // 2*x
__device__ __half g_w13h[(size_t)NE * 2 * HF * DM];     // rows interleaved g/u
__device__ __half g_w2h[(size_t)NE * DM * HF];
__device__ __half g_ipwh[(size_t)QKVW * DM];
__device__ __half g_owh[(size_t)DM * DM];
__device__ __half g_f1h[(size_t)DM * DM];
__device__ __half g_f2h[(size_t)DM * DM];
__device__ __half g_oph[(size_t)DM * DM];

// ---------------- helpers ----------------
__device__ __forceinline__ uint32_t h2u(float a, float b) {
    __half2 h = __floats2half2_rn(a, b);
    return *(uint32_t*)&h;
}

__device__ __forceinline__ void cp16(void* smem, const void* gmem) {
    uint32_t s = (uint32_t)__cvta_generic_to_shared(smem);
    asm volatile("cp.async.cg.shared.global [%0], [%1], 16;" :: "r"(s), "l"(gmem));
}
#define CP_COMMIT() asm volatile("cp.async.commit_group;" ::: "memory")
#define CP_WAIT2()  asm volatile("cp.async.wait_group 2;" ::: "memory")

__device__ __forceinline__ void mma16(float* c, const uint32_t* a, const uint32_t* b) {
    asm volatile(
        "mma.sync.aligned.m16n8k16.row.col.f32.f16.f16.f32 "
        "{%0,%1,%2,%3},{%4,%5,%6,%7},{%8,%9},{%0,%1,%2,%3};"
        : "+f"(c[0]), "+f"(c[1]), "+f"(c[2]), "+f"(c[3])
        : "r"(a[0]), "r"(a[1]), "r"(a[2]), "r"(a[3]), "r"(b[0]), "r"(b[1]));
}

// one 128x128x32 tile: 8 warps, warp tile 64x32, 2 k-steps of 16
__device__ __forceinline__ void mma_tile_h(const __half* As, const __half* Bs,
                                           float acc[4][4][4], int lane, int warpM, int warpN) {
    int lr = lane >> 2, lq = (lane & 3) * 2;
    #pragma unroll
    for (int ks = 0; ks < 2; ks++) {
        int kb = ks * 16 + lq;
        uint32_t a[4][4], b[4][2];
        #pragma unroll
        for (int mf = 0; mf < 4; mf++) {
            int rb = warpM * 64 + mf * 16 + lr;
            a[mf][0] = *(const uint32_t*)(As + rb * 40 + kb);
            a[mf][1] = *(const uint32_t*)(As + (rb + 8) * 40 + kb);
            a[mf][2] = *(const uint32_t*)(As + rb * 40 + kb + 8);
            a[mf][3] = *(const uint32_t*)(As + (rb + 8) * 40 + kb + 8);
        }
        #pragma unroll
        for (int nf = 0; nf < 4; nf++) {
            int cb = warpN * 32 + nf * 8 + lr;
            b[nf][0] = *(const uint32_t*)(Bs + cb * 40 + kb);
            b[nf][1] = *(const uint32_t*)(Bs + cb * 40 + kb + 8);
        }
        #pragma unroll
        for (int mf = 0; mf < 4; mf++)
            #pragma unroll
            for (int nf = 0; nf < 4; nf++)
                mma16(acc[mf][nf], a[mf], b[nf]);
    }
}

// ---------------- generic NT GEMM (fp16, 4-stage cp.async pipeline) ----------------
template<bool BIAS, bool RES, bool GELU, bool HOUT, bool MIRROR>
__global__ void __launch_bounds__(256) gemm_h(
    const __half* __restrict__ A, const __half* __restrict__ B,
    const float* __restrict__ bias, const float* __restrict__ res,
    void* __restrict__ Cv, __half* __restrict__ mirror, int N, int K)
{
    extern __shared__ __half sm[];
    __half* As = sm;
    __half* Bs = sm + NSTG * STGH;
    int tid = threadIdx.x, lane = tid & 31, warp = tid >> 5;
    int warpM = warp >> 2, warpN = warp & 3;
    size_t m0 = (size_t)blockIdx.x * 128;
    int n0 = blockIdx.y * 128;
    const __half* Ab = A + m0 * K;
    const __half* Bb = B + (size_t)n0 * K;
    float acc[4][4][4] = {};
    int r0w = tid >> 2, c8 = (tid & 3) * 8;
    int r1w = r0w + 64;
    int nch = K >> 5;

    #pragma unroll
    for (int p = 0; p < NSTG - 1; p++) {
        int kk = p * 32;
        cp16(&As[p * STGH + r0w * 40 + c8], Ab + (size_t)r0w * K + kk + c8);
        cp16(&As[p * STGH + r1w * 40 + c8], Ab + (size_t)r1w * K + kk + c8);
        cp16(&Bs[p * STGH + r0w * 40 + c8], Bb + (size_t)r0w * K + kk + c8);
        cp16(&Bs[p * STGH + r1w * 40 + c8], Bb + (size_t)r1w * K + kk + c8);
        CP_COMMIT();
    }

    int s = 0, sl = NSTG - 1;
    for (int c = 0; c < nch; c++) {
        CP_WAIT2();
        __syncthreads();
        if (c + NSTG - 1 < nch) {
            int kk = (c + NSTG - 1) * 32;
            cp16(&As[sl * STGH + r0w * 40 + c8], Ab + (size_t)r0w * K + kk + c8);
            cp16(&As[sl * STGH + r1w * 40 + c8], Ab + (size_t)r1w * K + kk + c8);
            cp16(&Bs[sl * STGH + r0w * 40 + c8], Bb + (size_t)r0w * K + kk + c8);
            cp16(&Bs[sl * STGH + r1w * 40 + c8], Bb + (size_t)r1w * K + kk + c8);
        }
        CP_COMMIT();
        mma_tile_h(As + s * STGH, Bs + s * STGH, acc, lane, warpM, warpN);
        if (++s == NSTG) s = 0;
        if (++sl == NSTG) sl = 0;
    }

    int lr = lane >> 2, lc = (lane & 3) * 2;
    #pragma unroll
    for (int mf = 0; mf < 4; mf++)
        #pragma unroll
        for (int h = 0; h < 2; h++) {
            size_t m = m0 + warpM * 64 + mf * 16 + lr + h * 8;
            #pragma unroll
            for (int nf = 0; nf < 4; nf++) {
                int col = n0 + warpN * 32 + nf * 8 + lc;
                float v0 = acc[mf][nf][h * 2], v1 = acc[mf][nf][h * 2 + 1];
                if (BIAS) { v0 += bias[col]; v1 += bias[col + 1]; }
                if (RES)  { v0 += res[m * N + col]; v1 += res[m * N + col + 1]; }
                if (GELU) {
                    v0 = 0.5f * v0 * (1.f + erff(v0 * 0.70710678118654752f));
                    v1 = 0.5f * v1 * (1.f + erff(v1 * 0.70710678118654752f));
                }
                if (HOUT) {
                    *(__half2*)((__half*)Cv + m * N + col) = __floats2half2_rn(v0, v1);
                } else {
                    *(float2*)((float*)Cv + m * N + col) = make_float2(v0, v1);
                    if (MIRROR)
                        *(__half2*)(mirror + m * N + col) = __floats2half2_rn(v0, v1);
                }
            }
        }
}

// ---------------- expert pass A: fused gu GEMM + SiLU ----------------
__global__ void __launch_bounds__(256) expA_h()
{
    int t = blockIdx.x;
    if (t >= g_ntiles) return;
    extern __shared__ __half sm[];
    __half* As = sm;
    __half* Bs = sm + NSTG * STGH;
    __shared__ int tok[128];
    int tid = threadIdx.x, lane = tid & 31, warp = tid >> 5;
    int warpM = warp >> 2, warpN = warp & 3;
    int e = g_tile_e[t], r0 = g_tile_r0[t], rows = g_tile_rows[t];
    int n0 = blockIdx.y * 128;
    if (tid < 128) tok[tid] = (tid < rows) ? (g_idx_list[r0 + tid] >> 1) : 0;
    __syncthreads();
    const __half* Bb = g_w13h + (size_t)e * 2 * HF * DM + (size_t)n0 * DM;
    float acc[4][4][4] = {};
    int r0w = tid >> 2, c8 = (tid & 3) * 8;
    int r1w = r0w + 64;
    const __half* a0p = g_xh + (size_t)tok[r0w] * DM;
    const __half* a1p = g_xh + (size_t)tok[r1w] * DM;
    int nch = DM >> 5;

    #pragma unroll
    for (int p = 0; p < NSTG - 1; p++) {
        int kk = p * 32;
        cp16(&As[p * STGH + r0w * 40 + c8], a0p + kk + c8);
        cp16(&As[p * STGH + r1w * 40 + c8], a1p + kk + c8);
        cp16(&Bs[p * STGH + r0w * 40 + c8], Bb + (size_t)r0w * DM + kk + c8);
        cp16(&Bs[p * STGH + r1w * 40 + c8], Bb + (size_t)r1w * DM + kk + c8);
        CP_COMMIT();
    }

    int s = 0, sl = NSTG - 1;
    for (int c = 0; c < nch; c++) {
        CP_WAIT2();
        __syncthreads();
        if (c + NSTG - 1 < nch) {
            int kk = (c + NSTG - 1) * 32;
            cp16(&As[sl * STGH + r0w * 40 + c8], a0p + kk + c8);
            cp16(&As[sl * STGH + r1w * 40 + c8], a1p + kk + c8);
            cp16(&Bs[sl * STGH + r0w * 40 + c8], Bb + (size_t)r0w * DM + kk + c8);
            cp16(&Bs[sl * STGH + r1w * 40 + c8], Bb + (size_t)r1w * DM + kk + c8);
        }
        CP_COMMIT();
        mma_tile_h(As + s * STGH, Bs + s * STGH, acc, lane, warpM, warpN);
        if (++s == NSTG) s = 0;
        if (++sl == NSTG) sl = 0;
    }

    int lr = lane >> 2, lc = (lane & 3) * 2;
    int hbase = blockIdx.y * 64;
    #pragma unroll
    for (int mf = 0; mf < 4; mf++)
        #pragma unroll
        for (int h = 0; h < 2; h++) {
            int rl = warpM * 64 + mf * 16 + lr + h * 8;
            if (rl < rows) {
                __half* ap = g_acth + (size_t)(r0 + rl) * HF + hbase;
                #pragma unroll
                for (int nf = 0; nf < 4; nf++) {
                    int colt = warpN * 32 + nf * 8 + lc;
                    float g = acc[mf][nf][h * 2];
                    float u = acc[mf][nf][h * 2 + 1];
                    ap[colt >> 1] = __float2half_rn(g / (1.f + expf(-g)) * u);
                }
            }
        }
}

// ---------------- expert pass B ----------------
__global__ void __launch_bounds__(256) expB_h(const float* __restrict__ x)
{
    int t = blockIdx.x;
    if (t >= g_ntiles) return;
    extern __shared__ __half sm[];
    __half* As = sm;
    __half* Bs = sm + NSTG * STGH;
    __shared__ int s_asn[128];
    int tid = threadIdx.x, lane = tid & 31, warp = tid >> 5;
    int warpM = warp >> 2, warpN = warp & 3;
    int e = g_tile_e[t], r0 = g_tile_r0[t], rows = g_tile_rows[t];
    int n0 = blockIdx.y * 128;
    if (tid < 128) s_asn[tid] = (tid < rows) ? g_idx_list[r0 + tid] : 0;
    const __half* Ab = g_acth + (size_t)r0 * HF;
    const __half* Bb = g_w2h + (size_t)e * DM * HF + (size_t)n0 * HF;
    float acc[4][4][4] = {};
    int r0w = tid >> 2, c8 = (tid & 3) * 8;
    int r1w = r0w + 64;
    int nch = HF >> 5;

    #pragma unroll
    for (int p = 0; p < NSTG - 1; p++) {
        int kk = p * 32;
        cp16(&As[p * STGH + r0w * 40 + c8], Ab + (size_t)r0w * HF + kk + c8);
        cp16(&As[p * STGH + r1w * 40 + c8], Ab + (size_t)r1w * HF + kk + c8);
        cp16(&Bs[p * STGH + r0w * 40 + c8], Bb + (size_t)r0w * HF + kk + c8);
        cp16(&Bs[p * STGH + r1w * 40 + c8], Bb + (size_t)r1w * HF + kk + c8);
        CP_COMMIT();
    }

    int s = 0, sl = NSTG - 1;
    for (int c = 0; c < nch; c++) {
        CP_WAIT2();
        __syncthreads();
        if (c + NSTG - 1 < nch) {
            int kk = (c + NSTG - 1) * 32;
            cp16(&As[sl * STGH + r0w * 40 + c8], Ab + (size_t)r0w * HF + kk + c8);
            cp16(&As[sl * STGH + r1w * 40 + c8], Ab + (size_t)r1w * HF + kk + c8);
            cp16(&Bs[sl * STGH + r0w * 40 + c8], Bb + (size_t)r0w * HF + kk + c8);
            cp16(&Bs[sl * STGH + r1w * 40 + c8], Bb + (size_t)r1w * HF + kk + c8);
        }
        CP_COMMIT();
        mma_tile_h(As + s * STGH, Bs + s * STGH, acc, lane, warpM, warpN);
        if (++s == NSTG) s = 0;
        if (++sl == NSTG) sl = 0;
    }

    int lr = lane >> 2, lc = (lane & 3) * 2;
    #pragma unroll
    for (int mf = 0; mf < 4; mf++)
        #pragma unroll
        for (int h = 0; h < 2; h++) {
            int rl = warpM * 64 + mf * 16 + lr + h * 8;
            if (rl < rows) {
                int a = s_asn[rl];
                int n = a >> 1, slot = a & 1;
                float kp = g_keep[a];
                const float* xr = x + (size_t)n * DM + n0;
                size_t base = ((size_t)n * 3 + slot) * DM + n0;
                #pragma unroll
                for (int nf = 0; nf < 4; nf++) {
                    int col = warpN * 32 + nf * 8 + lc;
                    float v0 = kp * (xr[col]     + acc[mf][nf][h * 2]);
                    float v1 = kp * (xr[col + 1] + acc[mf][nf][h * 2 + 1]);
                    *(float2*)(g_tokens + base + col) = make_float2(v0, v1);
                    *(__half2*)(g_tokh + base + col) = __floats2half2_rn(v0, v1);
                }
            }
        }
}

// ---------------- combined cvt: w13 (interleaved) + x (alpha=2) ----------------
#define W13_U4 ((size_t)NE * 2 * HF * DM / 8)
#define X_U4   ((size_t)NTOK * DM / 8)
__global__ void cvt_combined_kernel(const float* __restrict__ w13,
                                    const float* __restrict__ x) {
    size_t j = (size_t)blockIdx.x * 256 + threadIdx.x;
    if (j < W13_U4) {
        size_t per_e = (size_t)2 * HF * DM / 8;
        size_t e = j / per_e;
        size_t rem = j - e * per_e;
        int rp = (int)(rem / (DM / 8));
        int d8 = (int)(rem % (DM / 8));
        int h = rp >> 1;
        int src = (rp & 1) ? (HF + h) : h;
        const float* sp = w13 + (size_t)e * 2 * HF * DM + (size_t)src * DM + d8 * 8;
        float4 v0 = *(const float4*)sp;
        float4 v1 = *(const float4*)(sp + 4);
        uint4 o;
        o.x = h2u(v0.x, v0.y); o.y = h2u(v0.z, v0.w);
        o.z = h2u(v1.x, v1.y); o.w = h2u(v1.z, v1.w);
        ((uint4*)g_w13h)[j] = o;
    } else if (j < W13_U4 + X_U4) {
        size_t i = j - W13_U4;
        const float* sp = x + i * 8;
        float4 v0 = *(const float4*)sp;
        float4 v1 = *(const float4*)(sp + 4);
        uint4 o;
        o.x = h2u(2.f * v0.x, 2.f * v0.y); o.y = h2u(2.f * v0.z, 2.f * v0.w);
        o.z = h2u(2.f * v1.x, 2.f * v1.y); o.w = h2u(2.f * v1.z, 2.f * v1.w);
        ((uint4*)g_xh)[i] = o;
    }
}

__global__ void cvth_kernel(const float* __restrict__ sIn, __half* __restrict__ d,
                            int n4, float alpha) {
    int i = blockIdx.x * 256 + threadIdx.x;
    if (i >= n4) return;
    float4 v = ((const float4*)sIn)[i];
    ((uint2*)d)[i] = make_uint2(h2u(alpha * v.x, alpha * v.y), h2u(alpha * v.z, alpha * v.w));
}

// ---------------- small kernels ----------------
__global__ void zero_accum_kernel() {
    int t = threadIdx.x;
    if (t < NE) { g_router_sum[t] = 0.f; g_assign_sum[t] = 0.f; g_counts[t] = 0; g_fill[t] = 0; }
    if (t == 0) { g_z2 = 0.f; g_keepcnt = 0; }
}

__global__ void med_init_kernel(const float* __restrict__ mediator) {
    size_t total = (size_t)NTOK * DM;
    for (size_t i = blockIdx.x * blockDim.x + threadIdx.x; i < total; i += (size_t)gridDim.x * blockDim.x) {
        size_t n = i / DM;
        size_t d = i - n * DM;
        float v = mediator[d];
        g_tokens[(n * 3 + 2) * DM + d] = v;
        g_tokh[(n * 3 + 2) * DM + d] = __float2half_rn(v);
    }
}

__global__ void __launch_bounds__(256) gate_kernel(const float* __restrict__ x,
                                                   const float* __restrict__ gw,
                                                   float* __restrict__ out) {
    __shared__ float wsh[NE * DM];
    __shared__ float s_rs[NE], s_as[NE], s_z2s;
    __shared__ int   s_c[NE];
    int tid = threadIdx.x;
    for (int i = tid; i < NE * DM; i += 256) wsh[i] = gw[i];
    if (tid < NE) { s_rs[tid] = 0.f; s_as[tid] = 0.f; s_c[tid] = 0; }
    if (tid == 0) s_z2s = 0.f;
    __syncthreads();
    int warp = tid >> 5, lane = tid & 31;
    int n = blockIdx.x * 8 + warp;
    const float* xr = x + (size_t)n * DM;
    float xv[24];
    #pragma unroll
    for (int i = 0; i < 24; i++) xv[i] = xr[lane + i * 32];
    float l[NE];
    #pragma unroll
    for (int e = 0; e < NE; e++) {
        float sv = 0.f;
        const float* w = wsh + e * DM;
        #pragma unroll
        for (int i = 0; i < 24; i++) sv += xv[i] * w[lane + i * 32];
        #pragma unroll
        for (int o = 16; o; o >>= 1) sv += __shfl_xor_sync(0xffffffffu, sv, o);
        l[e] = sv;
    }
    if (lane == 0) {
        int i1 = 0; float v1 = l[0];
        #pragma unroll
        for (int e = 1; e < NE; e++) if (l[e] > v1) { v1 = l[e]; i1 = e; }
        int i2 = -1; float v2 = -3.4e38f;
        #pragma unroll
        for (int e = 0; e < NE; e++) if (e != i1 && l[e] > v2) { v2 = l[e]; i2 = e; }
        float e2 = expf(v2 - v1);
        float inv = 1.f / (1.f + e2);
        float p1 = inv, p2 = e2 * inv;
        float se = 0.f;
        #pragma unroll
        for (int e = 0; e < NE; e++) se += expf(l[e] - v1);
        float z = v1 + logf(se);
        #pragma unroll
        for (int e = 0; e < NE; e++) atomicAdd(&s_rs[e], expf(l[e] - v1) / se);
        atomicAdd(&s_as[i1], p1);
        atomicAdd(&s_as[i2], p2);
        atomicAdd(&s_z2s, z * z);
        atomicAdd(&s_c[i1], 1);
        atomicAdd(&s_c[i2], 1);
        g_te[2 * n] = i1; g_te[2 * n + 1] = i2;
        g_prio[2 * n] = v1; g_prio[2 * n + 1] = v2;
        g_tpk[2 * n] = p1; g_tpk[2 * n + 1] = p2;
        out[(size_t)NTOK * DM + 1 + 2 * n]     = (float)i1;
        out[(size_t)NTOK * DM + 1 + 2 * n + 1] = (float)i2;
    }
    __syncthreads();
    if (tid < NE) {
        atomicAdd(&g_router_sum[tid], s_rs[tid]);
        atomicAdd(&g_assign_sum[tid], s_as[tid]);
        atomicAdd(&g_counts[tid], s_c[tid]);
    }
    if (tid == 0) atomicAdd(&g_z2, s_z2s);
}

__global__ void build_tiles_kernel() {
    if (threadIdx.x != 0 || blockIdx.x != 0) return;
    int off = 0, nt = 0;
    for (int e = 0; e < NE; e++) {
        g_offsets[e] = off;
        int c = g_counts[e];
        int ntile = (c + 127) >> 7;
        for (int t = 0; t < ntile; t++) {
            g_tile_e[nt] = e;
            g_tile_r0[nt] = off + t * 128;
            int r = c - t * 128;
            g_tile_rows[nt] = r < 128 ? r : 128;
            nt++;
        }
        off += c;
    }
    g_ntiles = nt;
}

__global__ void scatter_kernel() {
    int i = blockIdx.x * 256 + threadIdx.x;
    if (i >= NKA) return;
    int e = g_te[i];
    int p = atomicAdd(&g_fill[e], 1);
    g_idx_list[g_offsets[e] + p] = i;
}

__global__ void keep_kernel() {
    int i = blockIdx.x * 256 + threadIdx.x;
    if (i >= NKA) return;
    int e = g_te[i];
    int kp;
    if (g_counts[e] <= CAPC) {
        kp = 1;
    } else {
        float pi = g_prio[i];
        int rank = 0;
        for (int j = 0; j < NKA; j++) {
            if (g_te[j] == e) {
                float pj = g_prio[j];
                if (pj > pi || (pj == pi && j < i)) rank++;
            }
        }
        kp = (rank < CAPC) ? 1 : 0;
    }
    g_keep[i] = (float)kp;
    atomicAdd(&g_keepcnt, kp);
}

__global__ void attn_kernel() {
    int n = blockIdx.x;
    int h = threadIdx.x >> 5, lane = threadIdx.x & 31;
    const __half* base = g_qkvh + (size_t)n * 3 * QKVW;
    float q[3][6], k[3][6], v[3][6];
    #pragma unroll
    for (int li = 0; li < 3; li++) {
        const __half* bp = base + (size_t)li * QKVW + h * 192 + lane * 6;
        #pragma unroll
        for (int dd = 0; dd < 6; dd++) {
            q[li][dd] = __half2float(bp[dd]);
            k[li][dd] = __half2float(bp[dd + DM]);
            v[li][dd] = __half2float(bp[dd + 2 * DM]);
        }
    }
    const float scale = 0.07216878364870322f;
    float b0 = (g_keep[2 * n]     > 0.5f) ? 0.f : -1e9f;
    float b1 = (g_keep[2 * n + 1] > 0.5f) ? 0.f : -1e9f;
    float s[3][3];
    #pragma unroll
    for (int qi = 0; qi < 3; qi++) {
        #pragma unroll
        for (int kj = 0; kj < 3; kj++) {
            float t = 0.f;
            #pragma unroll
            for (int dd = 0; dd < 6; dd++) t += q[qi][dd] * k[kj][dd];
            #pragma unroll
            for (int o = 16; o; o >>= 1) t += __shfl_xor_sync(0xffffffffu, t, o);
            s[qi][kj] = t * scale;
        }
        s[qi][0] += b0;
        s[qi][1] += b1;
    }
    #pragma unroll
    for (int qi = 0; qi < 3; qi++) {
        float m = fmaxf(s[qi][0], fmaxf(s[qi][1], s[qi][2]));
        float e0 = expf(s[qi][0] - m), e1 = expf(s[qi][1] - m), e2 = expf(s[qi][2] - m);
        float inv = 1.f / (e0 + e1 + e2);
        float a0 = e0 * inv, a1 = e1 * inv, a2 = e2 * inv;
        __half* op = g_attnh + (size_t)(n * 3 + qi) * DM + h * 192 + lane * 6;
        #pragma unroll
        for (int dd = 0; dd < 6; dd++)
            op[dd] = __float2half_rn(a0 * v[0][dd] + a1 * v[1][dd] + a2 * v[2][dd]);
    }
}

__global__ void rms_dual_kernel(const float* __restrict__ w1, const float* __restrict__ w2) {
    __shared__ float sh[8];
    __shared__ float sscale;
    int m = blockIdx.x, tid = threadIdx.x;
    float* row = g_tokens + (size_t)m * DM;
    float v0 = row[tid], v1 = row[tid + 256], v2 = row[tid + 512];
    float ss = v0 * v0 + v1 * v1 + v2 * v2;
    #pragma unroll
    for (int o = 16; o; o >>= 1) ss += __shfl_xor_sync(0xffffffffu, ss, o);
    if ((tid & 31) == 0) sh[tid >> 5] = ss;
    __syncthreads();
    if (tid == 0) {
        float t = 0.f;
        #pragma unroll
        for (int i = 0; i < 8; i++) t += sh[i];
        sscale = rsqrtf(t * (1.f / DM) + 1e-6f);
    }
    __syncthreads();
    float s1 = sscale;
    float t0 = v0 * s1 * w1[tid];
    float t1 = v1 * s1 * w1[tid + 256];
    float t2 = v2 * s1 * w1[tid + 512];
    row[tid] = t0; row[tid + 256] = t1; row[tid + 512] = t2;
    float ss2 = t0 * t0 + t1 * t1 + t2 * t2;
    #pragma unroll
    for (int o = 16; o; o >>= 1) ss2 += __shfl_xor_sync(0xffffffffu, ss2, o);
    __syncthreads();
    if ((tid & 31) == 0) sh[tid >> 5] = ss2;
    __syncthreads();
    if (tid == 0) {
        float t = 0.f;
        #pragma unroll
        for (int i = 0; i < 8; i++) t += sh[i];
        sscale = rsqrtf(t * (1.f / DM) + 1e-6f);
    }
    __syncthreads();
    float s2 = sscale;
    __half* ur = g_uh + (size_t)m * DM;
    ur[tid]       = __float2half_rn(t0 * s2 * w2[tid]);
    ur[tid + 256] = __float2half_rn(t1 * s2 * w2[tid + 256]);
    ur[tid + 512] = __float2half_rn(t2 * s2 * w2[tid + 512]);
}

__global__ void fuse_prep_kernel(const float* __restrict__ fgw, const float* __restrict__ fgb) {
    __shared__ float sh[8];
    __shared__ float par[3];
    int n = blockIdx.x, tid = threadIdx.x;
    const float* med = g_tokens + ((size_t)n * 3 + 2) * DM;
    float s = med[tid] * fgw[tid] + med[tid + 256] * fgw[tid + 256] + med[tid + 512] * fgw[tid + 512];
    #pragma unroll
    for (int o = 16; o; o >>= 1) s += __shfl_xor_sync(0xffffffffu, s, o);
    if ((tid & 31) == 0) sh[tid >> 5] = s;
    __syncthreads();
    if (tid == 0) {
        float t = 0.f;
        #pragma unroll
        for (int i = 0; i < 8; i++) t += sh[i];
        float g = 1.f / (1.f + expf(-(t + fgb[0])));
        float tp0 = g_tpk[2 * n] * g_keep[2 * n];
        float tp1 = g_tpk[2 * n + 1] * g_keep[2 * n + 1];
        float den = tp0 + tp1;
        par[0] = g;
        par[1] = den > 0.f ? tp0 / den : 0.f;
        par[2] = den > 0.f ? tp1 / den : 0.f;
    }
    __syncthreads();
    float g = par[0], w0 = par[1], w1 = par[2];
    const float* e0 = g_tokens + ((size_t)n * 3 + 0) * DM;
    const float* e1 = g_tokens + ((size_t)n * 3 + 1) * DM;
    __half* fm = g_fmh + (size_t)n * DM;
    #pragma unroll
    for (int c = 0; c < 3; c++) {
        int d = tid + c * 256;
        fm[d] = __float2half_rn(g * med[d] + (1.f - g) * (w0 * e0[d] + w1 * e1[d]));
    }
}

__global__ void aux_kernel(float* __restrict__ out) {
    if (threadIdx.x != 0 || blockIdx.x != 0) return;
    float bal = 0.f;
    for (int e = 0; e < NE; e++)
        bal += (g_router_sum[e] / (float)NTOK) * (g_assign_sum[e] / (float)NTOK);
    bal *= (float)NE;
    float aux = 0.01f * bal + 0.001f * (g_z2 / (float)NTOK)
              + 0.001f * (1.f - (float)g_keepcnt / (float)NKA);
    out[(size_t)NTOK * DM] = aux;
}

// ---------------- launch ----------------
extern "C" void kernel_launch(void* const* d_in, const int* in_sizes, int n_in,
                              void* d_out, int out_size) {
    const float* x          = (const float*)d_in[0];
    const float* gate_w     = (const float*)d_in[1];
    const float* w13        = (const float*)d_in[2];
    const float* w2         = (const float*)d_in[3];
    const float* in_proj_w  = (const float*)d_in[4];
    const float* in_proj_b  = (const float*)d_in[5];
    const float* out_w      = (const float*)d_in[6];
    const float* out_b      = (const float*)d_in[7];
    const float* norm1_w    = (const float*)d_in[8];
    const float* norm2_w    = (const float*)d_in[9];
    const float* ffn_w1     = (const float*)d_in[10];
    const float* ffn_w2     = (const float*)d_in[11];
    const float* mediator   = (const float*)d_in[12];
    const float* fuse_gate_w= (const float*)d_in[13];
    const float* fuse_gate_b= (const float*)d_in[14];
    const float* o_proj_w   = (const float*)d_in[15];
    float* out = (float*)d_out;

    float* p_tokens;
    __half *p_tokh, *p_w2h, *p_ipwh, *p_owh, *p_f1h, *p_f2h, *p_oph;
    __half *p_qkvh, *p_attnh, *p_uh, *p_hh, *p_fmh;
    cudaGetSymbolAddress((void**)&p_tokens, g_tokens);
    cudaGetSymbolAddress((void**)&p_tokh, g_tokh);
    cudaGetSymbolAddress((void**)&p_w2h, g_w2h);
    cudaGetSymbolAddress((void**)&p_ipwh, g_ipwh);
    cudaGetSymbolAddress((void**)&p_owh, g_owh);
    cudaGetSymbolAddress((void**)&p_f1h, g_f1h);
    cudaGetSymbolAddress((void**)&p_f2h, g_f2h);
    cudaGetSymbolAddress((void**)&p_oph, g_oph);
    cudaGetSymbolAddress((void**)&p_qkvh, g_qkvh);
    cudaGetSymbolAddress((void**)&p_attnh, g_attnh);
    cudaGetSymbolAddress((void**)&p_uh, g_uh);
    cudaGetSymbolAddress((void**)&p_hh, g_hh);
    cudaGetSymbolAddress((void**)&p_fmh, g_fmh);

    cudaFuncSetAttribute(gemm_h<true,  false, false, true,  false>, cudaFuncAttributeMaxDynamicSharedMemorySize, SMEMB);
    cudaFuncSetAttribute(gemm_h<true,  true,  false, false, false>, cudaFuncAttributeMaxDynamicSharedMemorySize, SMEMB);
    cudaFuncSetAttribute(gemm_h<false, false, true,  true,  false>, cudaFuncAttributeMaxDynamicSharedMemorySize, SMEMB);
    cudaFuncSetAttribute(gemm_h<false, true,  false, false, true >, cudaFuncAttributeMaxDynamicSharedMemorySize, SMEMB);
    cudaFuncSetAttribute(gemm_h<false, false, false, false, false>, cudaFuncAttributeMaxDynamicSharedMemorySize, SMEMB);
    cudaFuncSetAttribute(expA_h, cudaFuncAttributeMaxDynamicSharedMemorySize, SMEMB);
    cudaFuncSetAttribute(expB_h, cudaFuncAttributeMaxDynamicSharedMemorySize, SMEMB);

    zero_accum_kernel<<<1, 32>>>();
    cvt_combined_kernel<<<(int)((W13_U4 + X_U4 + 255) / 256), 256>>>(w13, x);
    gate_kernel<<<NTOK / 8, 256>>>(x, gate_w, out);
    build_tiles_kernel<<<1, 1>>>();
    scatter_kernel<<<NKA / 256, 256>>>();
    expA_h<<<dim3(MAXT, 2 * HF / 128), 256, SMEMB>>>();

    keep_kernel<<<NKA / 256, 256>>>();
    cvth_kernel<<<(NE * DM * HF / 4 + 255) / 256, 256>>>(w2, p_w2h, NE * DM * HF / 4, 1.f);
    med_init_kernel<<<2048, 256>>>(mediator);
    expB_h<<<dim3(MAXT, DM / 128), 256, SMEMB>>>(x);

    cvth_kernel<<<(QKVW * DM / 4 + 255) / 256, 256>>>(in_proj_w, p_ipwh, QKVW * DM / 4, 1.f);
    cvth_kernel<<<(DM * DM / 4 + 255) / 256, 256>>>(out_w, p_owh, DM * DM / 4, 1.f);
    cvth_kernel<<<(DM * DM / 4 + 255) / 256, 256>>>(ffn_w1, p_f1h, DM * DM / 4, 1.f);
    cvth_kernel<<<(DM * DM / 4 + 255) / 256, 256>>>(ffn_w2, p_f2h, DM * DM / 4, 1.f);
    cvth_kernel<<<(DM * DM / 4 + 255) / 256, 256>>>(o_proj_w, p_oph, DM * DM / 4, 1.f);

    for (int step = 0; step < 2; step++) {
        gemm_h<true, false, false, true, false><<<dim3(MROW / 128, QKVW / 128), 256, SMEMB>>>(
            p_tokh, p_ipwh, in_proj_b, nullptr, p_qkvh, nullptr, QKVW, DM);
        attn_kernel<<<NTOK, 128>>>();
        gemm_h<true, true, false, false, false><<<dim3(MROW / 128, DM / 128), 256, SMEMB>>>(
            p_attnh, p_owh, out_b, p_tokens, p_tokens, nullptr, DM, DM);
        rms_dual_kernel<<<MROW, 256>>>(norm1_w, norm2_w);
        gemm_h<false, false, true, true, false><<<dim3(MROW / 128, DM / 128), 256, SMEMB>>>(
            p_uh, p_f1h, nullptr, nullptr, p_hh, nullptr, DM, DM);
        gemm_h<false, true, false, false, true><<<dim3(MROW / 128, DM / 128), 256, SMEMB>>>(
            p_hh, p_f2h, nullptr, p_tokens, p_tokens, p_tokh, DM, DM);
    }

    fuse_prep_kernel<<<NTOK, 256>>>(fuse_gate_w, fuse_gate_b);
    gemm_h<false, false, false, false, false><<<dim3(NTOK / 128, DM / 128), 256, SMEMB>>>(
        p_fmh, p_oph, nullptr, nullptr, out, nullptr, DM, DM);
    aux_kernel<<<1, 1>>>(out);
}

// round 13
// speedup vs baseline: 1.0144x; 1.0144x over previous
#include <cuda_runtime.h>
#include <cuda_fp16.h>
#include <math.h>
#include <stdint.h>

#define NTOK 8192
#define DM   768
#define NE   8
#define NKA  16384
#define HF   2048
#define CAPC 4096
#define MROW 24576
#define QKVW 2304
#define MAXT 136

#define STGH  5120                 // 128*40 halves per matrix per stage
#define SMEMB (6 * STGH * 2)       // 3 stages x (A+B) = 61440 bytes

// ---------------- scratch ----------------
__device__ float g_router_sum[NE];
__device__ float g_assign_sum[NE];
__device__ float g_z2;
__device__ int   g_counts[NE];
__device__ int   g_fill[NE];
__device__ int   g_offsets[NE];
__device__ int   g_keepcnt;
__device__ int   g_te[NKA];
__device__ float g_prio[NKA];
__device__ float g_tpk[NKA];
__device__ float g_keep[NKA];
__device__ int   g_idx_list[NKA];
__device__ int   g_tile_e[MAXT];
__device__ int   g_tile_r0[MAXT];
__device__ int   g_tile_rows[MAXT];
__device__ int   g_ntiles;

__device__ float  g_tokens[(size_t)MROW * DM];
__device__ __half g_tokh[(size_t)MROW * DM];
__device__ __half g_acth[(size_t)(NKA + 128) * HF];
__device__ __half g_qkvh[(size_t)MROW * QKVW];
__device__ __half g_attnh[(size_t)MROW * DM];
__device__ __half g_uh[(size_t)MROW * DM];
__device__ __half g_hh[(size_t)MROW * DM];
__device__ __half g_fmh[(size_t)NTOK * DM];

__device__ __half g_xh[(size_t)NTOK * DM];              // 2*x
__device__ __half g_w13h[(size_t)NE * 2 * HF * DM];     // rows interleaved g/u
__device__ __half g_w2h[(size_t)NE * DM * HF];
__device__ __half g_ipwh[(size_t)QKVW * DM];
__device__ __half g_owh[(size_t)DM * DM];
__device__ __half g_f1h[(size_t)DM * DM];
__device__ __half g_f2h[(size_t)DM * DM];
__device__ __half g_oph[(size_t)DM * DM];

// ---------------- helpers ----------------
__device__ __forceinline__ uint32_t h2u(float a, float b) {
    __half2 h = __floats2half2_rn(a, b);
    return *(uint32_t*)&h;
}

__device__ __forceinline__ void cp16(void* smem, const void* gmem) {
    uint32_t s = (uint32_t)__cvta_generic_to_shared(smem);
    asm volatile("cp.async.cg.shared.global [%0], [%1], 16;" :: "r"(s), "l"(gmem));
}
#define CP_COMMIT() asm volatile("cp.async.commit_group;" ::: "memory")
#define CP_WAIT1()  asm volatile("cp.async.wait_group 1;" ::: "memory")

__device__ __forceinline__ void mma16(float* c, const uint32_t* a, const uint32_t* b) {
    asm volatile(
        "mma.sync.aligned.m16n8k16.row.col.f32.f16.f16.f32 "
        "{%0,%1,%2,%3},{%4,%5,%6,%7},{%8,%9},{%0,%1,%2,%3};"
        : "+f"(c[0]), "+f"(c[1]), "+f"(c[2]), "+f"(c[3])
        : "r"(a[0]), "r"(a[1]), "r"(a[2]), "r"(a[3]), "r"(b[0]), "r"(b[1]));
}

// one 128x128x32 tile: 8 warps, warp tile 64x32, 2 k-steps of 16
__device__ __forceinline__ void mma_tile_h(const __half* As, const __half* Bs,
                                           float acc[4][4][4], int lane, int warpM, int warpN) {
    int lr = lane >> 2, lq = (lane & 3) * 2;
    #pragma unroll
    for (int ks = 0; ks < 2; ks++) {
        int kb = ks * 16 + lq;
        uint32_t a[4][4], b[4][2];
        #pragma unroll
        for (int mf = 0; mf < 4; mf++) {
            int rb = warpM * 64 + mf * 16 + lr;
            a[mf][0] = *(const uint32_t*)(As + rb * 40 + kb);
            a[mf][1] = *(const uint32_t*)(As + (rb + 8) * 40 + kb);
            a[mf][2] = *(const uint32_t*)(As + rb * 40 + kb + 8);
            a[mf][3] = *(const uint32_t*)(As + (rb + 8) * 40 + kb + 8);
        }
        #pragma unroll
        for (int nf = 0; nf < 4; nf++) {
            int cb = warpN * 32 + nf * 8 + lr;
            b[nf][0] = *(const uint32_t*)(Bs + cb * 40 + kb);
            b[nf][1] = *(const uint32_t*)(Bs + cb * 40 + kb + 8);
        }
        #pragma unroll
        for (int mf = 0; mf < 4; mf++)
            #pragma unroll
            for (int nf = 0; nf < 4; nf++)
                mma16(acc[mf][nf], a[mf], b[nf]);
    }
}

// ---------------- generic NT GEMM (fp16, 3-stage cp.async pipeline) ----------------
template<bool BIAS, bool RES, bool GELU, bool HOUT, bool MIRROR>
__global__ void __launch_bounds__(256) gemm_h(
    const __half* __restrict__ A, const __half* __restrict__ B,
    const float* __restrict__ bias, const float* __restrict__ res,
    void* __restrict__ Cv, __half* __restrict__ mirror, int N, int K)
{
    extern __shared__ __half sm[];
    __half* As = sm;
    __half* Bs = sm + 3 * STGH;
    int tid = threadIdx.x, lane = tid & 31, warp = tid >> 5;
    int warpM = warp >> 2, warpN = warp & 3;
    size_t m0 = (size_t)blockIdx.x * 128;
    int n0 = blockIdx.y * 128;
    const __half* Ab = A + m0 * K;
    const __half* Bb = B + (size_t)n0 * K;
    float acc[4][4][4] = {};
    int r0w = tid >> 2, c8 = (tid & 3) * 8;
    int r1w = r0w + 64;
    int nch = K >> 5;

    #pragma unroll
    for (int p = 0; p < 2; p++) {
        int kk = p * 32;
        cp16(&As[p * STGH + r0w * 40 + c8], Ab + (size_t)r0w * K + kk + c8);
        cp16(&As[p * STGH + r1w * 40 + c8], Ab + (size_t)r1w * K + kk + c8);
        cp16(&Bs[p * STGH + r0w * 40 + c8], Bb + (size_t)r0w * K + kk + c8);
        cp16(&Bs[p * STGH + r1w * 40 + c8], Bb + (size_t)r1w * K + kk + c8);
        CP_COMMIT();
    }

    int s = 0, sl = 2;
    for (int c = 0; c < nch; c++) {
        CP_WAIT1();
        __syncthreads();
        if (c + 2 < nch) {
            int kk = (c + 2) * 32;
            cp16(&As[sl * STGH + r0w * 40 + c8], Ab + (size_t)r0w * K + kk + c8);
            cp16(&As[sl * STGH + r1w * 40 + c8], Ab + (size_t)r1w * K + kk + c8);
            cp16(&Bs[sl * STGH + r0w * 40 + c8], Bb + (size_t)r0w * K + kk + c8);
            cp16(&Bs[sl * STGH + r1w * 40 + c8], Bb + (size_t)r1w * K + kk + c8);
        }
        CP_COMMIT();
        mma_tile_h(As + s * STGH, Bs + s * STGH, acc, lane, warpM, warpN);
        if (++s == 3) s = 0;
        if (++sl == 3) sl = 0;
    }

    int lr = lane >> 2, lc = (lane & 3) * 2;
    #pragma unroll
    for (int mf = 0; mf < 4; mf++)
        #pragma unroll
        for (int h = 0; h < 2; h++) {
            size_t m = m0 + warpM * 64 + mf * 16 + lr + h * 8;
            #pragma unroll
            for (int nf = 0; nf < 4; nf++) {
                int col = n0 + warpN * 32 + nf * 8 + lc;
                float v0 = acc[mf][nf][h * 2], v1 = acc[mf][nf][h * 2 + 1];
                if (BIAS) { v0 += bias[col]; v1 += bias[col + 1]; }
                if (RES)  { v0 += res[m * N + col]; v1 += res[m * N + col + 1]; }
                if (GELU) {
                    v0 = 0.5f * v0 * (1.f + erff(v0 * 0.70710678118654752f));
                    v1 = 0.5f * v1 * (1.f + erff(v1 * 0.70710678118654752f));
                }
                if (HOUT) {
                    *(__half2*)((__half*)Cv + m * N + col) = __floats2half2_rn(v0, v1);
                } else {
                    *(float2*)((float*)Cv + m * N + col) = make_float2(v0, v1);
                    if (MIRROR)
                        *(__half2*)(mirror + m * N + col) = __floats2half2_rn(v0, v1);
                }
            }
        }
}

// ---------------- expert pass A: fused gu GEMM + SiLU ----------------
__global__ void __launch_bounds__(256) expA_h()
{
    int t = blockIdx.x;
    if (t >= g_ntiles) return;
    extern __shared__ __half sm[];
    __half* As = sm;
    __half* Bs = sm + 3 * STGH;
    __shared__ int tok[128];
    int tid = threadIdx.x, lane = tid & 31, warp = tid >> 5;
    int warpM = warp >> 2, warpN = warp & 3;
    int e = g_tile_e[t], r0 = g_tile_r0[t], rows = g_tile_rows[t];
    int n0 = blockIdx.y * 128;
    if (tid < 128) tok[tid] = (tid < rows) ? (g_idx_list[r0 + tid] >> 1) : 0;
    __syncthreads();
    const __half* Bb = g_w13h + (size_t)e * 2 * HF * DM + (size_t)n0 * DM;
    float acc[4][4][4] = {};
    int r0w = tid >> 2, c8 = (tid & 3) * 8;
    int r1w = r0w + 64;
    const __half* a0p = g_xh + (size_t)tok[r0w] * DM;
    const __half* a1p = g_xh + (size_t)tok[r1w] * DM;
    int nch = DM >> 5;

    #pragma unroll
    for (int p = 0; p < 2; p++) {
        int kk = p * 32;
        cp16(&As[p * STGH + r0w * 40 + c8], a0p + kk + c8);
        cp16(&As[p * STGH + r1w * 40 + c8], a1p + kk + c8);
        cp16(&Bs[p * STGH + r0w * 40 + c8], Bb + (size_t)r0w * DM + kk + c8);
        cp16(&Bs[p * STGH + r1w * 40 + c8], Bb + (size_t)r1w * DM + kk + c8);
        CP_COMMIT();
    }

    int s = 0, sl = 2;
    for (int c = 0; c < nch; c++) {
        CP_WAIT1();
        __syncthreads();
        if (c + 2 < nch) {
            int kk = (c + 2) * 32;
            cp16(&As[sl * STGH + r0w * 40 + c8], a0p + kk + c8);
            cp16(&As[sl * STGH + r1w * 40 + c8], a1p + kk + c8);
            cp16(&Bs[sl * STGH + r0w * 40 + c8], Bb + (size_t)r0w * DM + kk + c8);
            cp16(&Bs[sl * STGH + r1w * 40 + c8], Bb + (size_t)r1w * DM + kk + c8);
        }
        CP_COMMIT();
        mma_tile_h(As + s * STGH, Bs + s * STGH, acc, lane, warpM, warpN);
        if (++s == 3) s = 0;
        if (++sl == 3) sl = 0;
    }

    int lr = lane >> 2, lc = (lane & 3) * 2;
    int hbase = blockIdx.y * 64;
    #pragma unroll
    for (int mf = 0; mf < 4; mf++)
        #pragma unroll
        for (int h = 0; h < 2; h++) {
            int rl = warpM * 64 + mf * 16 + lr + h * 8;
            if (rl < rows) {
                __half* ap = g_acth + (size_t)(r0 + rl) * HF + hbase;
                #pragma unroll
                for (int nf = 0; nf < 4; nf++) {
                    int colt = warpN * 32 + nf * 8 + lc;
                    float g = acc[mf][nf][h * 2];
                    float u = acc[mf][nf][h * 2 + 1];
                    ap[colt >> 1] = __float2half_rn(g / (1.f + expf(-g)) * u);
                }
            }
        }
}

// ---------------- expert pass B ----------------
__global__ void __launch_bounds__(256) expB_h(const float* __restrict__ x)
{
    int t = blockIdx.x;
    if (t >= g_ntiles) return;
    extern __shared__ __half sm[];
    __half* As = sm;
    __half* Bs = sm + 3 * STGH;
    __shared__ int s_asn[128];
    int tid = threadIdx.x, lane = tid & 31, warp = tid >> 5;
    int warpM = warp >> 2, warpN = warp & 3;
    int e = g_tile_e[t], r0 = g_tile_r0[t], rows = g_tile_rows[t];
    int n0 = blockIdx.y * 128;
    if (tid < 128) s_asn[tid] = (tid < rows) ? g_idx_list[r0 + tid] : 0;
    const __half* Ab = g_acth + (size_t)r0 * HF;
    const __half* Bb = g_w2h + (size_t)e * DM * HF + (size_t)n0 * HF;
    float acc[4][4][4] = {};
    int r0w = tid >> 2, c8 = (tid & 3) * 8;
    int r1w = r0w + 64;
    int nch = HF >> 5;

    #pragma unroll
    for (int p = 0; p < 2; p++) {
        int kk = p * 32;
        cp16(&As[p * STGH + r0w * 40 + c8], Ab + (size_t)r0w * HF + kk + c8);
        cp16(&As[p * STGH + r1w * 40 + c8], Ab + (size_t)r1w * HF + kk + c8);
        cp16(&Bs[p * STGH + r0w * 40 + c8], Bb + (size_t)r0w * HF + kk + c8);
        cp16(&Bs[p * STGH + r1w * 40 + c8], Bb + (size_t)r1w * HF + kk + c8);
        CP_COMMIT();
    }

    int s = 0, sl = 2;
    for (int c = 0; c < nch; c++) {
        CP_WAIT1();
        __syncthreads();
        if (c + 2 < nch) {
            int kk = (c + 2) * 32;
            cp16(&As[sl * STGH + r0w * 40 + c8], Ab + (size_t)r0w * HF + kk + c8);
            cp16(&As[sl * STGH + r1w * 40 + c8], Ab + (size_t)r1w * HF + kk + c8);
            cp16(&Bs[sl * STGH + r0w * 40 + c8], Bb + (size_t)r0w * HF + kk + c8);
            cp16(&Bs[sl * STGH + r1w * 40 + c8], Bb + (size_t)r1w * HF + kk + c8);
        }
        CP_COMMIT();
        mma_tile_h(As + s * STGH, Bs + s * STGH, acc, lane, warpM, warpN);
        if (++s == 3) s = 0;
        if (++sl == 3) sl = 0;
    }

    int lr = lane >> 2, lc = (lane & 3) * 2;
    #pragma unroll
    for (int mf = 0; mf < 4; mf++)
        #pragma unroll
        for (int h = 0; h < 2; h++) {
            int rl = warpM * 64 + mf * 16 + lr + h * 8;
            if (rl < rows) {
                int a = s_asn[rl];
                int n = a >> 1, slot = a & 1;
                float kp = g_keep[a];
                const float* xr = x + (size_t)n * DM + n0;
                size_t base = ((size_t)n * 3 + slot) * DM + n0;
                #pragma unroll
                for (int nf = 0; nf < 4; nf++) {
                    int col = warpN * 32 + nf * 8 + lc;
                    float v0 = kp * (xr[col]     + acc[mf][nf][h * 2]);
                    float v1 = kp * (xr[col + 1] + acc[mf][nf][h * 2 + 1]);
                    *(float2*)(g_tokens + base + col) = make_float2(v0, v1);
                    *(__half2*)(g_tokh + base + col) = __floats2half2_rn(v0, v1);
                }
            }
        }
}

// ---------------- combined cvt: w13 (interleaved) + x (alpha=2) + mediator init ----------------
#define W13_U4 ((size_t)NE * 2 * HF * DM / 8)   // 3145728
#define X_U4   ((size_t)NTOK * DM / 8)          // 786432
__global__ void cvt_combined_kernel(const float* __restrict__ w13,
                                    const float* __restrict__ x,
                                    const float* __restrict__ mediator) {
    size_t j = (size_t)blockIdx.x * 256 + threadIdx.x;
    if (j < W13_U4) {
        size_t per_e = (size_t)2 * HF * DM / 8;
        size_t e = j / per_e;
        size_t rem = j - e * per_e;
        int rp = (int)(rem / (DM / 8));
        int d8 = (int)(rem % (DM / 8));
        int h = rp >> 1;
        int src = (rp & 1) ? (HF + h) : h;
        const float* sp = w13 + (size_t)e * 2 * HF * DM + (size_t)src * DM + d8 * 8;
        float4 v0 = *(const float4*)sp;
        float4 v1 = *(const float4*)(sp + 4);
        uint4 o;
        o.x = h2u(v0.x, v0.y); o.y = h2u(v0.z, v0.w);
        o.z = h2u(v1.x, v1.y); o.w = h2u(v1.z, v1.w);
        ((uint4*)g_w13h)[j] = o;
    } else if (j < W13_U4 + X_U4) {
        size_t i = j - W13_U4;
        const float* sp = x + i * 8;
        float4 v0 = *(const float4*)sp;
        float4 v1 = *(const float4*)(sp + 4);
        uint4 o;
        o.x = h2u(2.f * v0.x, 2.f * v0.y); o.y = h2u(2.f * v0.z, 2.f * v0.w);
        o.z = h2u(2.f * v1.x, 2.f * v1.y); o.w = h2u(2.f * v1.z, 2.f * v1.w);
        ((uint4*)g_xh)[i] = o;
    } else if (j < W13_U4 + 2 * X_U4) {
        size_t i = j - W13_U4 - X_U4;     // over NTOK * DM / 8
        size_t n = i / (DM / 8);
        int d8 = (int)(i % (DM / 8)) * 8;
        const float* sp = mediator + d8;
        float4 v0 = *(const float4*)sp;
        float4 v1 = *(const float4*)(sp + 4);
        size_t base = (n * 3 + 2) * DM + d8;
        *(float4*)(g_tokens + base) = v0;
        *(float4*)(g_tokens + base + 4) = v1;
        uint4 o;
        o.x = h2u(v0.x, v0.y); o.y = h2u(v0.z, v0.w);
        o.z = h2u(v1.x, v1.y); o.w = h2u(v1.z, v1.w);
        *(uint4*)(g_tokh + base) = o;
    }
}

// ---------------- all remaining weight cvts in ONE kernel ----------------
#define W2_U4  ((size_t)NE * DM * HF / 8)       // 1572864
#define IPW_U4 ((size_t)QKVW * DM / 8)          // 221184
#define DD_U4  ((size_t)DM * DM / 8)            // 73728
#define CVTW_TOTAL (W2_U4 + IPW_U4 + 4 * DD_U4)
__global__ void cvtw_all_kernel(const float* __restrict__ w2,
                                const float* __restrict__ ipw,
                                const float* __restrict__ ow,
                                const float* __restrict__ f1,
                                const float* __restrict__ f2,
                                const float* __restrict__ op) {
    size_t j = (size_t)blockIdx.x * 256 + threadIdx.x;
    if (j >= CVTW_TOTAL) return;
    const float* src;
    __half* dst;
    size_t i = j;
    if (i < W2_U4) { src = w2; dst = g_w2h; }
    else {
        i -= W2_U4;
        if (i < IPW_U4) { src = ipw; dst = g_ipwh; }
        else {
            i -= IPW_U4;
            if (i < DD_U4) { src = ow; dst = g_owh; }
            else {
                i -= DD_U4;
                if (i < DD_U4) { src = f1; dst = g_f1h; }
                else {
                    i -= DD_U4;
                    if (i < DD_U4) { src = f2; dst = g_f2h; }
                    else { i -= DD_U4; src = op; dst = g_oph; }
                }
            }
        }
    }
    const float* sp = src + i * 8;
    float4 v0 = *(const float4*)sp;
    float4 v1 = *(const float4*)(sp + 4);
    uint4 o;
    o.x = h2u(v0.x, v0.y); o.y = h2u(v0.z, v0.w);
    o.z = h2u(v1.x, v1.y); o.w = h2u(v1.z, v1.w);
    ((uint4*)dst)[i] = o;
}

// ---------------- small kernels ----------------
__global__ void zero_accum_kernel() {
    int t = threadIdx.x;
    if (t < NE) { g_router_sum[t] = 0.f; g_assign_sum[t] = 0.f; g_counts[t] = 0; g_fill[t] = 0; }
    if (t == 0) { g_z2 = 0.f; g_keepcnt = 0; }
}

__global__ void __launch_bounds__(256) gate_kernel(const float* __restrict__ x,
                                                   const float* __restrict__ gw,
                                                   float* __restrict__ out) {
    __shared__ float wsh[NE * DM];
    __shared__ float s_rs[NE], s_as[NE], s_z2s;
    __shared__ int   s_c[NE];
    int tid = threadIdx.x;
    for (int i = tid; i < NE * DM; i += 256) wsh[i] = gw[i];
    if (tid < NE) { s_rs[tid] = 0.f; s_as[tid] = 0.f; s_c[tid] = 0; }
    if (tid == 0) s_z2s = 0.f;
    __syncthreads();
    int warp = tid >> 5, lane = tid & 31;
    int n = blockIdx.x * 8 + warp;
    const float* xr = x + (size_t)n * DM;
    float xv[24];
    #pragma unroll
    for (int i = 0; i < 24; i++) xv[i] = xr[lane + i * 32];
    float l[NE];
    #pragma unroll
    for (int e = 0; e < NE; e++) {
        float sv = 0.f;
        const float* w = wsh + e * DM;
        #pragma unroll
        for (int i = 0; i < 24; i++) sv += xv[i] * w[lane + i * 32];
        #pragma unroll
        for (int o = 16; o; o >>= 1) sv += __shfl_xor_sync(0xffffffffu, sv, o);
        l[e] = sv;
    }
    if (lane == 0) {
        int i1 = 0; float v1 = l[0];
        #pragma unroll
        for (int e = 1; e < NE; e++) if (l[e] > v1) { v1 = l[e]; i1 = e; }
        int i2 = -1; float v2 = -3.4e38f;
        #pragma unroll
        for (int e = 0; e < NE; e++) if (e != i1 && l[e] > v2) { v2 = l[e]; i2 = e; }
        float e2 = expf(v2 - v1);
        float inv = 1.f / (1.f + e2);
        float p1 = inv, p2 = e2 * inv;
        float se = 0.f;
        #pragma unroll
        for (int e = 0; e < NE; e++) se += expf(l[e] - v1);
        float z = v1 + logf(se);
        #pragma unroll
        for (int e = 0; e < NE; e++) atomicAdd(&s_rs[e], expf(l[e] - v1) / se);
        atomicAdd(&s_as[i1], p1);
        atomicAdd(&s_as[i2], p2);
        atomicAdd(&s_z2s, z * z);
        atomicAdd(&s_c[i1], 1);
        atomicAdd(&s_c[i2], 1);
        g_te[2 * n] = i1; g_te[2 * n + 1] = i2;
        g_prio[2 * n] = v1; g_prio[2 * n + 1] = v2;
        g_tpk[2 * n] = p1; g_tpk[2 * n + 1] = p2;
        out[(size_t)NTOK * DM + 1 + 2 * n]     = (float)i1;
        out[(size_t)NTOK * DM + 1 + 2 * n + 1] = (float)i2;
    }
    __syncthreads();
    if (tid < NE) {
        atomicAdd(&g_router_sum[tid], s_rs[tid]);
        atomicAdd(&g_assign_sum[tid], s_as[tid]);
        atomicAdd(&g_counts[tid], s_c[tid]);
    }
    if (tid == 0) atomicAdd(&g_z2, s_z2s);
}

__global__ void build_tiles_kernel() {
    if (threadIdx.x != 0 || blockIdx.x != 0) return;
    int off = 0, nt = 0;
    for (int e = 0; e < NE; e++) {
        g_offsets[e] = off;
        int c = g_counts[e];
        int ntile = (c + 127) >> 7;
        for (int t = 0; t < ntile; t++) {
            g_tile_e[nt] = e;
            g_tile_r0[nt] = off + t * 128;
            int r = c - t * 128;
            g_tile_rows[nt] = r < 128 ? r : 128;
            nt++;
        }
        off += c;
    }
    g_ntiles = nt;
}

__global__ void scatter_kernel() {
    int i = blockIdx.x * 256 + threadIdx.x;
    if (i >= NKA) return;
    int e = g_te[i];
    int p = atomicAdd(&g_fill[e], 1);
    g_idx_list[g_offsets[e] + p] = i;
}

__global__ void keep_kernel() {
    int i = blockIdx.x * 256 + threadIdx.x;
    if (i >= NKA) return;
    int e = g_te[i];
    int kp;
    if (g_counts[e] <= CAPC) {
        kp = 1;
    } else {
        float pi = g_prio[i];
        int rank = 0;
        for (int j = 0; j < NKA; j++) {
            if (g_te[j] == e) {
                float pj = g_prio[j];
                if (pj > pi || (pj == pi && j < i)) rank++;
            }
        }
        kp = (rank < CAPC) ? 1 : 0;
    }
    g_keep[i] = (float)kp;
    atomicAdd(&g_keepcnt, kp);
}

__global__ void attn_kernel() {
    int n = blockIdx.x;
    int h = threadIdx.x >> 5, lane = threadIdx.x & 31;
    const __half* base = g_qkvh + (size_t)n * 3 * QKVW;
    float q[3][6], k[3][6], v[3][6];
    #pragma unroll
    for (int li = 0; li < 3; li++) {
        const __half* bp = base + (size_t)li * QKVW + h * 192 + lane * 6;
        #pragma unroll
        for (int dd = 0; dd < 6; dd++) {
            q[li][dd] = __half2float(bp[dd]);
            k[li][dd] = __half2float(bp[dd + DM]);
            v[li][dd] = __half2float(bp[dd + 2 * DM]);
        }
    }
    const float scale = 0.07216878364870322f;
    float b0 = (g_keep[2 * n]     > 0.5f) ? 0.f : -1e9f;
    float b1 = (g_keep[2 * n + 1] > 0.5f) ? 0.f : -1e9f;
    float s[3][3];
    #pragma unroll
    for (int qi = 0; qi < 3; qi++) {
        #pragma unroll
        for (int kj = 0; kj < 3; kj++) {
            float t = 0.f;
            #pragma unroll
            for (int dd = 0; dd < 6; dd++) t += q[qi][dd] * k[kj][dd];
            #pragma unroll
            for (int o = 16; o; o >>= 1) t += __shfl_xor_sync(0xffffffffu, t, o);
            s[qi][kj] = t * scale;
        }
        s[qi][0] += b0;
        s[qi][1] += b1;
    }
    #pragma unroll
    for (int qi = 0; qi < 3; qi++) {
        float m = fmaxf(s[qi][0], fmaxf(s[qi][1], s[qi][2]));
        float e0 = expf(s[qi][0] - m), e1 = expf(s[qi][1] - m), e2 = expf(s[qi][2] - m);
        float inv = 1.f / (e0 + e1 + e2);
        float a0 = e0 * inv, a1 = e1 * inv, a2 = e2 * inv;
        __half* op = g_attnh + (size_t)(n * 3 + qi) * DM + h * 192 + lane * 6;
        #pragma unroll
        for (int dd = 0; dd < 6; dd++)
            op[dd] = __float2half_rn(a0 * v[0][dd] + a1 * v[1][dd] + a2 * v[2][dd]);
    }
}

__global__ void rms_dual_kernel(const float* __restrict__ w1, const float* __restrict__ w2) {
    __shared__ float sh[8];
    __shared__ float sscale;
    int m = blockIdx.x, tid = threadIdx.x;
    float* row = g_tokens + (size_t)m * DM;
    float v0 = row[tid], v1 = row[tid + 256], v2 = row[tid + 512];
    float ss = v0 * v0 + v1 * v1 + v2 * v2;
    #pragma unroll
    for (int o = 16; o; o >>= 1) ss += __shfl_xor_sync(0xffffffffu, ss, o);
    if ((tid & 31) == 0) sh[tid >> 5] = ss;
    __syncthreads();
    if (tid == 0) {
        float t = 0.f;
        #pragma unroll
        for (int i = 0; i < 8; i++) t += sh[i];
        sscale = rsqrtf(t * (1.f / DM) + 1e-6f);
    }
    __syncthreads();
    float s1 = sscale;
    float t0 = v0 * s1 * w1[tid];
    float t1 = v1 * s1 * w1[tid + 256];
    float t2 = v2 * s1 * w1[tid + 512];
    row[tid] = t0; row[tid + 256] = t1; row[tid + 512] = t2;
    float ss2 = t0 * t0 + t1 * t1 + t2 * t2;
    #pragma unroll
    for (int o = 16; o; o >>= 1) ss2 += __shfl_xor_sync(0xffffffffu, ss2, o);
    __syncthreads();
    if ((tid & 31) == 0) sh[tid >> 5] = ss2;
    __syncthreads();
    if (tid == 0) {
        float t = 0.f;
        #pragma unroll
        for (int i = 0; i < 8; i++) t += sh[i];
        sscale = rsqrtf(t * (1.f / DM) + 1e-6f);
    }
    __syncthreads();
    float s2 = sscale;
    __half* ur = g_uh + (size_t)m * DM;
    ur[tid]       = __float2half_rn(t0 * s2 * w2[tid]);
    ur[tid + 256] = __float2half_rn(t1 * s2 * w2[tid + 256]);
    ur[tid + 512] = __float2half_rn(t2 * s2 * w2[tid + 512]);
}

__global__ void fuse_prep_kernel(const float* __restrict__ fgw, const float* __restrict__ fgb) {
    __shared__ float sh[8];
    __shared__ float par[3];
    int n = blockIdx.x, tid = threadIdx.x;
    const float* med = g_tokens + ((size_t)n * 3 + 2) * DM;
    float s = med[tid] * fgw[tid] + med[tid + 256] * fgw[tid + 256] + med[tid + 512] * fgw[tid + 512];
    #pragma unroll
    for (int o = 16; o; o >>= 1) s += __shfl_xor_sync(0xffffffffu, s, o);
    if ((tid & 31) == 0) sh[tid >> 5] = s;
    __syncthreads();
    if (tid == 0) {
        float t = 0.f;
        #pragma unroll
        for (int i = 0; i < 8; i++) t += sh[i];
        float g = 1.f / (1.f + expf(-(t + fgb[0])));
        float tp0 = g_tpk[2 * n] * g_keep[2 * n];
        float tp1 = g_tpk[2 * n + 1] * g_keep[2 * n + 1];
        float den = tp0 + tp1;
        par[0] = g;
        par[1] = den > 0.f ? tp0 / den : 0.f;
        par[2] = den > 0.f ? tp1 / den : 0.f;
    }
    __syncthreads();
    float g = par[0], w0 = par[1], w1 = par[2];
    const float* e0 = g_tokens + ((size_t)n * 3 + 0) * DM;
    const float* e1 = g_tokens + ((size_t)n * 3 + 1) * DM;
    __half* fm = g_fmh + (size_t)n * DM;
    #pragma unroll
    for (int c = 0; c < 3; c++) {
        int d = tid + c * 256;
        fm[d] = __float2half_rn(g * med[d] + (1.f - g) * (w0 * e0[d] + w1 * e1[d]));
    }
}

__global__ void aux_kernel(float* __restrict__ out) {
    if (threadIdx.x != 0 || blockIdx.x != 0) return;
    float bal = 0.f;
    for (int e = 0; e < NE; e++)
        bal += (g_router_sum[e] / (float)NTOK) * (g_assign_sum[e] / (float)NTOK);
    bal *= (float)NE;
    float aux = 0.01f * bal + 0.001f * (g_z2 / (float)NTOK)
              + 0.001f * (1.f - (float)g_keepcnt / (float)NKA);
    out[(size_t)NTOK * DM] = aux;
}

// ---------------- launch ----------------
extern "C" void kernel_launch(void* const* d_in, const int* in_sizes, int n_in,
                              void* d_out, int out_size) {
    const float* x          = (const float*)d_in[0];
    const float* gate_w     = (const float*)d_in[1];
    const float* w13        = (const float*)d_in[2];
    const float* w2         = (const float*)d_in[3];
    const float* in_proj_w  = (const float*)d_in[4];
    const float* in_proj_b  = (const float*)d_in[5];
    const float* out_w      = (const float*)d_in[6];
    const float* out_b      = (const float*)d_in[7];
    const float* norm1_w    = (const float*)d_in[8];
    const float* norm2_w    = (const float*)d_in[9];
    const float* ffn_w1     = (const float*)d_in[10];
    const float* ffn_w2     = (const float*)d_in[11];
    const float* mediator   = (const float*)d_in[12];
    const float* fuse_gate_w= (const float*)d_in[13];
    const float* fuse_gate_b= (const float*)d_in[14];
    const float* o_proj_w   = (const float*)d_in[15];
    float* out = (float*)d_out;

    float* p_tokens;
    __half *p_tokh, *p_ipwh, *p_owh, *p_f1h, *p_f2h, *p_oph;
    __half *p_qkvh, *p_attnh, *p_uh, *p_hh, *p_fmh;
    cudaGetSymbolAddress((void**)&p_tokens, g_tokens);
    cudaGetSymbolAddress((void**)&p_tokh, g_tokh);
    cudaGetSymbolAddress((void**)&p_ipwh, g_ipwh);
    cudaGetSymbolAddress((void**)&p_owh, g_owh);
    cudaGetSymbolAddress((void**)&p_f1h, g_f1h);
    cudaGetSymbolAddress((void**)&p_f2h, g_f2h);
    cudaGetSymbolAddress((void**)&p_oph, g_oph);
    cudaGetSymbolAddress((void**)&p_qkvh, g_qkvh);
    cudaGetSymbolAddress((void**)&p_attnh, g_attnh);
    cudaGetSymbolAddress((void**)&p_uh, g_uh);
    cudaGetSymbolAddress((void**)&p_hh, g_hh);
    cudaGetSymbolAddress((void**)&p_fmh, g_fmh);

    cudaFuncSetAttribute(gemm_h<true,  false, false, true,  false>, cudaFuncAttributeMaxDynamicSharedMemorySize, SMEMB);
    cudaFuncSetAttribute(gemm_h<true,  true,  false, false, false>, cudaFuncAttributeMaxDynamicSharedMemorySize, SMEMB);
    cudaFuncSetAttribute(gemm_h<false, false, true,  true,  false>, cudaFuncAttributeMaxDynamicSharedMemorySize, SMEMB);
    cudaFuncSetAttribute(gemm_h<false, true,  false, false, true >, cudaFuncAttributeMaxDynamicSharedMemorySize, SMEMB);
    cudaFuncSetAttribute(gemm_h<false, false, false, false, false>, cudaFuncAttributeMaxDynamicSharedMemorySize, SMEMB);
    cudaFuncSetAttribute(expA_h, cudaFuncAttributeMaxDynamicSharedMemorySize, SMEMB);
    cudaFuncSetAttribute(expB_h, cudaFuncAttributeMaxDynamicSharedMemorySize, SMEMB);

    zero_accum_kernel<<<1, 32>>>();                                                          // 1
    cvt_combined_kernel<<<(int)((W13_U4 + 2 * X_U4 + 255) / 256), 256>>>(w13, x, mediator);  // 2
    gate_kernel<<<NTOK / 8, 256>>>(x, gate_w, out);                                          // 3
    build_tiles_kernel<<<1, 1>>>();                                                          // 4
    scatter_kernel<<<NKA / 256, 256>>>();                                                    // 5
    expA_h<<<dim3(MAXT, 2 * HF / 128), 256, SMEMB>>>();                                      // 6

    keep_kernel<<<NKA / 256, 256>>>();
    cvtw_all_kernel<<<(int)((CVTW_TOTAL + 255) / 256), 256>>>(
        w2, in_proj_w, out_w, ffn_w1, ffn_w2, o_proj_w);
    expB_h<<<dim3(MAXT, DM / 128), 256, SMEMB>>>(x);

    for (int step = 0; step < 2; step++) {
        gemm_h<true, false, false, true, false><<<dim3(MROW / 128, QKVW / 128), 256, SMEMB>>>(
            p_tokh, p_ipwh, in_proj_b, nullptr, p_qkvh, nullptr, QKVW, DM);
        attn_kernel<<<NTOK, 128>>>();
        gemm_h<true, true, false, false, false><<<dim3(MROW / 128, DM / 128), 256, SMEMB>>>(
            p_attnh, p_owh, out_b, p_tokens, p_tokens, nullptr, DM, DM);
        rms_dual_kernel<<<MROW, 256>>>(norm1_w, norm2_w);
        gemm_h<false, false, true, true, false><<<dim3(MROW / 128, DM / 128), 256, SMEMB>>>(
            p_uh, p_f1h, nullptr, nullptr, p_hh, nullptr, DM, DM);
        gemm_h<false, true, false, false, true><<<dim3(MROW / 128, DM / 128), 256, SMEMB>>>(
            p_hh, p_f2h, nullptr, p_tokens, p_tokens, p_tokh, DM, DM);
    }

    fuse_prep_kernel<<<NTOK, 256>>>(fuse_gate_w, fuse_gate_b);
    gemm_h<false, false, false, false, false><<<dim3(NTOK / 128, DM / 128), 256, SMEMB>>>(
        p_fmh, p_oph, nullptr, nullptr, out, nullptr, DM, DM);
    aux_kernel<<<1, 1>>>(out);
}

// round 14
// speedup vs baseline: 1.0165x; 1.0021x over previous
#include <cuda_runtime.h>
#include <cuda_fp16.h>
#include <math.h>
#include <stdint.h>

#define NTOK 8192
#define DM   768
#define NE   8
#define NKA  16384
#define HF   2048
#define CAPC 4096
#define MROW 24576
#define QKVW 2304
#define MAXT 136

#define STGH  5120                 // 128*40 halves per matrix per stage
#define SMEMB (6 * STGH * 2)       // 3 stages x (A+B) = 61440 bytes

// ---------------- scratch ----------------
__device__ float g_router_sum[NE];
__device__ float g_assign_sum[NE];
__device__ float g_z2;
__device__ int   g_counts[NE];
__device__ int   g_fill[NE];
__device__ int   g_offsets[NE];
__device__ int   g_keepcnt;
__device__ int   g_te[NKA];
__device__ float g_prio[NKA];
__device__ float g_tpk[NKA];
__device__ float g_keep[NKA];
__device__ int   g_idx_list[NKA];
__device__ int   g_tile_e[MAXT];
__device__ int   g_tile_r0[MAXT];
__device__ int   g_tile_rows[MAXT];
__device__ int   g_ntiles;

__device__ float  g_tokens[(size_t)MROW * DM];
__device__ __half g_tokh[(size_t)MROW * DM];
__device__ __half g_acth[(size_t)(NKA + 128) * HF];
__device__ __half g_qkvh[(size_t)MROW * QKVW];
__device__ __half g_attnh[(size_t)MROW * DM];
__device__ __half g_uh[(size_t)MROW * DM];
__device__ __half g_hh[(size_t)MROW * DM];
__device__ __half g_fmh[(size_t)NTOK * DM];

__device__ __half g_xh[(size_t)NTOK * DM];              // 2*x
__device__ __half g_w13h[(size_t)NE * 2 * HF * DM];     // rows interleaved g/u
__device__ __half g_w2h[(size_t)NE * DM * HF];
__device__ __half g_ipwh[(size_t)QKVW * DM];
__device__ __half g_owh[(size_t)DM * DM];
__device__ __half g_f1h[(size_t)DM * DM];
__device__ __half g_f2h[(size_t)DM * DM];
__device__ __half g_oph[(size_t)DM * DM];

// ---------------- helpers ----------------
__device__ __forceinline__ uint32_t h2u(float a, float b) {
    __half2 h = __floats2half2_rn(a, b);
    return *(uint32_t*)&h;
}

__device__ __forceinline__ void cp16(void* smem, const void* gmem) {
    uint32_t s = (uint32_t)__cvta_generic_to_shared(smem);
    asm volatile("cp.async.cg.shared.global [%0], [%1], 16;" :: "r"(s), "l"(gmem));
}
#define CP_COMMIT() asm volatile("cp.async.commit_group;" ::: "memory")
#define CP_WAIT1()  asm volatile("cp.async.wait_group 1;" ::: "memory")

__device__ __forceinline__ void mma16(float* c, const uint32_t* a, const uint32_t* b) {
    asm volatile(
        "mma.sync.aligned.m16n8k16.row.col.f32.f16.f16.f32 "
        "{%0,%1,%2,%3},{%4,%5,%6,%7},{%8,%9},{%0,%1,%2,%3};"
        : "+f"(c[0]), "+f"(c[1]), "+f"(c[2]), "+f"(c[3])
        : "r"(a[0]), "r"(a[1]), "r"(a[2]), "r"(a[3]), "r"(b[0]), "r"(b[1]));
}

// one 128x128x32 tile: 8 warps, warp tile 64x32, 2 k-steps of 16
__device__ __forceinline__ void mma_tile_h(const __half* As, const __half* Bs,
                                           float acc[4][4][4], int lane, int warpM, int warpN) {
    int lr = lane >> 2, lq = (lane & 3) * 2;
    #pragma unroll
    for (int ks = 0; ks < 2; ks++) {
        int kb = ks * 16 + lq;
        uint32_t a[4][4], b[4][2];
        #pragma unroll
        for (int mf = 0; mf < 4; mf++) {
            int rb = warpM * 64 + mf * 16 + lr;
            a[mf][0] = *(const uint32_t*)(As + rb * 40 + kb);
            a[mf][1] = *(const uint32_t*)(As + (rb + 8) * 40 + kb);
            a[mf][2] = *(const uint32_t*)(As + rb * 40 + kb + 8);
            a[mf][3] = *(const uint32_t*)(As + (rb + 8) * 40 + kb + 8);
        }
        #pragma unroll
        for (int nf = 0; nf < 4; nf++) {
            int cb = warpN * 32 + nf * 8 + lr;
            b[nf][0] = *(const uint32_t*)(Bs + cb * 40 + kb);
            b[nf][1] = *(const uint32_t*)(Bs + cb * 40 + kb + 8);
        }
        #pragma unroll
        for (int mf = 0; mf < 4; mf++)
            #pragma unroll
            for (int nf = 0; nf < 4; nf++)
                mma16(acc[mf][nf], a[mf], b[nf]);
    }
}

// ---------------- generic NT GEMM (fp16, 3-stage cp.async pipeline) ----------------
template<bool BIAS, bool RES, bool GELU, bool HOUT, bool MIRROR>
__global__ void __launch_bounds__(256) gemm_h(
    const __half* __restrict__ A, const __half* __restrict__ B,
    const float* __restrict__ bias, const float* __restrict__ res,
    void* __restrict__ Cv, __half* __restrict__ mirror, int N, int K)
{
    extern __shared__ __half sm[];
    __half* As = sm;
    __half* Bs = sm + 3 * STGH;
    int tid = threadIdx.x, lane = tid & 31, warp = tid >> 5;
    int warpM = warp >> 2, warpN = warp & 3;
    size_t m0 = (size_t)blockIdx.x * 128;
    int n0 = blockIdx.y * 128;
    const __half* Ab = A + m0 * K;
    const __half* Bb = B + (size_t)n0 * K;
    float acc[4][4][4] = {};
    int r0w = tid >> 2, c8 = (tid & 3) * 8;
    int r1w = r0w + 64;
    int nch = K >> 5;

    #pragma unroll
    for (int p = 0; p < 2; p++) {
        int kk = p * 32;
        cp16(&As[p * STGH + r0w * 40 + c8], Ab + (size_t)r0w * K + kk + c8);
        cp16(&As[p * STGH + r1w * 40 + c8], Ab + (size_t)r1w * K + kk + c8);
        cp16(&Bs[p * STGH + r0w * 40 + c8], Bb + (size_t)r0w * K + kk + c8);
        cp16(&Bs[p * STGH + r1w * 40 + c8], Bb + (size_t)r1w * K + kk + c8);
        CP_COMMIT();
    }

    int s = 0, sl = 2;
    for (int c = 0; c < nch; c++) {
        CP_WAIT1();
        __syncthreads();
        if (c + 2 < nch) {
            int kk = (c + 2) * 32;
            cp16(&As[sl * STGH + r0w * 40 + c8], Ab + (size_t)r0w * K + kk + c8);
            cp16(&As[sl * STGH + r1w * 40 + c8], Ab + (size_t)r1w * K + kk + c8);
            cp16(&Bs[sl * STGH + r0w * 40 + c8], Bb + (size_t)r0w * K + kk + c8);
            cp16(&Bs[sl * STGH + r1w * 40 + c8], Bb + (size_t)r1w * K + kk + c8);
        }
        CP_COMMIT();
        mma_tile_h(As + s * STGH, Bs + s * STGH, acc, lane, warpM, warpN);
        if (++s == 3) s = 0;
        if (++sl == 3) sl = 0;
    }

    int lr = lane >> 2, lc = (lane & 3) * 2;
    #pragma unroll
    for (int mf = 0; mf < 4; mf++)
        #pragma unroll
        for (int h = 0; h < 2; h++) {
            size_t m = m0 + warpM * 64 + mf * 16 + lr + h * 8;
            #pragma unroll
            for (int nf = 0; nf < 4; nf++) {
                int col = n0 + warpN * 32 + nf * 8 + lc;
                float v0 = acc[mf][nf][h * 2], v1 = acc[mf][nf][h * 2 + 1];
                if (BIAS) { v0 += bias[col]; v1 += bias[col + 1]; }
                if (RES)  { v0 += res[m * N + col]; v1 += res[m * N + col + 1]; }
                if (GELU) {
                    v0 = 0.5f * v0 * (1.f + erff(v0 * 0.70710678118654752f));
                    v1 = 0.5f * v1 * (1.f + erff(v1 * 0.70710678118654752f));
                }
                if (HOUT) {
                    *(__half2*)((__half*)Cv + m * N + col) = __floats2half2_rn(v0, v1);
                } else {
                    *(float2*)((float*)Cv + m * N + col) = make_float2(v0, v1);
                    if (MIRROR)
                        *(__half2*)(mirror + m * N + col) = __floats2half2_rn(v0, v1);
                }
            }
        }
}

// ---------------- expert pass A: fused gu GEMM + SiLU ----------------
__global__ void __launch_bounds__(256) expA_h()
{
    int t = blockIdx.x;
    if (t >= g_ntiles) return;
    extern __shared__ __half sm[];
    __half* As = sm;
    __half* Bs = sm + 3 * STGH;
    __shared__ int tok[128];
    int tid = threadIdx.x, lane = tid & 31, warp = tid >> 5;
    int warpM = warp >> 2, warpN = warp & 3;
    int e = g_tile_e[t], r0 = g_tile_r0[t], rows = g_tile_rows[t];
    int n0 = blockIdx.y * 128;
    if (tid < 128) tok[tid] = (tid < rows) ? (g_idx_list[r0 + tid] >> 1) : 0;
    __syncthreads();
    const __half* Bb = g_w13h + (size_t)e * 2 * HF * DM + (size_t)n0 * DM;
    float acc[4][4][4] = {};
    int r0w = tid >> 2, c8 = (tid & 3) * 8;
    int r1w = r0w + 64;
    const __half* a0p = g_xh + (size_t)tok[r0w] * DM;
    const __half* a1p = g_xh + (size_t)tok[r1w] * DM;
    int nch = DM >> 5;

    #pragma unroll
    for (int p = 0; p < 2; p++) {
        int kk = p * 32;
        cp16(&As[p * STGH + r0w * 40 + c8], a0p + kk + c8);
        cp16(&As[p * STGH + r1w * 40 + c8], a1p + kk + c8);
        cp16(&Bs[p * STGH + r0w * 40 + c8], Bb + (size_t)r0w * DM + kk + c8);
        cp16(&Bs[p * STGH + r1w * 40 + c8], Bb + (size_t)r1w * DM + kk + c8);
        CP_COMMIT();
    }

    int s = 0, sl = 2;
    for (int c = 0; c < nch; c++) {
        CP_WAIT1();
        __syncthreads();
        if (c + 2 < nch) {
            int kk = (c + 2) * 32;
            cp16(&As[sl * STGH + r0w * 40 + c8], a0p + kk + c8);
            cp16(&As[sl * STGH + r1w * 40 + c8], a1p + kk + c8);
            cp16(&Bs[sl * STGH + r0w * 40 + c8], Bb + (size_t)r0w * DM + kk + c8);
            cp16(&Bs[sl * STGH + r1w * 40 + c8], Bb + (size_t)r1w * DM + kk + c8);
        }
        CP_COMMIT();
        mma_tile_h(As + s * STGH, Bs + s * STGH, acc, lane, warpM, warpN);
        if (++s == 3) s = 0;
        if (++sl == 3) sl = 0;
    }

    int lr = lane >> 2, lc = (lane & 3) * 2;
    int hbase = blockIdx.y * 64;
    #pragma unroll
    for (int mf = 0; mf < 4; mf++)
        #pragma unroll
        for (int h = 0; h < 2; h++) {
            int rl = warpM * 64 + mf * 16 + lr + h * 8;
            if (rl < rows) {
                __half* ap = g_acth + (size_t)(r0 + rl) * HF + hbase;
                #pragma unroll
                for (int nf = 0; nf < 4; nf++) {
                    int colt = warpN * 32 + nf * 8 + lc;
                    float g = acc[mf][nf][h * 2];
                    float u = acc[mf][nf][h * 2 + 1];
                    ap[colt >> 1] = __float2half_rn(g / (1.f + expf(-g)) * u);
                }
            }
        }
}

// ---------------- expert pass B ----------------
__global__ void __launch_bounds__(256) expB_h(const float* __restrict__ x)
{
    int t = blockIdx.x;
    if (t >= g_ntiles) return;
    extern __shared__ __half sm[];
    __half* As = sm;
    __half* Bs = sm + 3 * STGH;
    __shared__ int s_asn[128];
    int tid = threadIdx.x, lane = tid & 31, warp = tid >> 5;
    int warpM = warp >> 2, warpN = warp & 3;
    int e = g_tile_e[t], r0 = g_tile_r0[t], rows = g_tile_rows[t];
    int n0 = blockIdx.y * 128;
    if (tid < 128) s_asn[tid] = (tid < rows) ? g_idx_list[r0 + tid] : 0;
    const __half* Ab = g_acth + (size_t)r0 * HF;
    const __half* Bb = g_w2h + (size_t)e * DM * HF + (size_t)n0 * HF;
    float acc[4][4][4] = {};
    int r0w = tid >> 2, c8 = (tid & 3) * 8;
    int r1w = r0w + 64;
    int nch = HF >> 5;

    #pragma unroll
    for (int p = 0; p < 2; p++) {
        int kk = p * 32;
        cp16(&As[p * STGH + r0w * 40 + c8], Ab + (size_t)r0w * HF + kk + c8);
        cp16(&As[p * STGH + r1w * 40 + c8], Ab + (size_t)r1w * HF + kk + c8);
        cp16(&Bs[p * STGH + r0w * 40 + c8], Bb + (size_t)r0w * HF + kk + c8);
        cp16(&Bs[p * STGH + r1w * 40 + c8], Bb + (size_t)r1w * HF + kk + c8);
        CP_COMMIT();
    }

    int s = 0, sl = 2;
    for (int c = 0; c < nch; c++) {
        CP_WAIT1();
        __syncthreads();
        if (c + 2 < nch) {
            int kk = (c + 2) * 32;
            cp16(&As[sl * STGH + r0w * 40 + c8], Ab + (size_t)r0w * HF + kk + c8);
            cp16(&As[sl * STGH + r1w * 40 + c8], Ab + (size_t)r1w * HF + kk + c8);
            cp16(&Bs[sl * STGH + r0w * 40 + c8], Bb + (size_t)r0w * HF + kk + c8);
            cp16(&Bs[sl * STGH + r1w * 40 + c8], Bb + (size_t)r1w * HF + kk + c8);
        }
        CP_COMMIT();
        mma_tile_h(As + s * STGH, Bs + s * STGH, acc, lane, warpM, warpN);
        if (++s == 3) s = 0;
        if (++sl == 3) sl = 0;
    }

    int lr = lane >> 2, lc = (lane & 3) * 2;
    #pragma unroll
    for (int mf = 0; mf < 4; mf++)
        #pragma unroll
        for (int h = 0; h < 2; h++) {
            int rl = warpM * 64 + mf * 16 + lr + h * 8;
            if (rl < rows) {
                int a = s_asn[rl];
                int n = a >> 1, slot = a & 1;
                float kp = g_keep[a];
                const float* xr = x + (size_t)n * DM + n0;
                size_t base = ((size_t)n * 3 + slot) * DM + n0;
                #pragma unroll
                for (int nf = 0; nf < 4; nf++) {
                    int col = warpN * 32 + nf * 8 + lc;
                    float v0 = kp * (xr[col]     + acc[mf][nf][h * 2]);
                    float v1 = kp * (xr[col + 1] + acc[mf][nf][h * 2 + 1]);
                    *(float2*)(g_tokens + base + col) = make_float2(v0, v1);
                    *(__half2*)(g_tokh + base + col) = __floats2half2_rn(v0, v1);
                }
            }
        }
}

// ---------------- combined cvt: w13 (interleaved) + x (alpha=2) + mediator init ----------------
#define W13_U4 ((size_t)NE * 2 * HF * DM / 8)
#define X_U4   ((size_t)NTOK * DM / 8)
__global__ void cvt_combined_kernel(const float* __restrict__ w13,
                                    const float* __restrict__ x,
                                    const float* __restrict__ mediator) {
    size_t j = (size_t)blockIdx.x * 256 + threadIdx.x;
    if (j < W13_U4) {
        size_t per_e = (size_t)2 * HF * DM / 8;
        size_t e = j / per_e;
        size_t rem = j - e * per_e;
        int rp = (int)(rem / (DM / 8));
        int d8 = (int)(rem % (DM / 8));
        int h = rp >> 1;
        int src = (rp & 1) ? (HF + h) : h;
        const float* sp = w13 + (size_t)e * 2 * HF * DM + (size_t)src * DM + d8 * 8;
        float4 v0 = *(const float4*)sp;
        float4 v1 = *(const float4*)(sp + 4);
        uint4 o;
        o.x = h2u(v0.x, v0.y); o.y = h2u(v0.z, v0.w);
        o.z = h2u(v1.x, v1.y); o.w = h2u(v1.z, v1.w);
        ((uint4*)g_w13h)[j] = o;
    } else if (j < W13_U4 + X_U4) {
        size_t i = j - W13_U4;
        const float* sp = x + i * 8;
        float4 v0 = *(const float4*)sp;
        float4 v1 = *(const float4*)(sp + 4);
        uint4 o;
        o.x = h2u(2.f * v0.x, 2.f * v0.y); o.y = h2u(2.f * v0.z, 2.f * v0.w);
        o.z = h2u(2.f * v1.x, 2.f * v1.y); o.w = h2u(2.f * v1.z, 2.f * v1.w);
        ((uint4*)g_xh)[i] = o;
    } else if (j < W13_U4 + 2 * X_U4) {
        size_t i = j - W13_U4 - X_U4;
        size_t n = i / (DM / 8);
        int d8 = (int)(i % (DM / 8)) * 8;
        const float* sp = mediator + d8;
        float4 v0 = *(const float4*)sp;
        float4 v1 = *(const float4*)(sp + 4);
        size_t base = (n * 3 + 2) * DM + d8;
        *(float4*)(g_tokens + base) = v0;
        *(float4*)(g_tokens + base + 4) = v1;
        uint4 o;
        o.x = h2u(v0.x, v0.y); o.y = h2u(v0.z, v0.w);
        o.z = h2u(v1.x, v1.y); o.w = h2u(v1.z, v1.w);
        *(uint4*)(g_tokh + base) = o;
    }
}

// ---------------- all remaining weight cvts in ONE kernel ----------------
#define W2_U4  ((size_t)NE * DM * HF / 8)
#define IPW_U4 ((size_t)QKVW * DM / 8)
#define DD_U4  ((size_t)DM * DM / 8)
#define CVTW_TOTAL (W2_U4 + IPW_U4 + 4 * DD_U4)
__global__ void cvtw_all_kernel(const float* __restrict__ w2,
                                const float* __restrict__ ipw,
                                const float* __restrict__ ow,
                                const float* __restrict__ f1,
                                const float* __restrict__ f2,
                                const float* __restrict__ op) {
    size_t j = (size_t)blockIdx.x * 256 + threadIdx.x;
    if (j >= CVTW_TOTAL) return;
    const float* src;
    __half* dst;
    size_t i = j;
    if (i < W2_U4) { src = w2; dst = g_w2h; }
    else {
        i -= W2_U4;
        if (i < IPW_U4) { src = ipw; dst = g_ipwh; }
        else {
            i -= IPW_U4;
            if (i < DD_U4) { src = ow; dst = g_owh; }
            else {
                i -= DD_U4;
                if (i < DD_U4) { src = f1; dst = g_f1h; }
                else {
                    i -= DD_U4;
                    if (i < DD_U4) { src = f2; dst = g_f2h; }
                    else { i -= DD_U4; src = op; dst = g_oph; }
                }
            }
        }
    }
    const float* sp = src + i * 8;
    float4 v0 = *(const float4*)sp;
    float4 v1 = *(const float4*)(sp + 4);
    uint4 o;
    o.x = h2u(v0.x, v0.y); o.y = h2u(v0.z, v0.w);
    o.z = h2u(v1.x, v1.y); o.w = h2u(v1.z, v1.w);
    ((uint4*)dst)[i] = o;
}

// ---------------- small kernels ----------------
__global__ void zero_accum_kernel() {
    int t = threadIdx.x;
    if (t < NE) { g_router_sum[t] = 0.f; g_assign_sum[t] = 0.f; g_counts[t] = 0; g_fill[t] = 0; }
    if (t == 0) { g_z2 = 0.f; g_keepcnt = 0; }
}

__global__ void __launch_bounds__(256) gate_kernel(const float* __restrict__ x,
                                                   const float* __restrict__ gw,
                                                   float* __restrict__ out) {
    __shared__ float wsh[NE * DM];
    __shared__ float s_rs[NE], s_as[NE], s_z2s;
    __shared__ int   s_c[NE];
    int tid = threadIdx.x;
    for (int i = tid; i < NE * DM; i += 256) wsh[i] = gw[i];
    if (tid < NE) { s_rs[tid] = 0.f; s_as[tid] = 0.f; s_c[tid] = 0; }
    if (tid == 0) s_z2s = 0.f;
    __syncthreads();
    int warp = tid >> 5, lane = tid & 31;
    int n = blockIdx.x * 8 + warp;
    const float* xr = x + (size_t)n * DM;
    float xv[24];
    #pragma unroll
    for (int i = 0; i < 24; i++) xv[i] = xr[lane + i * 32];
    float l[NE];
    #pragma unroll
    for (int e = 0; e < NE; e++) {
        float sv = 0.f;
        const float* w = wsh + e * DM;
        #pragma unroll
        for (int i = 0; i < 24; i++) sv += xv[i] * w[lane + i * 32];
        #pragma unroll
        for (int o = 16; o; o >>= 1) sv += __shfl_xor_sync(0xffffffffu, sv, o);
        l[e] = sv;
    }
    if (lane == 0) {
        int i1 = 0; float v1 = l[0];
        #pragma unroll
        for (int e = 1; e < NE; e++) if (l[e] > v1) { v1 = l[e]; i1 = e; }
        int i2 = -1; float v2 = -3.4e38f;
        #pragma unroll
        for (int e = 0; e < NE; e++) if (e != i1 && l[e] > v2) { v2 = l[e]; i2 = e; }
        float e2 = expf(v2 - v1);
        float inv = 1.f / (1.f + e2);
        float p1 = inv, p2 = e2 * inv;
        float se = 0.f;
        #pragma unroll
        for (int e = 0; e < NE; e++) se += expf(l[e] - v1);
        float z = v1 + logf(se);
        #pragma unroll
        for (int e = 0; e < NE; e++) atomicAdd(&s_rs[e], expf(l[e] - v1) / se);
        atomicAdd(&s_as[i1], p1);
        atomicAdd(&s_as[i2], p2);
        atomicAdd(&s_z2s, z * z);
        atomicAdd(&s_c[i1], 1);
        atomicAdd(&s_c[i2], 1);
        g_te[2 * n] = i1; g_te[2 * n + 1] = i2;
        g_prio[2 * n] = v1; g_prio[2 * n + 1] = v2;
        g_tpk[2 * n] = p1; g_tpk[2 * n + 1] = p2;
        out[(size_t)NTOK * DM + 1 + 2 * n]     = (float)i1;
        out[(size_t)NTOK * DM + 1 + 2 * n + 1] = (float)i2;
    }
    __syncthreads();
    if (tid < NE) {
        atomicAdd(&g_router_sum[tid], s_rs[tid]);
        atomicAdd(&g_assign_sum[tid], s_as[tid]);
        atomicAdd(&g_counts[tid], s_c[tid]);
    }
    if (tid == 0) atomicAdd(&g_z2, s_z2s);
}

__global__ void build_tiles_kernel() {
    if (threadIdx.x != 0 || blockIdx.x != 0) return;
    int off = 0, nt = 0;
    for (int e = 0; e < NE; e++) {
        g_offsets[e] = off;
        int c = g_counts[e];
        int ntile = (c + 127) >> 7;
        for (int t = 0; t < ntile; t++) {
            g_tile_e[nt] = e;
            g_tile_r0[nt] = off + t * 128;
            int r = c - t * 128;
            g_tile_rows[nt] = r < 128 ? r : 128;
            nt++;
        }
        off += c;
    }
    g_ntiles = nt;
}

__global__ void scatter_kernel() {
    int i = blockIdx.x * 256 + threadIdx.x;
    if (i >= NKA) return;
    int e = g_te[i];
    int p = atomicAdd(&g_fill[e], 1);
    g_idx_list[g_offsets[e] + p] = i;
}

__global__ void keep_kernel() {
    int i = blockIdx.x * 256 + threadIdx.x;
    if (i >= NKA) return;
    int e = g_te[i];
    int kp;
    if (g_counts[e] <= CAPC) {
        kp = 1;
    } else {
        float pi = g_prio[i];
        int rank = 0;
        for (int j = 0; j < NKA; j++) {
            if (g_te[j] == e) {
                float pj = g_prio[j];
                if (pj > pi || (pj == pi && j < i)) rank++;
            }
        }
        kp = (rank < CAPC) ? 1 : 0;
    }
    g_keep[i] = (float)kp;
    atomicAdd(&g_keepcnt, kp);
}

__global__ void attn_kernel() {
    int n = blockIdx.x;
    int h = threadIdx.x >> 5, lane = threadIdx.x & 31;
    const __half* base = g_qkvh + (size_t)n * 3 * QKVW;
    float q[3][6], k[3][6], v[3][6];
    #pragma unroll
    for (int li = 0; li < 3; li++) {
        const __half* bp = base + (size_t)li * QKVW + h * 192 + lane * 6;
        #pragma unroll
        for (int dd = 0; dd < 6; dd++) {
            q[li][dd] = __half2float(bp[dd]);
            k[li][dd] = __half2float(bp[dd + DM]);
            v[li][dd] = __half2float(bp[dd + 2 * DM]);
        }
    }
    const float scale = 0.07216878364870322f;
    float b0 = (g_keep[2 * n]     > 0.5f) ? 0.f : -1e9f;
    float b1 = (g_keep[2 * n + 1] > 0.5f) ? 0.f : -1e9f;
    float s[3][3];
    #pragma unroll
    for (int qi = 0; qi < 3; qi++) {
        #pragma unroll
        for (int kj = 0; kj < 3; kj++) {
            float t = 0.f;
            #pragma unroll
            for (int dd = 0; dd < 6; dd++) t += q[qi][dd] * k[kj][dd];
            #pragma unroll
            for (int o = 16; o; o >>= 1) t += __shfl_xor_sync(0xffffffffu, t, o);
            s[qi][kj] = t * scale;
        }
        s[qi][0] += b0;
        s[qi][1] += b1;
    }
    #pragma unroll
    for (int qi = 0; qi < 3; qi++) {
        float m = fmaxf(s[qi][0], fmaxf(s[qi][1], s[qi][2]));
        float e0 = expf(s[qi][0] - m), e1 = expf(s[qi][1] - m), e2 = expf(s[qi][2] - m);
        float inv = 1.f / (e0 + e1 + e2);
        float a0 = e0 * inv, a1 = e1 * inv, a2 = e2 * inv;
        __half* op = g_attnh + (size_t)(n * 3 + qi) * DM + h * 192 + lane * 6;
        #pragma unroll
        for (int dd = 0; dd < 6; dd++)
            op[dd] = __float2half_rn(a0 * v[0][dd] + a1 * v[1][dd] + a2 * v[2][dd]);
    }
}

__global__ void rms_dual_kernel(const float* __restrict__ w1, const float* __restrict__ w2) {
    __shared__ float sh[8];
    __shared__ float sscale;
    int m = blockIdx.x, tid = threadIdx.x;
    float* row = g_tokens + (size_t)m * DM;
    float v0 = row[tid], v1 = row[tid + 256], v2 = row[tid + 512];
    float ss = v0 * v0 + v1 * v1 + v2 * v2;
    #pragma unroll
    for (int o = 16; o; o >>= 1) ss += __shfl_xor_sync(0xffffffffu, ss, o);
    if ((tid & 31) == 0) sh[tid >> 5] = ss;
    __syncthreads();
    if (tid == 0) {
        float t = 0.f;
        #pragma unroll
        for (int i = 0; i < 8; i++) t += sh[i];
        sscale = rsqrtf(t * (1.f / DM) + 1e-6f);
    }
    __syncthreads();
    float s1 = sscale;
    float t0 = v0 * s1 * w1[tid];
    float t1 = v1 * s1 * w1[tid + 256];
    float t2 = v2 * s1 * w1[tid + 512];
    row[tid] = t0; row[tid + 256] = t1; row[tid + 512] = t2;
    float ss2 = t0 * t0 + t1 * t1 + t2 * t2;
    #pragma unroll
    for (int o = 16; o; o >>= 1) ss2 += __shfl_xor_sync(0xffffffffu, ss2, o);
    __syncthreads();
    if ((tid & 31) == 0) sh[tid >> 5] = ss2;
    __syncthreads();
    if (tid == 0) {
        float t = 0.f;
        #pragma unroll
        for (int i = 0; i < 8; i++) t += sh[i];
        sscale = rsqrtf(t * (1.f / DM) + 1e-6f);
    }
    __syncthreads();
    float s2 = sscale;
    __half* ur = g_uh + (size_t)m * DM;
    ur[tid]       = __float2half_rn(t0 * s2 * w2[tid]);
    ur[tid + 256] = __float2half_rn(t1 * s2 * w2[tid + 256]);
    ur[tid + 512] = __float2half_rn(t2 * s2 * w2[tid + 512]);
}

// fuse_prep + aux (block 0 thread 0 writes aux scalar)
__global__ void fuse_prep_kernel(const float* __restrict__ fgw, const float* __restrict__ fgb,
                                 float* __restrict__ out) {
    __shared__ float sh[8];
    __shared__ float par[3];
    int n = blockIdx.x, tid = threadIdx.x;
    const float* med = g_tokens + ((size_t)n * 3 + 2) * DM;
    float s = med[tid] * fgw[tid] + med[tid + 256] * fgw[tid + 256] + med[tid + 512] * fgw[tid + 512];
    #pragma unroll
    for (int o = 16; o; o >>= 1) s += __shfl_xor_sync(0xffffffffu, s, o);
    if ((tid & 31) == 0) sh[tid >> 5] = s;
    __syncthreads();
    if (tid == 0) {
        float t = 0.f;
        #pragma unroll
        for (int i = 0; i < 8; i++) t += sh[i];
        float g = 1.f / (1.f + expf(-(t + fgb[0])));
        float tp0 = g_tpk[2 * n] * g_keep[2 * n];
        float tp1 = g_tpk[2 * n + 1] * g_keep[2 * n + 1];
        float den = tp0 + tp1;
        par[0] = g;
        par[1] = den > 0.f ? tp0 / den : 0.f;
        par[2] = den > 0.f ? tp1 / den : 0.f;
        if (n == 0) {
            float bal = 0.f;
            for (int e = 0; e < NE; e++)
                bal += (g_router_sum[e] / (float)NTOK) * (g_assign_sum[e] / (float)NTOK);
            bal *= (float)NE;
            out[(size_t)NTOK * DM] = 0.01f * bal + 0.001f * (g_z2 / (float)NTOK)
                + 0.001f * (1.f - (float)g_keepcnt / (float)NKA);
        }
    }
    __syncthreads();
    float g = par[0], w0 = par[1], w1 = par[2];
    const float* e0 = g_tokens + ((size_t)n * 3 + 0) * DM;
    const float* e1 = g_tokens + ((size_t)n * 3 + 1) * DM;
    __half* fm = g_fmh + (size_t)n * DM;
    #pragma unroll
    for (int c = 0; c < 3; c++) {
        int d = tid + c * 256;
        fm[d] = __float2half_rn(g * med[d] + (1.f - g) * (w0 * e0[d] + w1 * e1[d]));
    }
}

// ---------------- launch ----------------
extern "C" void kernel_launch(void* const* d_in, const int* in_sizes, int n_in,
                              void* d_out, int out_size) {
    const float* x          = (const float*)d_in[0];
    const float* gate_w     = (const float*)d_in[1];
    const float* w13        = (const float*)d_in[2];
    const float* w2         = (const float*)d_in[3];
    const float* in_proj_w  = (const float*)d_in[4];
    const float* in_proj_b  = (const float*)d_in[5];
    const float* out_w      = (const float*)d_in[6];
    const float* out_b      = (const float*)d_in[7];
    const float* norm1_w    = (const float*)d_in[8];
    const float* norm2_w    = (const float*)d_in[9];
    const float* ffn_w1     = (const float*)d_in[10];
    const float* ffn_w2     = (const float*)d_in[11];
    const float* mediator   = (const float*)d_in[12];
    const float* fuse_gate_w= (const float*)d_in[13];
    const float* fuse_gate_b= (const float*)d_in[14];
    const float* o_proj_w   = (const float*)d_in[15];
    float* out = (float*)d_out;

    float* p_tokens;
    __half *p_tokh, *p_ipwh, *p_owh, *p_f1h, *p_f2h, *p_oph;
    __half *p_qkvh, *p_attnh, *p_uh, *p_hh, *p_fmh;
    cudaGetSymbolAddress((void**)&p_tokens, g_tokens);
    cudaGetSymbolAddress((void**)&p_tokh, g_tokh);
    cudaGetSymbolAddress((void**)&p_ipwh, g_ipwh);
    cudaGetSymbolAddress((void**)&p_owh, g_owh);
    cudaGetSymbolAddress((void**)&p_f1h, g_f1h);
    cudaGetSymbolAddress((void**)&p_f2h, g_f2h);
    cudaGetSymbolAddress((void**)&p_oph, g_oph);
    cudaGetSymbolAddress((void**)&p_qkvh, g_qkvh);
    cudaGetSymbolAddress((void**)&p_attnh, g_attnh);
    cudaGetSymbolAddress((void**)&p_uh, g_uh);
    cudaGetSymbolAddress((void**)&p_hh, g_hh);
    cudaGetSymbolAddress((void**)&p_fmh, g_fmh);

    cudaFuncSetAttribute(gemm_h<true,  false, false, true,  false>, cudaFuncAttributeMaxDynamicSharedMemorySize, SMEMB);
    cudaFuncSetAttribute(gemm_h<true,  true,  false, false, false>, cudaFuncAttributeMaxDynamicSharedMemorySize, SMEMB);
    cudaFuncSetAttribute(gemm_h<false, false, true,  true,  false>, cudaFuncAttributeMaxDynamicSharedMemorySize, SMEMB);
    cudaFuncSetAttribute(gemm_h<false, true,  false, false, true >, cudaFuncAttributeMaxDynamicSharedMemorySize, SMEMB);
    cudaFuncSetAttribute(gemm_h<false, false, false, false, false>, cudaFuncAttributeMaxDynamicSharedMemorySize, SMEMB);
    cudaFuncSetAttribute(expA_h, cudaFuncAttributeMaxDynamicSharedMemorySize, SMEMB);
    cudaFuncSetAttribute(expB_h, cudaFuncAttributeMaxDynamicSharedMemorySize, SMEMB);

    // fork a side stream inside the capture for the independent cvt work
    cudaStream_t s2;
    cudaStreamCreateWithFlags(&s2, cudaStreamNonBlocking);
    cudaEvent_t evF, evJ;
    cudaEventCreateWithFlags(&evF, cudaEventDisableTiming);
    cudaEventCreateWithFlags(&evJ, cudaEventDisableTiming);

    cudaEventRecord(evF, 0);
    cudaStreamWaitEvent(s2, evF, 0);
    cvt_combined_kernel<<<(int)((W13_U4 + 2 * X_U4 + 255) / 256), 256, 0, s2>>>(w13, x, mediator);
    cvtw_all_kernel<<<(int)((CVTW_TOTAL + 255) / 256), 256, 0, s2>>>(
        w2, in_proj_w, out_w, ffn_w1, ffn_w2, o_proj_w);
    cudaEventRecord(evJ, s2);

    zero_accum_kernel<<<1, 32>>>();
    gate_kernel<<<NTOK / 8, 256>>>(x, gate_w, out);
    build_tiles_kernel<<<1, 1>>>();
    scatter_kernel<<<NKA / 256, 256>>>();
    keep_kernel<<<NKA / 256, 256>>>();

    cudaStreamWaitEvent(0, evJ, 0);

    expA_h<<<dim3(MAXT, 2 * HF / 128), 256, SMEMB>>>();
    expB_h<<<dim3(MAXT, DM / 128), 256, SMEMB>>>(x);

    for (int step = 0; step < 2; step++) {
        gemm_h<true, false, false, true, false><<<dim3(MROW / 128, QKVW / 128), 256, SMEMB>>>(
            p_tokh, p_ipwh, in_proj_b, nullptr, p_qkvh, nullptr, QKVW, DM);
        attn_kernel<<<NTOK, 128>>>();
        gemm_h<true, true, false, false, false><<<dim3(MROW / 128, DM / 128), 256, SMEMB>>>(
            p_attnh, p_owh, out_b, p_tokens, p_tokens, nullptr, DM, DM);
        rms_dual_kernel<<<MROW, 256>>>(norm1_w, norm2_w);
        gemm_h<false, false, true, true, false><<<dim3(MROW / 128, DM / 128), 256, SMEMB>>>(
            p_uh, p_f1h, nullptr, nullptr, p_hh, nullptr, DM, DM);
        gemm_h<false, true, false, false, true><<<dim3(MROW / 128, DM / 128), 256, SMEMB>>>(
            p_hh, p_f2h, nullptr, p_tokens, p_tokens, p_tokh, DM, DM);
    }

    fuse_prep_kernel<<<NTOK, 256>>>(fuse_gate_w, fuse_gate_b, out);
    gemm_h<false, false, false, false, false><<<dim3(NTOK / 128, DM / 128), 256, SMEMB>>>(
        p_fmh, p_oph, nullptr, nullptr, out, nullptr, DM, DM);
}

// round 15
// speedup vs baseline: 1.0243x; 1.0077x over previous
#include <cuda_runtime.h>
#include <cuda_fp16.h>
#include <math.h>
#include <stdint.h>

#define NTOK 8192
#define DM   768
#define NE   8
#define NKA  16384
#define HF   2048
#define CAPC 4096
#define MROW 24576
#define QKVW 2304
#define MAXT 136

#define STGH  5120                 // 128*40 halves per matrix per stage
#define SMEMB (6 * STGH * 2)       // 3 stages x (A+B) = 61440 bytes

// ---------------- scratch ----------------
__device__ float g_router_sum[NE];
__device__ float g_assign_sum[NE];
__device__ float g_z2;
__device__ int   g_counts[NE];
__device__ int   g_fill[NE];
__device__ int   g_offsets[NE];
__device__ int   g_keepcnt;
__device__ int   g_te[NKA];
__device__ float g_prio[NKA];
__device__ float g_tpk[NKA];
__device__ float g_keep[NKA];
__device__ int   g_idx_list[NKA];
__device__ int   g_tile_e[MAXT];
__device__ int   g_tile_r0[MAXT];
__device__ int   g_tile_rows[MAXT];
__device__ int   g_ntiles;

__device__ float  g_tokens[(size_t)MROW * DM];
__device__ __half g_tokh[(size_t)MROW * DM];
__device__ __half g_acth[(size_t)(NKA + 128) * HF];
__device__ __half g_qkvh[(size_t)MROW * QKVW];
__device__ __half g_attnh[(size_t)MROW * DM];
__device__ __half g_uh[(size_t)MROW * DM];
__device__ __half g_hh[(size_t)MROW * DM];
__device__ __half g_fmh[(size_t)NTOK * DM];

__device__ __half g_xh[(size_t)NTOK * DM];              // 2*x
__device__ __half g_w13h[(size_t)NE * 2 * HF * DM];     // rows interleaved g/u
__device__ __half g_w2h[(size_t)NE * DM * HF];
__device__ __half g_ipwh[(size_t)QKVW * DM];
__device__ __half g_owh[(size_t)DM * DM];
__device__ __half g_f1h[(size_t)DM * DM];
__device__ __half g_f2h[(size_t)DM * DM];
__device__ __half g_oph[(size_t)DM * DM];

// ---------------- helpers ----------------
__device__ __forceinline__ uint32_t h2u(float a, float b) {
    __half2 h = __floats2half2_rn(a, b);
    return *(uint32_t*)&h;
}

__device__ __forceinline__ void cp16(void* smem, const void* gmem) {
    uint32_t s = (uint32_t)__cvta_generic_to_shared(smem);
    asm volatile("cp.async.cg.shared.global [%0], [%1], 16;" :: "r"(s), "l"(gmem));
}
#define CP_COMMIT() asm volatile("cp.async.commit_group;" ::: "memory")
#define CP_WAIT1()  asm volatile("cp.async.wait_group 1;" ::: "memory")

__device__ __forceinline__ void mma16(float* c, const uint32_t* a, const uint32_t* b) {
    asm volatile(
        "mma.sync.aligned.m16n8k16.row.col.f32.f16.f16.f32 "
        "{%0,%1,%2,%3},{%4,%5,%6,%7},{%8,%9},{%0,%1,%2,%3};"
        : "+f"(c[0]), "+f"(c[1]), "+f"(c[2]), "+f"(c[3])
        : "r"(a[0]), "r"(a[1]), "r"(a[2]), "r"(a[3]), "r"(b[0]), "r"(b[1]));
}

// one 128x128x32 tile: 8 warps, warp tile 64x32, 2 k-steps of 16
__device__ __forceinline__ void mma_tile_h(const __half* As, const __half* Bs,
                                           float acc[4][4][4], int lane, int warpM, int warpN) {
    int lr = lane >> 2, lq = (lane & 3) * 2;
    #pragma unroll
    for (int ks = 0; ks < 2; ks++) {
        int kb = ks * 16 + lq;
        uint32_t a[4][4], b[4][2];
        #pragma unroll
        for (int mf = 0; mf < 4; mf++) {
            int rb = warpM * 64 + mf * 16 + lr;
            a[mf][0] = *(const uint32_t*)(As + rb * 40 + kb);
            a[mf][1] = *(const uint32_t*)(As + (rb + 8) * 40 + kb);
            a[mf][2] = *(const uint32_t*)(As + rb * 40 + kb + 8);
            a[mf][3] = *(const uint32_t*)(As + (rb + 8) * 40 + kb + 8);
        }
        #pragma unroll
        for (int nf = 0; nf < 4; nf++) {
            int cb = warpN * 32 + nf * 8 + lr;
            b[nf][0] = *(const uint32_t*)(Bs + cb * 40 + kb);
            b[nf][1] = *(const uint32_t*)(Bs + cb * 40 + kb + 8);
        }
        #pragma unroll
        for (int mf = 0; mf < 4; mf++)
            #pragma unroll
            for (int nf = 0; nf < 4; nf++)
                mma16(acc[mf][nf], a[mf], b[nf]);
    }
}

// ---------------- generic NT GEMM (fp16, 3-stage cp.async pipeline) ----------------
template<bool BIAS, bool RES, bool GELU, bool HOUT, bool MIRROR>
__global__ void __launch_bounds__(256) gemm_h(
    const __half* __restrict__ A, const __half* __restrict__ B,
    const float* __restrict__ bias, const float* __restrict__ res,
    void* __restrict__ Cv, __half* __restrict__ mirror, int N, int K)
{
    extern __shared__ __half sm[];
    __half* As = sm;
    __half* Bs = sm + 3 * STGH;
    int tid = threadIdx.x, lane = tid & 31, warp = tid >> 5;
    int warpM = warp >> 2, warpN = warp & 3;
    size_t m0 = (size_t)blockIdx.x * 128;
    int n0 = blockIdx.y * 128;
    const __half* Ab = A + m0 * K;
    const __half* Bb = B + (size_t)n0 * K;
    float acc[4][4][4] = {};
    int r0w = tid >> 2, c8 = (tid & 3) * 8;
    int r1w = r0w + 64;
    int nch = K >> 5;

    #pragma unroll
    for (int p = 0; p < 2; p++) {
        int kk = p * 32;
        cp16(&As[p * STGH + r0w * 40 + c8], Ab + (size_t)r0w * K + kk + c8);
        cp16(&As[p * STGH + r1w * 40 + c8], Ab + (size_t)r1w * K + kk + c8);
        cp16(&Bs[p * STGH + r0w * 40 + c8], Bb + (size_t)r0w * K + kk + c8);
        cp16(&Bs[p * STGH + r1w * 40 + c8], Bb + (size_t)r1w * K + kk + c8);
        CP_COMMIT();
    }

    int s = 0, sl = 2;
    for (int c = 0; c < nch; c++) {
        CP_WAIT1();
        __syncthreads();
        if (c + 2 < nch) {
            int kk = (c + 2) * 32;
            cp16(&As[sl * STGH + r0w * 40 + c8], Ab + (size_t)r0w * K + kk + c8);
            cp16(&As[sl * STGH + r1w * 40 + c8], Ab + (size_t)r1w * K + kk + c8);
            cp16(&Bs[sl * STGH + r0w * 40 + c8], Bb + (size_t)r0w * K + kk + c8);
            cp16(&Bs[sl * STGH + r1w * 40 + c8], Bb + (size_t)r1w * K + kk + c8);
        }
        CP_COMMIT();
        mma_tile_h(As + s * STGH, Bs + s * STGH, acc, lane, warpM, warpN);
        if (++s == 3) s = 0;
        if (++sl == 3) sl = 0;
    }

    int lr = lane >> 2, lc = (lane & 3) * 2;
    #pragma unroll
    for (int mf = 0; mf < 4; mf++)
        #pragma unroll
        for (int h = 0; h < 2; h++) {
            size_t m = m0 + warpM * 64 + mf * 16 + lr + h * 8;
            #pragma unroll
            for (int nf = 0; nf < 4; nf++) {
                int col = n0 + warpN * 32 + nf * 8 + lc;
                float v0 = acc[mf][nf][h * 2], v1 = acc[mf][nf][h * 2 + 1];
                if (BIAS) { v0 += bias[col]; v1 += bias[col + 1]; }
                if (RES)  { v0 += res[m * N + col]; v1 += res[m * N + col + 1]; }
                if (GELU) {
                    v0 = 0.5f * v0 * (1.f + erff(v0 * 0.70710678118654752f));
                    v1 = 0.5f * v1 * (1.f + erff(v1 * 0.70710678118654752f));
                }
                if (HOUT) {
                    *(__half2*)((__half*)Cv + m * N + col) = __floats2half2_rn(v0, v1);
                } else {
                    *(float2*)((float*)Cv + m * N + col) = make_float2(v0, v1);
                    if (MIRROR)
                        *(__half2*)(mirror + m * N + col) = __floats2half2_rn(v0, v1);
                }
            }
        }
}

// ---------------- expert pass A: fused gu GEMM + SiLU ----------------
__global__ void __launch_bounds__(256) expA_h()
{
    int t = blockIdx.x;
    if (t >= g_ntiles) return;
    extern __shared__ __half sm[];
    __half* As = sm;
    __half* Bs = sm + 3 * STGH;
    __shared__ int tok[128];
    int tid = threadIdx.x, lane = tid & 31, warp = tid >> 5;
    int warpM = warp >> 2, warpN = warp & 3;
    int e = g_tile_e[t], r0 = g_tile_r0[t], rows = g_tile_rows[t];
    int n0 = blockIdx.y * 128;
    if (tid < 128) tok[tid] = (tid < rows) ? (g_idx_list[r0 + tid] >> 1) : 0;
    __syncthreads();
    const __half* Bb = g_w13h + (size_t)e * 2 * HF * DM + (size_t)n0 * DM;
    float acc[4][4][4] = {};
    int r0w = tid >> 2, c8 = (tid & 3) * 8;
    int r1w = r0w + 64;
    const __half* a0p = g_xh + (size_t)tok[r0w] * DM;
    const __half* a1p = g_xh + (size_t)tok[r1w] * DM;
    int nch = DM >> 5;

    #pragma unroll
    for (int p = 0; p < 2; p++) {
        int kk = p * 32;
        cp16(&As[p * STGH + r0w * 40 + c8], a0p + kk + c8);
        cp16(&As[p * STGH + r1w * 40 + c8], a1p + kk + c8);
        cp16(&Bs[p * STGH + r0w * 40 + c8], Bb + (size_t)r0w * DM + kk + c8);
        cp16(&Bs[p * STGH + r1w * 40 + c8], Bb + (size_t)r1w * DM + kk + c8);
        CP_COMMIT();
    }

    int s = 0, sl = 2;
    for (int c = 0; c < nch; c++) {
        CP_WAIT1();
        __syncthreads();
        if (c + 2 < nch) {
            int kk = (c + 2) * 32;
            cp16(&As[sl * STGH + r0w * 40 + c8], a0p + kk + c8);
            cp16(&As[sl * STGH + r1w * 40 + c8], a1p + kk + c8);
            cp16(&Bs[sl * STGH + r0w * 40 + c8], Bb + (size_t)r0w * DM + kk + c8);
            cp16(&Bs[sl * STGH + r1w * 40 + c8], Bb + (size_t)r1w * DM + kk + c8);
        }
        CP_COMMIT();
        mma_tile_h(As + s * STGH, Bs + s * STGH, acc, lane, warpM, warpN);
        if (++s == 3) s = 0;
        if (++sl == 3) sl = 0;
    }

    int lr = lane >> 2, lc = (lane & 3) * 2;
    int hbase = blockIdx.y * 64;
    #pragma unroll
    for (int mf = 0; mf < 4; mf++)
        #pragma unroll
        for (int h = 0; h < 2; h++) {
            int rl = warpM * 64 + mf * 16 + lr + h * 8;
            if (rl < rows) {
                __half* ap = g_acth + (size_t)(r0 + rl) * HF + hbase;
                #pragma unroll
                for (int nf = 0; nf < 4; nf++) {
                    int colt = warpN * 32 + nf * 8 + lc;
                    float g = acc[mf][nf][h * 2];
                    float u = acc[mf][nf][h * 2 + 1];
                    ap[colt >> 1] = __float2half_rn(g / (1.f + expf(-g)) * u);
                }
            }
        }
}

// ---------------- expert pass B ----------------
__global__ void __launch_bounds__(256) expB_h(const float* __restrict__ x)
{
    int t = blockIdx.x;
    if (t >= g_ntiles) return;
    extern __shared__ __half sm[];
    __half* As = sm;
    __half* Bs = sm + 3 * STGH;
    __shared__ int s_asn[128];
    int tid = threadIdx.x, lane = tid & 31, warp = tid >> 5;
    int warpM = warp >> 2, warpN = warp & 3;
    int e = g_tile_e[t], r0 = g_tile_r0[t], rows = g_tile_rows[t];
    int n0 = blockIdx.y * 128;
    if (tid < 128) s_asn[tid] = (tid < rows) ? g_idx_list[r0 + tid] : 0;
    const __half* Ab = g_acth + (size_t)r0 * HF;
    const __half* Bb = g_w2h + (size_t)e * DM * HF + (size_t)n0 * HF;
    float acc[4][4][4] = {};
    int r0w = tid >> 2, c8 = (tid & 3) * 8;
    int r1w = r0w + 64;
    int nch = HF >> 5;

    #pragma unroll
    for (int p = 0; p < 2; p++) {
        int kk = p * 32;
        cp16(&As[p * STGH + r0w * 40 + c8], Ab + (size_t)r0w * HF + kk + c8);
        cp16(&As[p * STGH + r1w * 40 + c8], Ab + (size_t)r1w * HF + kk + c8);
        cp16(&Bs[p * STGH + r0w * 40 + c8], Bb + (size_t)r0w * HF + kk + c8);
        cp16(&Bs[p * STGH + r1w * 40 + c8], Bb + (size_t)r1w * HF + kk + c8);
        CP_COMMIT();
    }

    int s = 0, sl = 2;
    for (int c = 0; c < nch; c++) {
        CP_WAIT1();
        __syncthreads();
        if (c + 2 < nch) {
            int kk = (c + 2) * 32;
            cp16(&As[sl * STGH + r0w * 40 + c8], Ab + (size_t)r0w * HF + kk + c8);
            cp16(&As[sl * STGH + r1w * 40 + c8], Ab + (size_t)r1w * HF + kk + c8);
            cp16(&Bs[sl * STGH + r0w * 40 + c8], Bb + (size_t)r0w * HF + kk + c8);
            cp16(&Bs[sl * STGH + r1w * 40 + c8], Bb + (size_t)r1w * HF + kk + c8);
        }
        CP_COMMIT();
        mma_tile_h(As + s * STGH, Bs + s * STGH, acc, lane, warpM, warpN);
        if (++s == 3) s = 0;
        if (++sl == 3) sl = 0;
    }

    int lr = lane >> 2, lc = (lane & 3) * 2;
    #pragma unroll
    for (int mf = 0; mf < 4; mf++)
        #pragma unroll
        for (int h = 0; h < 2; h++) {
            int rl = warpM * 64 + mf * 16 + lr + h * 8;
            if (rl < rows) {
                int a = s_asn[rl];
                int n = a >> 1, slot = a & 1;
                float kp = g_keep[a];
                const float* xr = x + (size_t)n * DM + n0;
                size_t base = ((size_t)n * 3 + slot) * DM + n0;
                #pragma unroll
                for (int nf = 0; nf < 4; nf++) {
                    int col = warpN * 32 + nf * 8 + lc;
                    float v0 = kp * (xr[col]     + acc[mf][nf][h * 2]);
                    float v1 = kp * (xr[col + 1] + acc[mf][nf][h * 2 + 1]);
                    *(float2*)(g_tokens + base + col) = make_float2(v0, v1);
                    *(__half2*)(g_tokh + base + col) = __floats2half2_rn(v0, v1);
                }
            }
        }
}

// ---------------- combined cvt: w13 (interleaved) + x (alpha=2) + mediator init ----------------
#define W13_U4 ((size_t)NE * 2 * HF * DM / 8)
#define X_U4   ((size_t)NTOK * DM / 8)
__global__ void cvt_combined_kernel(const float* __restrict__ w13,
                                    const float* __restrict__ x,
                                    const float* __restrict__ mediator) {
    size_t j = (size_t)blockIdx.x * 256 + threadIdx.x;
    if (j < W13_U4) {
        size_t per_e = (size_t)2 * HF * DM / 8;
        size_t e = j / per_e;
        size_t rem = j - e * per_e;
        int rp = (int)(rem / (DM / 8));
        int d8 = (int)(rem % (DM / 8));
        int h = rp >> 1;
        int src = (rp & 1) ? (HF + h) : h;
        const float* sp = w13 + (size_t)e * 2 * HF * DM + (size_t)src * DM + d8 * 8;
        float4 v0 = *(const float4*)sp;
        float4 v1 = *(const float4*)(sp + 4);
        uint4 o;
        o.x = h2u(v0.x, v0.y); o.y = h2u(v0.z, v0.w);
        o.z = h2u(v1.x, v1.y); o.w = h2u(v1.z, v1.w);
        ((uint4*)g_w13h)[j] = o;
    } else if (j < W13_U4 + X_U4) {
        size_t i = j - W13_U4;
        const float* sp = x + i * 8;
        float4 v0 = *(const float4*)sp;
        float4 v1 = *(const float4*)(sp + 4);
        uint4 o;
        o.x = h2u(2.f * v0.x, 2.f * v0.y); o.y = h2u(2.f * v0.z, 2.f * v0.w);
        o.z = h2u(2.f * v1.x, 2.f * v1.y); o.w = h2u(2.f * v1.z, 2.f * v1.w);
        ((uint4*)g_xh)[i] = o;
    } else if (j < W13_U4 + 2 * X_U4) {
        size_t i = j - W13_U4 - X_U4;
        size_t n = i / (DM / 8);
        int d8 = (int)(i % (DM / 8)) * 8;
        const float* sp = mediator + d8;
        float4 v0 = *(const float4*)sp;
        float4 v1 = *(const float4*)(sp + 4);
        size_t base = (n * 3 + 2) * DM + d8;
        *(float4*)(g_tokens + base) = v0;
        *(float4*)(g_tokens + base + 4) = v1;
        uint4 o;
        o.x = h2u(v0.x, v0.y); o.y = h2u(v0.z, v0.w);
        o.z = h2u(v1.x, v1.y); o.w = h2u(v1.z, v1.w);
        *(uint4*)(g_tokh + base) = o;
    }
}

// ---------------- all remaining weight cvts in ONE kernel ----------------
#define W2_U4  ((size_t)NE * DM * HF / 8)
#define IPW_U4 ((size_t)QKVW * DM / 8)
#define DD_U4  ((size_t)DM * DM / 8)
#define CVTW_TOTAL (W2_U4 + IPW_U4 + 4 * DD_U4)
__global__ void cvtw_all_kernel(const float* __restrict__ w2,
                                const float* __restrict__ ipw,
                                const float* __restrict__ ow,
                                const float* __restrict__ f1,
                                const float* __restrict__ f2,
                                const float* __restrict__ op) {
    size_t j = (size_t)blockIdx.x * 256 + threadIdx.x;
    if (j >= CVTW_TOTAL) return;
    const float* src;
    __half* dst;
    size_t i = j;
    if (i < W2_U4) { src = w2; dst = g_w2h; }
    else {
        i -= W2_U4;
        if (i < IPW_U4) { src = ipw; dst = g_ipwh; }
        else {
            i -= IPW_U4;
            if (i < DD_U4) { src = ow; dst = g_owh; }
            else {
                i -= DD_U4;
                if (i < DD_U4) { src = f1; dst = g_f1h; }
                else {
                    i -= DD_U4;
                    if (i < DD_U4) { src = f2; dst = g_f2h; }
                    else { i -= DD_U4; src = op; dst = g_oph; }
                }
            }
        }
    }
    const float* sp = src + i * 8;
    float4 v0 = *(const float4*)sp;
    float4 v1 = *(const float4*)(sp + 4);
    uint4 o;
    o.x = h2u(v0.x, v0.y); o.y = h2u(v0.z, v0.w);
    o.z = h2u(v1.x, v1.y); o.w = h2u(v1.z, v1.w);
    ((uint4*)dst)[i] = o;
}

// ---------------- small kernels ----------------
__global__ void zero_accum_kernel() {
    int t = threadIdx.x;
    if (t < NE) { g_router_sum[t] = 0.f; g_assign_sum[t] = 0.f; g_counts[t] = 0; g_fill[t] = 0; }
    if (t == 0) { g_z2 = 0.f; g_keepcnt = 0; }
}

__global__ void __launch_bounds__(256) gate_kernel(const float* __restrict__ x,
                                                   const float* __restrict__ gw,
                                                   float* __restrict__ out) {
    __shared__ float wsh[NE * DM];
    __shared__ float s_rs[NE], s_as[NE], s_z2s;
    __shared__ int   s_c[NE];
    int tid = threadIdx.x;
    for (int i = tid; i < NE * DM; i += 256) wsh[i] = gw[i];
    if (tid < NE) { s_rs[tid] = 0.f; s_as[tid] = 0.f; s_c[tid] = 0; }
    if (tid == 0) s_z2s = 0.f;
    __syncthreads();
    int warp = tid >> 5, lane = tid & 31;
    int n = blockIdx.x * 8 + warp;
    const float* xr = x + (size_t)n * DM;
    float xv[24];
    #pragma unroll
    for (int i = 0; i < 24; i++) xv[i] = xr[lane + i * 32];
    float l[NE];
    #pragma unroll
    for (int e = 0; e < NE; e++) {
        float sv = 0.f;
        const float* w = wsh + e * DM;
        #pragma unroll
        for (int i = 0; i < 24; i++) sv += xv[i] * w[lane + i * 32];
        #pragma unroll
        for (int o = 16; o; o >>= 1) sv += __shfl_xor_sync(0xffffffffu, sv, o);
        l[e] = sv;
    }
    if (lane == 0) {
        int i1 = 0; float v1 = l[0];
        #pragma unroll
        for (int e = 1; e < NE; e++) if (l[e] > v1) { v1 = l[e]; i1 = e; }
        int i2 = -1; float v2 = -3.4e38f;
        #pragma unroll
        for (int e = 0; e < NE; e++) if (e != i1 && l[e] > v2) { v2 = l[e]; i2 = e; }
        float e2 = expf(v2 - v1);
        float inv = 1.f / (1.f + e2);
        float p1 = inv, p2 = e2 * inv;
        float se = 0.f;
        #pragma unroll
        for (int e = 0; e < NE; e++) se += expf(l[e] - v1);
        float z = v1 + logf(se);
        #pragma unroll
        for (int e = 0; e < NE; e++) atomicAdd(&s_rs[e], expf(l[e] - v1) / se);
        atomicAdd(&s_as[i1], p1);
        atomicAdd(&s_as[i2], p2);
        atomicAdd(&s_z2s, z * z);
        atomicAdd(&s_c[i1], 1);
        atomicAdd(&s_c[i2], 1);
        g_te[2 * n] = i1; g_te[2 * n + 1] = i2;
        g_prio[2 * n] = v1; g_prio[2 * n + 1] = v2;
        g_tpk[2 * n] = p1; g_tpk[2 * n + 1] = p2;
        out[(size_t)NTOK * DM + 1 + 2 * n]     = (float)i1;
        out[(size_t)NTOK * DM + 1 + 2 * n + 1] = (float)i2;
    }
    __syncthreads();
    if (tid < NE) {
        atomicAdd(&g_router_sum[tid], s_rs[tid]);
        atomicAdd(&g_assign_sum[tid], s_as[tid]);
        atomicAdd(&g_counts[tid], s_c[tid]);
    }
    if (tid == 0) atomicAdd(&g_z2, s_z2s);
}

__global__ void build_tiles_kernel() {
    if (threadIdx.x != 0 || blockIdx.x != 0) return;
    int off = 0, nt = 0;
    for (int e = 0; e < NE; e++) {
        g_offsets[e] = off;
        int c = g_counts[e];
        int ntile = (c + 127) >> 7;
        for (int t = 0; t < ntile; t++) {
            g_tile_e[nt] = e;
            g_tile_r0[nt] = off + t * 128;
            int r = c - t * 128;
            g_tile_rows[nt] = r < 128 ? r : 128;
            nt++;
        }
        off += c;
    }
    g_ntiles = nt;
}

__global__ void scatter_kernel() {
    int i = blockIdx.x * 256 + threadIdx.x;
    if (i >= NKA) return;
    int e = g_te[i];
    int p = atomicAdd(&g_fill[e], 1);
    g_idx_list[g_offsets[e] + p] = i;
}

__global__ void keep_kernel() {
    int i = blockIdx.x * 256 + threadIdx.x;
    if (i >= NKA) return;
    int e = g_te[i];
    int kp;
    if (g_counts[e] <= CAPC) {
        kp = 1;
    } else {
        float pi = g_prio[i];
        int rank = 0;
        for (int j = 0; j < NKA; j++) {
            if (g_te[j] == e) {
                float pj = g_prio[j];
                if (pj > pi || (pj == pi && j < i)) rank++;
            }
        }
        kp = (rank < CAPC) ? 1 : 0;
    }
    g_keep[i] = (float)kp;
    atomicAdd(&g_keepcnt, kp);
}

// 2 tokens per block (8 warps), half2-vectorized loads/stores
__global__ void __launch_bounds__(256) attn_kernel() {
    int warp = threadIdx.x >> 5, lane = threadIdx.x & 31;
    int n = blockIdx.x * 2 + (warp >> 2);
    int h = warp & 3;
    const __half* base = g_qkvh + (size_t)n * 3 * QKVW + h * 192 + lane * 6;
    float q[3][6], k[3][6], v[3][6];
    #pragma unroll
    for (int li = 0; li < 3; li++) {
        const __half* bp = base + (size_t)li * QKVW;
        #pragma unroll
        for (int seg = 0; seg < 3; seg++) {
            const __half* mp = bp + seg * DM;        // q/k/v
            float2 p0 = __half22float2(*(const __half2*)(mp));
            float2 p1 = __half22float2(*(const __half2*)(mp + 2));
            float2 p2 = __half22float2(*(const __half2*)(mp + 4));
            float* d = (seg == 0) ? q[li] : (seg == 1) ? k[li] : v[li];
            d[0] = p0.x; d[1] = p0.y; d[2] = p1.x; d[3] = p1.y; d[4] = p2.x; d[5] = p2.y;
        }
    }
    const float scale = 0.07216878364870322f;
    float b0 = (g_keep[2 * n]     > 0.5f) ? 0.f : -1e9f;
    float b1 = (g_keep[2 * n + 1] > 0.5f) ? 0.f : -1e9f;
    float s[3][3];
    #pragma unroll
    for (int qi = 0; qi < 3; qi++) {
        #pragma unroll
        for (int kj = 0; kj < 3; kj++) {
            float t = 0.f;
            #pragma unroll
            for (int dd = 0; dd < 6; dd++) t += q[qi][dd] * k[kj][dd];
            #pragma unroll
            for (int o = 16; o; o >>= 1) t += __shfl_xor_sync(0xffffffffu, t, o);
            s[qi][kj] = t * scale;
        }
        s[qi][0] += b0;
        s[qi][1] += b1;
    }
    #pragma unroll
    for (int qi = 0; qi < 3; qi++) {
        float m = fmaxf(s[qi][0], fmaxf(s[qi][1], s[qi][2]));
        float e0 = expf(s[qi][0] - m), e1 = expf(s[qi][1] - m), e2 = expf(s[qi][2] - m);
        float inv = 1.f / (e0 + e1 + e2);
        float a0 = e0 * inv, a1 = e1 * inv, a2 = e2 * inv;
        __half* op = g_attnh + (size_t)(n * 3 + qi) * DM + h * 192 + lane * 6;
        #pragma unroll
        for (int p = 0; p < 3; p++) {
            float o0 = a0 * v[0][2 * p]     + a1 * v[1][2 * p]     + a2 * v[2][2 * p];
            float o1 = a0 * v[0][2 * p + 1] + a1 * v[1][2 * p + 1] + a2 * v[2][2 * p + 1];
            *(__half2*)(op + 2 * p) = __floats2half2_rn(o0, o1);
        }
    }
}

__global__ void rms_dual_kernel(const float* __restrict__ w1, const float* __restrict__ w2) {
    __shared__ float sh[8];
    __shared__ float sscale;
    int m = blockIdx.x, tid = threadIdx.x;
    float* row = g_tokens + (size_t)m * DM;
    float v0 = row[tid], v1 = row[tid + 256], v2 = row[tid + 512];
    float ss = v0 * v0 + v1 * v1 + v2 * v2;
    #pragma unroll
    for (int o = 16; o; o >>= 1) ss += __shfl_xor_sync(0xffffffffu, ss, o);
    if ((tid & 31) == 0) sh[tid >> 5] = ss;
    __syncthreads();
    if (tid == 0) {
        float t = 0.f;
        #pragma unroll
        for (int i = 0; i < 8; i++) t += sh[i];
        sscale = rsqrtf(t * (1.f / DM) + 1e-6f);
    }
    __syncthreads();
    float s1 = sscale;
    float t0 = v0 * s1 * w1[tid];
    float t1 = v1 * s1 * w1[tid + 256];
    float t2 = v2 * s1 * w1[tid + 512];
    row[tid] = t0; row[tid + 256] = t1; row[tid + 512] = t2;
    float ss2 = t0 * t0 + t1 * t1 + t2 * t2;
    #pragma unroll
    for (int o = 16; o; o >>= 1) ss2 += __shfl_xor_sync(0xffffffffu, ss2, o);
    __syncthreads();
    if ((tid & 31) == 0) sh[tid >> 5] = ss2;
    __syncthreads();
    if (tid == 0) {
        float t = 0.f;
        #pragma unroll
        for (int i = 0; i < 8; i++) t += sh[i];
        sscale = rsqrtf(t * (1.f / DM) + 1e-6f);
    }
    __syncthreads();
    float s2 = sscale;
    __half* ur = g_uh + (size_t)m * DM;
    ur[tid]       = __float2half_rn(t0 * s2 * w2[tid]);
    ur[tid + 256] = __float2half_rn(t1 * s2 * w2[tid + 256]);
    ur[tid + 512] = __float2half_rn(t2 * s2 * w2[tid + 512]);
}

// fuse_prep + aux (block 0 thread 0 writes aux scalar)
__global__ void fuse_prep_kernel(const float* __restrict__ fgw, const float* __restrict__ fgb,
                                 float* __restrict__ out) {
    __shared__ float sh[8];
    __shared__ float par[3];
    int n = blockIdx.x, tid = threadIdx.x;
    const float* med = g_tokens + ((size_t)n * 3 + 2) * DM;
    float s = med[tid] * fgw[tid] + med[tid + 256] * fgw[tid + 256] + med[tid + 512] * fgw[tid + 512];
    #pragma unroll
    for (int o = 16; o; o >>= 1) s += __shfl_xor_sync(0xffffffffu, s, o);
    if ((tid & 31) == 0) sh[tid >> 5] = s;
    __syncthreads();
    if (tid == 0) {
        float t = 0.f;
        #pragma unroll
        for (int i = 0; i < 8; i++) t += sh[i];
        float g = 1.f / (1.f + expf(-(t + fgb[0])));
        float tp0 = g_tpk[2 * n] * g_keep[2 * n];
        float tp1 = g_tpk[2 * n + 1] * g_keep[2 * n + 1];
        float den = tp0 + tp1;
        par[0] = g;
        par[1] = den > 0.f ? tp0 / den : 0.f;
        par[2] = den > 0.f ? tp1 / den : 0.f;
        if (n == 0) {
            float bal = 0.f;
            for (int e = 0; e < NE; e++)
                bal += (g_router_sum[e] / (float)NTOK) * (g_assign_sum[e] / (float)NTOK);
            bal *= (float)NE;
            out[(size_t)NTOK * DM] = 0.01f * bal + 0.001f * (g_z2 / (float)NTOK)
                + 0.001f * (1.f - (float)g_keepcnt / (float)NKA);
        }
    }
    __syncthreads();
    float g = par[0], w0 = par[1], w1 = par[2];
    const float* e0 = g_tokens + ((size_t)n * 3 + 0) * DM;
    const float* e1 = g_tokens + ((size_t)n * 3 + 1) * DM;
    __half* fm = g_fmh + (size_t)n * DM;
    #pragma unroll
    for (int c = 0; c < 3; c++) {
        int d = tid + c * 256;
        fm[d] = __float2half_rn(g * med[d] + (1.f - g) * (w0 * e0[d] + w1 * e1[d]));
    }
}

// ---------------- launch ----------------
extern "C" void kernel_launch(void* const* d_in, const int* in_sizes, int n_in,
                              void* d_out, int out_size) {
    const float* x          = (const float*)d_in[0];
    const float* gate_w     = (const float*)d_in[1];
    const float* w13        = (const float*)d_in[2];
    const float* w2         = (const float*)d_in[3];
    const float* in_proj_w  = (const float*)d_in[4];
    const float* in_proj_b  = (const float*)d_in[5];
    const float* out_w      = (const float*)d_in[6];
    const float* out_b      = (const float*)d_in[7];
    const float* norm1_w    = (const float*)d_in[8];
    const float* norm2_w    = (const float*)d_in[9];
    const float* ffn_w1     = (const float*)d_in[10];
    const float* ffn_w2     = (const float*)d_in[11];
    const float* mediator   = (const float*)d_in[12];
    const float* fuse_gate_w= (const float*)d_in[13];
    const float* fuse_gate_b= (const float*)d_in[14];
    const float* o_proj_w   = (const float*)d_in[15];
    float* out = (float*)d_out;

    float* p_tokens;
    __half *p_tokh, *p_ipwh, *p_owh, *p_f1h, *p_f2h, *p_oph;
    __half *p_qkvh, *p_attnh, *p_uh, *p_hh, *p_fmh;
    cudaGetSymbolAddress((void**)&p_tokens, g_tokens);
    cudaGetSymbolAddress((void**)&p_tokh, g_tokh);
    cudaGetSymbolAddress((void**)&p_ipwh, g_ipwh);
    cudaGetSymbolAddress((void**)&p_owh, g_owh);
    cudaGetSymbolAddress((void**)&p_f1h, g_f1h);
    cudaGetSymbolAddress((void**)&p_f2h, g_f2h);
    cudaGetSymbolAddress((void**)&p_oph, g_oph);
    cudaGetSymbolAddress((void**)&p_qkvh, g_qkvh);
    cudaGetSymbolAddress((void**)&p_attnh, g_attnh);
    cudaGetSymbolAddress((void**)&p_uh, g_uh);
    cudaGetSymbolAddress((void**)&p_hh, g_hh);
    cudaGetSymbolAddress((void**)&p_fmh, g_fmh);

    cudaFuncSetAttribute(gemm_h<true,  false, false, true,  false>, cudaFuncAttributeMaxDynamicSharedMemorySize, SMEMB);
    cudaFuncSetAttribute(gemm_h<true,  true,  false, false, false>, cudaFuncAttributeMaxDynamicSharedMemorySize, SMEMB);
    cudaFuncSetAttribute(gemm_h<false, false, true,  true,  false>, cudaFuncAttributeMaxDynamicSharedMemorySize, SMEMB);
    cudaFuncSetAttribute(gemm_h<false, true,  false, false, true >, cudaFuncAttributeMaxDynamicSharedMemorySize, SMEMB);
    cudaFuncSetAttribute(gemm_h<false, false, false, false, false>, cudaFuncAttributeMaxDynamicSharedMemorySize, SMEMB);
    cudaFuncSetAttribute(expA_h, cudaFuncAttributeMaxDynamicSharedMemorySize, SMEMB);
    cudaFuncSetAttribute(expB_h, cudaFuncAttributeMaxDynamicSharedMemorySize, SMEMB);

    // fork a side stream inside the capture for the independent cvt work
    cudaStream_t s2;
    cudaStreamCreateWithFlags(&s2, cudaStreamNonBlocking);
    cudaEvent_t evF, evJ;
    cudaEventCreateWithFlags(&evF, cudaEventDisableTiming);
    cudaEventCreateWithFlags(&evJ, cudaEventDisableTiming);

    cudaEventRecord(evF, 0);
    cudaStreamWaitEvent(s2, evF, 0);
    cvt_combined_kernel<<<(int)((W13_U4 + 2 * X_U4 + 255) / 256), 256, 0, s2>>>(w13, x, mediator);
    cvtw_all_kernel<<<(int)((CVTW_TOTAL + 255) / 256), 256, 0, s2>>>(
        w2, in_proj_w, out_w, ffn_w1, ffn_w2, o_proj_w);
    cudaEventRecord(evJ, s2);

    zero_accum_kernel<<<1, 32>>>();
    gate_kernel<<<NTOK / 8, 256>>>(x, gate_w, out);
    build_tiles_kernel<<<1, 1>>>();
    scatter_kernel<<<NKA / 256, 256>>>();
    keep_kernel<<<NKA / 256, 256>>>();

    cudaStreamWaitEvent(0, evJ, 0);

    expA_h<<<dim3(MAXT, 2 * HF / 128), 256, SMEMB>>>();
    expB_h<<<dim3(MAXT, DM / 128), 256, SMEMB>>>(x);

    for (int step = 0; step < 2; step++) {
        gemm_h<true, false, false, true, false><<<dim3(MROW / 128, QKVW / 128), 256, SMEMB>>>(
            p_tokh, p_ipwh, in_proj_b, nullptr, p_qkvh, nullptr, QKVW, DM);
        attn_kernel<<<NTOK / 2, 256>>>();
        gemm_h<true, true, false, false, false><<<dim3(MROW / 128, DM / 128), 256, SMEMB>>>(
            p_attnh, p_owh, out_b, p_tokens, p_tokens, nullptr, DM, DM);
        rms_dual_kernel<<<MROW, 256>>>(norm1_w, norm2_w);
        gemm_h<false, false, true, true, false><<<dim3(MROW / 128, DM / 128), 256, SMEMB>>>(
            p_uh, p_f1h, nullptr, nullptr, p_hh, nullptr, DM, DM);
        gemm_h<false, true, false, false, true><<<dim3(MROW / 128, DM / 128), 256, SMEMB>>>(
            p_hh, p_f2h, nullptr, p_tokens, p_tokens, p_tokh, DM, DM);
    }

    fuse_prep_kernel<<<NTOK, 256>>>(fuse_gate_w, fuse_gate_b, out);
    gemm_h<false, false, false, false, false><<<dim3(NTOK / 128, DM / 128), 256, SMEMB>>>(
        p_fmh, p_oph, nullptr, nullptr, out, nullptr, DM, DM);
}

// round 16
// speedup vs baseline: 1.0618x; 1.0366x over previous
#include <cuda_runtime.h>
#include <cuda_fp16.h>
#include <math.h>
#include <stdint.h>

#define NTOK 8192
#define DM   768
#define NE   8
#define NKA  16384
#define HF   2048
#define CAPC 4096
#define MROW 24576
#define QKVW 2304
#define MAXT 136

#define STGH  5120                 // 128*40 halves per matrix per stage
#define SMEMB (6 * STGH * 2)       // 3 stages x (A+B) = 61440 bytes

// ---------------- scratch ----------------
__device__ float g_router_sum[NE];
__device__ float g_assign_sum[NE];
__device__ float g_z2;
__device__ int   g_counts[NE];
__device__ int   g_fill[NE];
__device__ int   g_offsets[NE];
__device__ int   g_keepcnt;
__device__ int   g_te[NKA];
__device__ float g_prio[NKA];
__device__ float g_tpk[NKA];
__device__ float g_keep[NKA];
__device__ int   g_idx_list[NKA];
__device__ int   g_tile_e[MAXT];
__device__ int   g_tile_r0[MAXT];
__device__ int   g_tile_rows[MAXT];
__device__ int   g_ntiles;

__device__ float  g_tokens[(size_t)MROW * DM];
__device__ __half g_tokh[(size_t)MROW * DM];
__device__ __half g_acth[(size_t)(NKA + 128) * HF];
__device__ __half g_qkvh[(size_t)MROW * QKVW];
__device__ __half g_qkvmed[QKVW];
__device__ __half g_attnh[(size_t)MROW * DM];
__device__ __half g_uh[(size_t)MROW * DM];
__device__ __half g_hh[(size_t)MROW * DM];
__device__ __half g_fmh[(size_t)NTOK * DM];

__device__ __half g_xh[(size_t)NTOK * DM];              // 2*x
__device__ __half g_w13h[(size_t)NE * 2 * HF * DM];     // rows interleaved g/u
__device__ __half g_w2h[(size_t)NE * DM * HF];
__device__ __half g_ipwh[(size_t)QKVW * DM];
__device__ __half g_owh[(size_t)DM * DM];
__device__ __half g_f1h[(size_t)DM * DM];
__device__ __half g_f2h[(size_t)DM * DM];
__device__ __half g_oph[(size_t)DM * DM];

// ---------------- helpers ----------------
__device__ __forceinline__ uint32_t h2u(float a, float b) {
    __half2 h = __floats2half2_rn(a, b);
    return *(uint32_t*)&h;
}

__device__ __forceinline__ void cp16(void* smem, const void* gmem) {
    uint32_t s = (uint32_t)__cvta_generic_to_shared(smem);
    asm volatile("cp.async.cg.shared.global [%0], [%1], 16;" :: "r"(s), "l"(gmem));
}
#define CP_COMMIT() asm volatile("cp.async.commit_group;" ::: "memory")
#define CP_WAIT1()  asm volatile("cp.async.wait_group 1;" ::: "memory")

__device__ __forceinline__ void mma16(float* c, const uint32_t* a, const uint32_t* b) {
    asm volatile(
        "mma.sync.aligned.m16n8k16.row.col.f32.f16.f16.f32 "
        "{%0,%1,%2,%3},{%4,%5,%6,%7},{%8,%9},{%0,%1,%2,%3};"
        : "+f"(c[0]), "+f"(c[1]), "+f"(c[2]), "+f"(c[3])
        : "r"(a[0]), "r"(a[1]), "r"(a[2]), "r"(a[3]), "r"(b[0]), "r"(b[1]));
}

// one 128x128x32 tile: 8 warps, warp tile 64x32, 2 k-steps of 16
__device__ __forceinline__ void mma_tile_h(const __half* As, const __half* Bs,
                                           float acc[4][4][4], int lane, int warpM, int warpN) {
    int lr = lane >> 2, lq = (lane & 3) * 2;
    #pragma unroll
    for (int ks = 0; ks < 2; ks++) {
        int kb = ks * 16 + lq;
        uint32_t a[4][4], b[4][2];
        #pragma unroll
        for (int mf = 0; mf < 4; mf++) {
            int rb = warpM * 64 + mf * 16 + lr;
            a[mf][0] = *(const uint32_t*)(As + rb * 40 + kb);
            a[mf][1] = *(const uint32_t*)(As + (rb + 8) * 40 + kb);
            a[mf][2] = *(const uint32_t*)(As + rb * 40 + kb + 8);
            a[mf][3] = *(const uint32_t*)(As + (rb + 8) * 40 + kb + 8);
        }
        #pragma unroll
        for (int nf = 0; nf < 4; nf++) {
            int cb = warpN * 32 + nf * 8 + lr;
            b[nf][0] = *(const uint32_t*)(Bs + cb * 40 + kb);
            b[nf][1] = *(const uint32_t*)(Bs + cb * 40 + kb + 8);
        }
        #pragma unroll
        for (int mf = 0; mf < 4; mf++)
            #pragma unroll
            for (int nf = 0; nf < 4; nf++)
                mma16(acc[mf][nf], a[mf], b[nf]);
    }
}

// ---------------- generic NT GEMM (fp16, 3-stage cp.async pipeline) ----------------
template<bool BIAS, bool RES, bool GELU, bool HOUT, bool MIRROR>
__global__ void __launch_bounds__(256) gemm_h(
    const __half* __restrict__ A, const __half* __restrict__ B,
    const float* __restrict__ bias, const float* __restrict__ res,
    void* __restrict__ Cv, __half* __restrict__ mirror, int N, int K)
{
    extern __shared__ __half sm[];
    __half* As = sm;
    __half* Bs = sm + 3 * STGH;
    int tid = threadIdx.x, lane = tid & 31, warp = tid >> 5;
    int warpM = warp >> 2, warpN = warp & 3;
    size_t m0 = (size_t)blockIdx.x * 128;
    int n0 = blockIdx.y * 128;
    const __half* Ab = A + m0 * K;
    const __half* Bb = B + (size_t)n0 * K;
    float acc[4][4][4] = {};
    int r0w = tid >> 2, c8 = (tid & 3) * 8;
    int r1w = r0w + 64;
    int nch = K >> 5;

    #pragma unroll
    for (int p = 0; p < 2; p++) {
        int kk = p * 32;
        cp16(&As[p * STGH + r0w * 40 + c8], Ab + (size_t)r0w * K + kk + c8);
        cp16(&As[p * STGH + r1w * 40 + c8], Ab + (size_t)r1w * K + kk + c8);
        cp16(&Bs[p * STGH + r0w * 40 + c8], Bb + (size_t)r0w * K + kk + c8);
        cp16(&Bs[p * STGH + r1w * 40 + c8], Bb + (size_t)r1w * K + kk + c8);
        CP_COMMIT();
    }

    int s = 0, sl = 2;
    for (int c = 0; c < nch; c++) {
        CP_WAIT1();
        __syncthreads();
        if (c + 2 < nch) {
            int kk = (c + 2) * 32;
            cp16(&As[sl * STGH + r0w * 40 + c8], Ab + (size_t)r0w * K + kk + c8);
            cp16(&As[sl * STGH + r1w * 40 + c8], Ab + (size_t)r1w * K + kk + c8);
            cp16(&Bs[sl * STGH + r0w * 40 + c8], Bb + (size_t)r0w * K + kk + c8);
            cp16(&Bs[sl * STGH + r1w * 40 + c8], Bb + (size_t)r1w * K + kk + c8);
        }
        CP_COMMIT();
        mma_tile_h(As + s * STGH, Bs + s * STGH, acc, lane, warpM, warpN);
        if (++s == 3) s = 0;
        if (++sl == 3) sl = 0;
    }

    int lr = lane >> 2, lc = (lane & 3) * 2;
    #pragma unroll
    for (int mf = 0; mf < 4; mf++)
        #pragma unroll
        for (int h = 0; h < 2; h++) {
            size_t m = m0 + warpM * 64 + mf * 16 + lr + h * 8;
            #pragma unroll
            for (int nf = 0; nf < 4; nf++) {
                int col = n0 + warpN * 32 + nf * 8 + lc;
                float v0 = acc[mf][nf][h * 2], v1 = acc[mf][nf][h * 2 + 1];
                if (BIAS) { v0 += bias[col]; v1 += bias[col + 1]; }
                if (RES)  { v0 += res[m * N + col]; v1 += res[m * N + col + 1]; }
                if (GELU) {
                    v0 = 0.5f * v0 * (1.f + erff(v0 * 0.70710678118654752f));
                    v1 = 0.5f * v1 * (1.f + erff(v1 * 0.70710678118654752f));
                }
                if (HOUT) {
                    *(__half2*)((__half*)Cv + m * N + col) = __floats2half2_rn(v0, v1);
                } else {
                    *(float2*)((float*)Cv + m * N + col) = make_float2(v0, v1);
                    if (MIRROR)
                        *(__half2*)(mirror + m * N + col) = __floats2half2_rn(v0, v1);
                }
            }
        }
}

// ---------------- step-0 QKV GEMM over expert rows only (row map r -> (r>>1)*3 + (r&1)) ----------------
__global__ void __launch_bounds__(256) gemm_qkv0(const float* __restrict__ bias)
{
    extern __shared__ __half sm[];
    __half* As = sm;
    __half* Bs = sm + 3 * STGH;
    int tid = threadIdx.x, lane = tid & 31, warp = tid >> 5;
    int warpM = warp >> 2, warpN = warp & 3;
    size_t m0 = (size_t)blockIdx.x * 128;
    int n0 = blockIdx.y * 128;
    const int K = DM;
    const __half* Bb = g_ipwh + (size_t)n0 * K;
    float acc[4][4][4] = {};
    int r0w = tid >> 2, c8 = (tid & 3) * 8;
    int r1w = r0w + 64;
    // gathered A row pointers
    size_t gr0 = ((m0 + r0w) >> 1) * 3 + ((m0 + r0w) & 1);
    size_t gr1 = ((m0 + r1w) >> 1) * 3 + ((m0 + r1w) & 1);
    const __half* a0p = g_tokh + gr0 * K;
    const __half* a1p = g_tokh + gr1 * K;
    int nch = K >> 5;

    #pragma unroll
    for (int p = 0; p < 2; p++) {
        int kk = p * 32;
        cp16(&As[p * STGH + r0w * 40 + c8], a0p + kk + c8);
        cp16(&As[p * STGH + r1w * 40 + c8], a1p + kk + c8);
        cp16(&Bs[p * STGH + r0w * 40 + c8], Bb + (size_t)r0w * K + kk + c8);
        cp16(&Bs[p * STGH + r1w * 40 + c8], Bb + (size_t)r1w * K + kk + c8);
        CP_COMMIT();
    }

    int s = 0, sl = 2;
    for (int c = 0; c < nch; c++) {
        CP_WAIT1();
        __syncthreads();
        if (c + 2 < nch) {
            int kk = (c + 2) * 32;
            cp16(&As[sl * STGH + r0w * 40 + c8], a0p + kk + c8);
            cp16(&As[sl * STGH + r1w * 40 + c8], a1p + kk + c8);
            cp16(&Bs[sl * STGH + r0w * 40 + c8], Bb + (size_t)r0w * K + kk + c8);
            cp16(&Bs[sl * STGH + r1w * 40 + c8], Bb + (size_t)r1w * K + kk + c8);
        }
        CP_COMMIT();
        mma_tile_h(As + s * STGH, Bs + s * STGH, acc, lane, warpM, warpN);
        if (++s == 3) s = 0;
        if (++sl == 3) sl = 0;
    }

    int lr = lane >> 2, lc = (lane & 3) * 2;
    #pragma unroll
    for (int mf = 0; mf < 4; mf++)
        #pragma unroll
        for (int h = 0; h < 2; h++) {
            size_t m = m0 + warpM * 64 + mf * 16 + lr + h * 8;
            size_t gm = (m >> 1) * 3 + (m & 1);
            #pragma unroll
            for (int nf = 0; nf < 4; nf++) {
                int col = n0 + warpN * 32 + nf * 8 + lc;
                float v0 = acc[mf][nf][h * 2] + bias[col];
                float v1 = acc[mf][nf][h * 2 + 1] + bias[col + 1];
                *(__half2*)(g_qkvh + gm * QKVW + col) = __floats2half2_rn(v0, v1);
            }
        }
}

// mediator QKV (one row), warp-per-column
__global__ void __launch_bounds__(256) med_qkv_kernel(const float* __restrict__ bias) {
    int warp = threadIdx.x >> 5, lane = threadIdx.x & 31;
    int col = blockIdx.x * 8 + warp;       // 2304 cols -> 288 blocks
    const __half* med = g_tokh + 2 * DM;   // token 0, slot 2
    const __half* w = g_ipwh + (size_t)col * DM;
    float sv = 0.f;
    #pragma unroll
    for (int i = 0; i < 24; i++) {
        int d = lane + i * 32;
        sv += __half2float(med[d]) * __half2float(w[d]);
    }
    #pragma unroll
    for (int o = 16; o; o >>= 1) sv += __shfl_xor_sync(0xffffffffu, sv, o);
    if (lane == 0) g_qkvmed[col] = __float2half_rn(sv + bias[col]);
}

// ---------------- expert pass A: fused gu GEMM + SiLU ----------------
__global__ void __launch_bounds__(256) expA_h()
{
    int t = blockIdx.x;
    if (t >= g_ntiles) return;
    extern __shared__ __half sm[];
    __half* As = sm;
    __half* Bs = sm + 3 * STGH;
    __shared__ int tok[128];
    int tid = threadIdx.x, lane = tid & 31, warp = tid >> 5;
    int warpM = warp >> 2, warpN = warp & 3;
    int e = g_tile_e[t], r0 = g_tile_r0[t], rows = g_tile_rows[t];
    int n0 = blockIdx.y * 128;
    if (tid < 128) tok[tid] = (tid < rows) ? (g_idx_list[r0 + tid] >> 1) : 0;
    __syncthreads();
    const __half* Bb = g_w13h + (size_t)e * 2 * HF * DM + (size_t)n0 * DM;
    float acc[4][4][4] = {};
    int r0w = tid >> 2, c8 = (tid & 3) * 8;
    int r1w = r0w + 64;
    const __half* a0p = g_xh + (size_t)tok[r0w] * DM;
    const __half* a1p = g_xh + (size_t)tok[r1w] * DM;
    int nch = DM >> 5;

    #pragma unroll
    for (int p = 0; p < 2; p++) {
        int kk = p * 32;
        cp16(&As[p * STGH + r0w * 40 + c8], a0p + kk + c8);
        cp16(&As[p * STGH + r1w * 40 + c8], a1p + kk + c8);
        cp16(&Bs[p * STGH + r0w * 40 + c8], Bb + (size_t)r0w * DM + kk + c8);
        cp16(&Bs[p * STGH + r1w * 40 + c8], Bb + (size_t)r1w * DM + kk + c8);
        CP_COMMIT();
    }

    int s = 0, sl = 2;
    for (int c = 0; c < nch; c++) {
        CP_WAIT1();
        __syncthreads();
        if (c + 2 < nch) {
            int kk = (c + 2) * 32;
            cp16(&As[sl * STGH + r0w * 40 + c8], a0p + kk + c8);
            cp16(&As[sl * STGH + r1w * 40 + c8], a1p + kk + c8);
            cp16(&Bs[sl * STGH + r0w * 40 + c8], Bb + (size_t)r0w * DM + kk + c8);
            cp16(&Bs[sl * STGH + r1w * 40 + c8], Bb + (size_t)r1w * DM + kk + c8);
        }
        CP_COMMIT();
        mma_tile_h(As + s * STGH, Bs + s * STGH, acc, lane, warpM, warpN);
        if (++s == 3) s = 0;
        if (++sl == 3) sl = 0;
    }

    int lr = lane >> 2, lc = (lane & 3) * 2;
    int hbase = blockIdx.y * 64;
    #pragma unroll
    for (int mf = 0; mf < 4; mf++)
        #pragma unroll
        for (int h = 0; h < 2; h++) {
            int rl = warpM * 64 + mf * 16 + lr + h * 8;
            if (rl < rows) {
                __half* ap = g_acth + (size_t)(r0 + rl) * HF + hbase;
                #pragma unroll
                for (int nf = 0; nf < 4; nf++) {
                    int colt = warpN * 32 + nf * 8 + lc;
                    float g = acc[mf][nf][h * 2];
                    float u = acc[mf][nf][h * 2 + 1];
                    ap[colt >> 1] = __float2half_rn(g / (1.f + expf(-g)) * u);
                }
            }
        }
}

// ---------------- expert pass B ----------------
__global__ void __launch_bounds__(256) expB_h(const float* __restrict__ x)
{
    int t = blockIdx.x;
    if (t >= g_ntiles) return;
    extern __shared__ __half sm[];
    __half* As = sm;
    __half* Bs = sm + 3 * STGH;
    __shared__ int s_asn[128];
    int tid = threadIdx.x, lane = tid & 31, warp = tid >> 5;
    int warpM = warp >> 2, warpN = warp & 3;
    int e = g_tile_e[t], r0 = g_tile_r0[t], rows = g_tile_rows[t];
    int n0 = blockIdx.y * 128;
    if (tid < 128) s_asn[tid] = (tid < rows) ? g_idx_list[r0 + tid] : 0;
    const __half* Ab = g_acth + (size_t)r0 * HF;
    const __half* Bb = g_w2h + (size_t)e * DM * HF + (size_t)n0 * HF;
    float acc[4][4][4] = {};
    int r0w = tid >> 2, c8 = (tid & 3) * 8;
    int r1w = r0w + 64;
    int nch = HF >> 5;

    #pragma unroll
    for (int p = 0; p < 2; p++) {
        int kk = p * 32;
        cp16(&As[p * STGH + r0w * 40 + c8], Ab + (size_t)r0w * HF + kk + c8);
        cp16(&As[p * STGH + r1w * 40 + c8], Ab + (size_t)r1w * HF + kk + c8);
        cp16(&Bs[p * STGH + r0w * 40 + c8], Bb + (size_t)r0w * HF + kk + c8);
        cp16(&Bs[p * STGH + r1w * 40 + c8], Bb + (size_t)r1w * HF + kk + c8);
        CP_COMMIT();
    }

    int s = 0, sl = 2;
    for (int c = 0; c < nch; c++) {
        CP_WAIT1();
        __syncthreads();
        if (c + 2 < nch) {
            int kk = (c + 2) * 32;
            cp16(&As[sl * STGH + r0w * 40 + c8], Ab + (size_t)r0w * HF + kk + c8);
            cp16(&As[sl * STGH + r1w * 40 + c8], Ab + (size_t)r1w * HF + kk + c8);
            cp16(&Bs[sl * STGH + r0w * 40 + c8], Bb + (size_t)r0w * HF + kk + c8);
            cp16(&Bs[sl * STGH + r1w * 40 + c8], Bb + (size_t)r1w * HF + kk + c8);
        }
        CP_COMMIT();
        mma_tile_h(As + s * STGH, Bs + s * STGH, acc, lane, warpM, warpN);
        if (++s == 3) s = 0;
        if (++sl == 3) sl = 0;
    }

    int lr = lane >> 2, lc = (lane & 3) * 2;
    #pragma unroll
    for (int mf = 0; mf < 4; mf++)
        #pragma unroll
        for (int h = 0; h < 2; h++) {
            int rl = warpM * 64 + mf * 16 + lr + h * 8;
            if (rl < rows) {
                int a = s_asn[rl];
                int n = a >> 1, slot = a & 1;
                float kp = g_keep[a];
                const float* xr = x + (size_t)n * DM + n0;
                size_t base = ((size_t)n * 3 + slot) * DM + n0;
                #pragma unroll
                for (int nf = 0; nf < 4; nf++) {
                    int col = warpN * 32 + nf * 8 + lc;
                    float v0 = kp * (xr[col]     + acc[mf][nf][h * 2]);
                    float v1 = kp * (xr[col + 1] + acc[mf][nf][h * 2 + 1]);
                    *(float2*)(g_tokens + base + col) = make_float2(v0, v1);
                    *(__half2*)(g_tokh + base + col) = __floats2half2_rn(v0, v1);
                }
            }
        }
}

// ---------------- combined cvt: w13 (interleaved) + x (alpha=2) + mediator init ----------------
#define W13_U4 ((size_t)NE * 2 * HF * DM / 8)
#define X_U4   ((size_t)NTOK * DM / 8)
__global__ void cvt_combined_kernel(const float* __restrict__ w13,
                                    const float* __restrict__ x,
                                    const float* __restrict__ mediator) {
    size_t j = (size_t)blockIdx.x * 256 + threadIdx.x;
    if (j < W13_U4) {
        size_t per_e = (size_t)2 * HF * DM / 8;
        size_t e = j / per_e;
        size_t rem = j - e * per_e;
        int rp = (int)(rem / (DM / 8));
        int d8 = (int)(rem % (DM / 8));
        int h = rp >> 1;
        int src = (rp & 1) ? (HF + h) : h;
        const float* sp = w13 + (size_t)e * 2 * HF * DM + (size_t)src * DM + d8 * 8;
        float4 v0 = *(const float4*)sp;
        float4 v1 = *(const float4*)(sp + 4);
        uint4 o;
        o.x = h2u(v0.x, v0.y); o.y = h2u(v0.z, v0.w);
        o.z = h2u(v1.x, v1.y); o.w = h2u(v1.z, v1.w);
        ((uint4*)g_w13h)[j] = o;
    } else if (j < W13_U4 + X_U4) {
        size_t i = j - W13_U4;
        const float* sp = x + i * 8;
        float4 v0 = *(const float4*)sp;
        float4 v1 = *(const float4*)(sp + 4);
        uint4 o;
        o.x = h2u(2.f * v0.x, 2.f * v0.y); o.y = h2u(2.f * v0.z, 2.f * v0.w);
        o.z = h2u(2.f * v1.x, 2.f * v1.y); o.w = h2u(2.f * v1.z, 2.f * v1.w);
        ((uint4*)g_xh)[i] = o;
    } else if (j < W13_U4 + 2 * X_U4) {
        size_t i = j - W13_U4 - X_U4;
        size_t n = i / (DM / 8);
        int d8 = (int)(i % (DM / 8)) * 8;
        const float* sp = mediator + d8;
        float4 v0 = *(const float4*)sp;
        float4 v1 = *(const float4*)(sp + 4);
        size_t base = (n * 3 + 2) * DM + d8;
        *(float4*)(g_tokens + base) = v0;
        *(float4*)(g_tokens + base + 4) = v1;
        uint4 o;
        o.x = h2u(v0.x, v0.y); o.y = h2u(v0.z, v0.w);
        o.z = h2u(v1.x, v1.y); o.w = h2u(v1.z, v1.w);
        *(uint4*)(g_tokh + base) = o;
    }
}

// ---------------- all remaining weight cvts in ONE kernel ----------------
#define W2_U4  ((size_t)NE * DM * HF / 8)
#define IPW_U4 ((size_t)QKVW * DM / 8)
#define DD_U4  ((size_t)DM * DM / 8)
#define CVTW_TOTAL (W2_U4 + IPW_U4 + 4 * DD_U4)
__global__ void cvtw_all_kernel(const float* __restrict__ w2,
                                const float* __restrict__ ipw,
                                const float* __restrict__ ow,
                                const float* __restrict__ f1,
                                const float* __restrict__ f2,
                                const float* __restrict__ op) {
    size_t j = (size_t)blockIdx.x * 256 + threadIdx.x;
    if (j >= CVTW_TOTAL) return;
    const float* src;
    __half* dst;
    size_t i = j;
    if (i < W2_U4) { src = w2; dst = g_w2h; }
    else {
        i -= W2_U4;
        if (i < IPW_U4) { src = ipw; dst = g_ipwh; }
        else {
            i -= IPW_U4;
            if (i < DD_U4) { src = ow; dst = g_owh; }
            else {
                i -= DD_U4;
                if (i < DD_U4) { src = f1; dst = g_f1h; }
                else {
                    i -= DD_U4;
                    if (i < DD_U4) { src = f2; dst = g_f2h; }
                    else { i -= DD_U4; src = op; dst = g_oph; }
                }
            }
        }
    }
    const float* sp = src + i * 8;
    float4 v0 = *(const float4*)sp;
    float4 v1 = *(const float4*)(sp + 4);
    uint4 o;
    o.x = h2u(v0.x, v0.y); o.y = h2u(v0.z, v0.w);
    o.z = h2u(v1.x, v1.y); o.w = h2u(v1.z, v1.w);
    ((uint4*)dst)[i] = o;
}

// ---------------- small kernels ----------------
__global__ void zero_accum_kernel() {
    int t = threadIdx.x;
    if (t < NE) { g_router_sum[t] = 0.f; g_assign_sum[t] = 0.f; g_counts[t] = 0; g_fill[t] = 0; }
    if (t == 0) { g_z2 = 0.f; g_keepcnt = 0; }
}

__global__ void __launch_bounds__(256) gate_kernel(const float* __restrict__ x,
                                                   const float* __restrict__ gw,
                                                   float* __restrict__ out) {
    __shared__ float wsh[NE * DM];
    __shared__ float s_rs[NE], s_as[NE], s_z2s;
    __shared__ int   s_c[NE];
    int tid = threadIdx.x;
    for (int i = tid; i < NE * DM; i += 256) wsh[i] = gw[i];
    if (tid < NE) { s_rs[tid] = 0.f; s_as[tid] = 0.f; s_c[tid] = 0; }
    if (tid == 0) s_z2s = 0.f;
    __syncthreads();
    int warp = tid >> 5, lane = tid & 31;
    int n = blockIdx.x * 8 + warp;
    const float* xr = x + (size_t)n * DM;
    float xv[24];
    #pragma unroll
    for (int i = 0; i < 24; i++) xv[i] = xr[lane + i * 32];
    float l[NE];
    #pragma unroll
    for (int e = 0; e < NE; e++) {
        float sv = 0.f;
        const float* w = wsh + e * DM;
        #pragma unroll
        for (int i = 0; i < 24; i++) sv += xv[i] * w[lane + i * 32];
        #pragma unroll
        for (int o = 16; o; o >>= 1) sv += __shfl_xor_sync(0xffffffffu, sv, o);
        l[e] = sv;
    }
    if (lane == 0) {
        int i1 = 0; float v1 = l[0];
        #pragma unroll
        for (int e = 1; e < NE; e++) if (l[e] > v1) { v1 = l[e]; i1 = e; }
        int i2 = -1; float v2 = -3.4e38f;
        #pragma unroll
        for (int e = 0; e < NE; e++) if (e != i1 && l[e] > v2) { v2 = l[e]; i2 = e; }
        float e2 = expf(v2 - v1);
        float inv = 1.f / (1.f + e2);
        float p1 = inv, p2 = e2 * inv;
        float se = 0.f;
        #pragma unroll
        for (int e = 0; e < NE; e++) se += expf(l[e] - v1);
        float z = v1 + logf(se);
        #pragma unroll
        for (int e = 0; e < NE; e++) atomicAdd(&s_rs[e], expf(l[e] - v1) / se);
        atomicAdd(&s_as[i1], p1);
        atomicAdd(&s_as[i2], p2);
        atomicAdd(&s_z2s, z * z);
        atomicAdd(&s_c[i1], 1);
        atomicAdd(&s_c[i2], 1);
        g_te[2 * n] = i1; g_te[2 * n + 1] = i2;
        g_prio[2 * n] = v1; g_prio[2 * n + 1] = v2;
        g_tpk[2 * n] = p1; g_tpk[2 * n + 1] = p2;
        out[(size_t)NTOK * DM + 1 + 2 * n]     = (float)i1;
        out[(size_t)NTOK * DM + 1 + 2 * n + 1] = (float)i2;
    }
    __syncthreads();
    if (tid < NE) {
        atomicAdd(&g_router_sum[tid], s_rs[tid]);
        atomicAdd(&g_assign_sum[tid], s_as[tid]);
        atomicAdd(&g_counts[tid], s_c[tid]);
    }
    if (tid == 0) atomicAdd(&g_z2, s_z2s);
}

__global__ void build_tiles_kernel() {
    if (threadIdx.x != 0 || blockIdx.x != 0) return;
    int off = 0, nt = 0;
    for (int e = 0; e < NE; e++) {
        g_offsets[e] = off;
        int c = g_counts[e];
        int ntile = (c + 127) >> 7;
        for (int t = 0; t < ntile; t++) {
            g_tile_e[nt] = e;
            g_tile_r0[nt] = off + t * 128;
            int r = c - t * 128;
            g_tile_rows[nt] = r < 128 ? r : 128;
            nt++;
        }
        off += c;
    }
    g_ntiles = nt;
}

__global__ void scatter_kernel() {
    int i = blockIdx.x * 256 + threadIdx.x;
    if (i >= NKA) return;
    int e = g_te[i];
    int p = atomicAdd(&g_fill[e], 1);
    g_idx_list[g_offsets[e] + p] = i;
}

__global__ void keep_kernel() {
    int i = blockIdx.x * 256 + threadIdx.x;
    if (i >= NKA) return;
    int e = g_te[i];
    int kp;
    if (g_counts[e] <= CAPC) {
        kp = 1;
    } else {
        float pi = g_prio[i];
        int rank = 0;
        for (int j = 0; j < NKA; j++) {
            if (g_te[j] == e) {
                float pj = g_prio[j];
                if (pj > pi || (pj == pi && j < i)) rank++;
            }
        }
        kp = (rank < CAPC) ? 1 : 0;
    }
    g_keep[i] = (float)kp;
    atomicAdd(&g_keepcnt, kp);
}

// 2 tokens per block (8 warps), half2-vectorized; MED0: mediator qkv from g_qkvmed
template<bool MED0>
__global__ void __launch_bounds__(256) attn_kernel() {
    int warp = threadIdx.x >> 5, lane = threadIdx.x & 31;
    int n = blockIdx.x * 2 + (warp >> 2);
    int h = warp & 3;
    int hoff = h * 192 + lane * 6;
    float q[3][6], k[3][6], v[3][6];
    #pragma unroll
    for (int li = 0; li < 3; li++) {
        const __half* bp;
        if (MED0 && li == 2) bp = g_qkvmed + hoff;
        else bp = g_qkvh + (size_t)(n * 3 + li) * QKVW + hoff;
        #pragma unroll
        for (int seg = 0; seg < 3; seg++) {
            const __half* mp = bp + seg * DM;
            float2 p0 = __half22float2(*(const __half2*)(mp));
            float2 p1 = __half22float2(*(const __half2*)(mp + 2));
            float2 p2 = __half22float2(*(const __half2*)(mp + 4));
            float* d = (seg == 0) ? q[li] : (seg == 1) ? k[li] : v[li];
            d[0] = p0.x; d[1] = p0.y; d[2] = p1.x; d[3] = p1.y; d[4] = p2.x; d[5] = p2.y;
        }
    }
    const float scale = 0.07216878364870322f;
    float b0 = (g_keep[2 * n]     > 0.5f) ? 0.f : -1e9f;
    float b1 = (g_keep[2 * n + 1] > 0.5f) ? 0.f : -1e9f;
    float s[3][3];
    #pragma unroll
    for (int qi = 0; qi < 3; qi++) {
        #pragma unroll
        for (int kj = 0; kj < 3; kj++) {
            float t = 0.f;
            #pragma unroll
            for (int dd = 0; dd < 6; dd++) t += q[qi][dd] * k[kj][dd];
            #pragma unroll
            for (int o = 16; o; o >>= 1) t += __shfl_xor_sync(0xffffffffu, t, o);
            s[qi][kj] = t * scale;
        }
        s[qi][0] += b0;
        s[qi][1] += b1;
    }
    #pragma unroll
    for (int qi = 0; qi < 3; qi++) {
        float m = fmaxf(s[qi][0], fmaxf(s[qi][1], s[qi][2]));
        float e0 = expf(s[qi][0] - m), e1 = expf(s[qi][1] - m), e2 = expf(s[qi][2] - m);
        float inv = 1.f / (e0 + e1 + e2);
        float a0 = e0 * inv, a1 = e1 * inv, a2 = e2 * inv;
        __half* op = g_attnh + (size_t)(n * 3 + qi) * DM + hoff;
        #pragma unroll
        for (int p = 0; p < 3; p++) {
            float o0 = a0 * v[0][2 * p]     + a1 * v[1][2 * p]     + a2 * v[2][2 * p];
            float o1 = a0 * v[0][2 * p + 1] + a1 * v[1][2 * p + 1] + a2 * v[2][2 * p + 1];
            *(__half2*)(op + 2 * p) = __floats2half2_rn(o0, o1);
        }
    }
}

__global__ void rms_dual_kernel(const float* __restrict__ w1, const float* __restrict__ w2) {
    __shared__ float sh[8];
    __shared__ float sscale;
    int m = blockIdx.x, tid = threadIdx.x;
    float* row = g_tokens + (size_t)m * DM;
    float v0 = row[tid], v1 = row[tid + 256], v2 = row[tid + 512];
    float ss = v0 * v0 + v1 * v1 + v2 * v2;
    #pragma unroll
    for (int o = 16; o; o >>= 1) ss += __shfl_xor_sync(0xffffffffu, ss, o);
    if ((tid & 31) == 0) sh[tid >> 5] = ss;
    __syncthreads();
    if (tid == 0) {
        float t = 0.f;
        #pragma unroll
        for (int i = 0; i < 8; i++) t += sh[i];
        sscale = rsqrtf(t * (1.f / DM) + 1e-6f);
    }
    __syncthreads();
    float s1 = sscale;
    float t0 = v0 * s1 * w1[tid];
    float t1 = v1 * s1 * w1[tid + 256];
    float t2 = v2 * s1 * w1[tid + 512];
    row[tid] = t0; row[tid + 256] = t1; row[tid + 512] = t2;
    float ss2 = t0 * t0 + t1 * t1 + t2 * t2;
    #pragma unroll
    for (int o = 16; o; o >>= 1) ss2 += __shfl_xor_sync(0xffffffffu, ss2, o);
    __syncthreads();
    if ((tid & 31) == 0) sh[tid >> 5] = ss2;
    __syncthreads();
    if (tid == 0) {
        float t = 0.f;
        #pragma unroll
        for (int i = 0; i < 8; i++) t += sh[i];
        sscale = rsqrtf(t * (1.f / DM) + 1e-6f);
    }
    __syncthreads();
    float s2 = sscale;
    __half* ur = g_uh + (size_t)m * DM;
    ur[tid]       = __float2half_rn(t0 * s2 * w2[tid]);
    ur[tid + 256] = __float2half_rn(t1 * s2 * w2[tid + 256]);
    ur[tid + 512] = __float2half_rn(t2 * s2 * w2[tid + 512]);
}

// fuse_prep + aux (block 0 thread 0 writes aux scalar)
__global__ void fuse_prep_kernel(const float* __restrict__ fgw, const float* __restrict__ fgb,
                                 float* __restrict__ out) {
    __shared__ float sh[8];
    __shared__ float par[3];
    int n = blockIdx.x, tid = threadIdx.x;
    const float* med = g_tokens + ((size_t)n * 3 + 2) * DM;
    float s = med[tid] * fgw[tid] + med[tid + 256] * fgw[tid + 256] + med[tid + 512] * fgw[tid + 512];
    #pragma unroll
    for (int o = 16; o; o >>= 1) s += __shfl_xor_sync(0xffffffffu, s, o);
    if ((tid & 31) == 0) sh[tid >> 5] = s;
    __syncthreads();
    if (tid == 0) {
        float t = 0.f;
        #pragma unroll
        for (int i = 0; i < 8; i++) t += sh[i];
        float g = 1.f / (1.f + expf(-(t + fgb[0])));
        float tp0 = g_tpk[2 * n] * g_keep[2 * n];
        float tp1 = g_tpk[2 * n + 1] * g_keep[2 * n + 1];
        float den = tp0 + tp1;
        par[0] = g;
        par[1] = den > 0.f ? tp0 / den : 0.f;
        par[2] = den > 0.f ? tp1 / den : 0.f;
        if (n == 0) {
            float bal = 0.f;
            for (int e = 0; e < NE; e++)
                bal += (g_router_sum[e] / (float)NTOK) * (g_assign_sum[e] / (float)NTOK);
            bal *= (float)NE;
            out[(size_t)NTOK * DM] = 0.01f * bal + 0.001f * (g_z2 / (float)NTOK)
                + 0.001f * (1.f - (float)g_keepcnt / (float)NKA);
        }
    }
    __syncthreads();
    float g = par[0], w0 = par[1], w1 = par[2];
    const float* e0 = g_tokens + ((size_t)n * 3 + 0) * DM;
    const float* e1 = g_tokens + ((size_t)n * 3 + 1) * DM;
    __half* fm = g_fmh + (size_t)n * DM;
    #pragma unroll
    for (int c = 0; c < 3; c++) {
        int d = tid + c * 256;
        fm[d] = __float2half_rn(g * med[d] + (1.f - g) * (w0 * e0[d] + w1 * e1[d]));
    }
}

// ---------------- launch ----------------
extern "C" void kernel_launch(void* const* d_in, const int* in_sizes, int n_in,
                              void* d_out, int out_size) {
    const float* x          = (const float*)d_in[0];
    const float* gate_w     = (const float*)d_in[1];
    const float* w13        = (const float*)d_in[2];
    const float* w2         = (const float*)d_in[3];
    const float* in_proj_w  = (const float*)d_in[4];
    const float* in_proj_b  = (const float*)d_in[5];
    const float* out_w      = (const float*)d_in[6];
    const float* out_b      = (const float*)d_in[7];
    const float* norm1_w    = (const float*)d_in[8];
    const float* norm2_w    = (const float*)d_in[9];
    const float* ffn_w1     = (const float*)d_in[10];
    const float* ffn_w2     = (const float*)d_in[11];
    const float* mediator   = (const float*)d_in[12];
    const float* fuse_gate_w= (const float*)d_in[13];
    const float* fuse_gate_b= (const float*)d_in[14];
    const float* o_proj_w   = (const float*)d_in[15];
    float* out = (float*)d_out;

    float* p_tokens;
    __half *p_tokh, *p_ipwh, *p_owh, *p_f1h, *p_f2h, *p_oph;
    __half *p_qkvh, *p_attnh, *p_uh, *p_hh, *p_fmh;
    cudaGetSymbolAddress((void**)&p_tokens, g_tokens);
    cudaGetSymbolAddress((void**)&p_tokh, g_tokh);
    cudaGetSymbolAddress((void**)&p_ipwh, g_ipwh);
    cudaGetSymbolAddress((void**)&p_owh, g_owh);
    cudaGetSymbolAddress((void**)&p_f1h, g_f1h);
    cudaGetSymbolAddress((void**)&p_f2h, g_f2h);
    cudaGetSymbolAddress((void**)&p_oph, g_oph);
    cudaGetSymbolAddress((void**)&p_qkvh, g_qkvh);
    cudaGetSymbolAddress((void**)&p_attnh, g_attnh);
    cudaGetSymbolAddress((void**)&p_uh, g_uh);
    cudaGetSymbolAddress((void**)&p_hh, g_hh);
    cudaGetSymbolAddress((void**)&p_fmh, g_fmh);

    cudaFuncSetAttribute(gemm_h<true,  false, false, true,  false>, cudaFuncAttributeMaxDynamicSharedMemorySize, SMEMB);
    cudaFuncSetAttribute(gemm_h<true,  true,  false, false, false>, cudaFuncAttributeMaxDynamicSharedMemorySize, SMEMB);
    cudaFuncSetAttribute(gemm_h<false, false, true,  true,  false>, cudaFuncAttributeMaxDynamicSharedMemorySize, SMEMB);
    cudaFuncSetAttribute(gemm_h<false, true,  false, false, true >, cudaFuncAttributeMaxDynamicSharedMemorySize, SMEMB);
    cudaFuncSetAttribute(gemm_h<false, false, false, false, false>, cudaFuncAttributeMaxDynamicSharedMemorySize, SMEMB);
    cudaFuncSetAttribute(gemm_qkv0, cudaFuncAttributeMaxDynamicSharedMemorySize, SMEMB);
    cudaFuncSetAttribute(expA_h, cudaFuncAttributeMaxDynamicSharedMemorySize, SMEMB);
    cudaFuncSetAttribute(expB_h, cudaFuncAttributeMaxDynamicSharedMemorySize, SMEMB);

    // fork a side stream inside the capture for the independent cvt work
    cudaStream_t s2;
    cudaStreamCreateWithFlags(&s2, cudaStreamNonBlocking);
    cudaEvent_t evF, evJ;
    cudaEventCreateWithFlags(&evF, cudaEventDisableTiming);
    cudaEventCreateWithFlags(&evJ, cudaEventDisableTiming);

    cudaEventRecord(evF, 0);
    cudaStreamWaitEvent(s2, evF, 0);
    cvt_combined_kernel<<<(int)((W13_U4 + 2 * X_U4 + 255) / 256), 256, 0, s2>>>(w13, x, mediator);
    cvtw_all_kernel<<<(int)((CVTW_TOTAL + 255) / 256), 256, 0, s2>>>(
        w2, in_proj_w, out_w, ffn_w1, ffn_w2, o_proj_w);
    cudaEventRecord(evJ, s2);

    zero_accum_kernel<<<1, 32>>>();
    gate_kernel<<<NTOK / 8, 256>>>(x, gate_w, out);
    build_tiles_kernel<<<1, 1>>>();
    scatter_kernel<<<NKA / 256, 256>>>();
    keep_kernel<<<NKA / 256, 256>>>();

    cudaStreamWaitEvent(0, evJ, 0);

    expA_h<<<dim3(MAXT, 2 * HF / 128), 256, SMEMB>>>();
    expB_h<<<dim3(MAXT, DM / 128), 256, SMEMB>>>(x);

    // ---- step 0: mediator QKV computed once ----
    med_qkv_kernel<<<QKVW / 8, 256>>>(in_proj_b);
    gemm_qkv0<<<dim3(NKA / 128, QKVW / 128), 256, SMEMB>>>(in_proj_b);
    attn_kernel<true><<<NTOK / 2, 256>>>();
    gemm_h<true, true, false, false, false><<<dim3(MROW / 128, DM / 128), 256, SMEMB>>>(
        p_attnh, p_owh, out_b, p_tokens, p_tokens, nullptr, DM, DM);
    rms_dual_kernel<<<MROW, 256>>>(norm1_w, norm2_w);
    gemm_h<false, false, true, true, false><<<dim3(MROW / 128, DM / 128), 256, SMEMB>>>(
        p_uh, p_f1h, nullptr, nullptr, p_hh, nullptr, DM, DM);
    gemm_h<false, true, false, false, true><<<dim3(MROW / 128, DM / 128), 256, SMEMB>>>(
        p_hh, p_f2h, nullptr, p_tokens, p_tokens, p_tokh, DM, DM);

    // ---- step 1: full path ----
    gemm_h<true, false, false, true, false><<<dim3(MROW / 128, QKVW / 128), 256, SMEMB>>>(
        p_tokh, p_ipwh, in_proj_b, nullptr, p_qkvh, nullptr, QKVW, DM);
    attn_kernel<false><<<NTOK / 2, 256>>>();
    gemm_h<true, true, false, false, false><<<dim3(MROW / 128, DM / 128), 256, SMEMB>>>(
        p_attnh, p_owh, out_b, p_tokens, p_tokens, nullptr, DM, DM);
    rms_dual_kernel<<<MROW, 256>>>(norm1_w, norm2_w);
    gemm_h<false, false, true, true, false><<<dim3(MROW / 128, DM / 128), 256, SMEMB>>>(
        p_uh, p_f1h, nullptr, nullptr, p_hh, nullptr, DM, DM);
    gemm_h<false, true, false, false, true><<<dim3(MROW / 128, DM / 128), 256, SMEMB>>>(
        p_hh, p_f2h, nullptr, p_tokens, p_tokens, p_tokh, DM, DM);

    fuse_prep_kernel<<<NTOK, 256>>>(fuse_gate_w, fuse_gate_b, out);
    gemm_h<false, false, false, false, false><<<dim3(NTOK / 128, DM / 128), 256, SMEMB>>>(
        p_fmh, p_oph, nullptr, nullptr, out, nullptr, DM, DM);
}

// round 17
// speedup vs baseline: 1.0956x; 1.0318x over previous
#include <cuda_runtime.h>
#include <cuda_fp16.h>
#include <math.h>
#include <stdint.h>

#define NTOK 8192
#define DM   768
#define NE   8
#define NKA  16384
#define HF   2048
#define CAPC 4096
#define MROW 24576
#define QKVW 2304
#define MAXT 136

#define STGH  5120                 // 128*40 halves per matrix per stage
#define SMEMB (6 * STGH * 2)       // 3 stages x (A+B) = 61440 bytes

// ---------------- scratch ----------------
__device__ float g_router_sum[NE];
__device__ float g_assign_sum[NE];
__device__ float g_z2;
__device__ int   g_counts[NE];
__device__ int   g_fill[NE];
__device__ int   g_offsets[NE];
__device__ int   g_keepcnt;
__device__ int   g_te[NKA];
__device__ float g_prio[NKA];
__device__ float g_tpk[NKA];
__device__ float g_keep[NKA];
__device__ int   g_idx_list[NKA];
__device__ int   g_tile_e[MAXT];
__device__ int   g_tile_r0[MAXT];
__device__ int   g_tile_rows[MAXT];
__device__ int   g_ntiles;

__device__ __half g_tokh[(size_t)MROW * DM];            // fp16 residual stream (sole copy)
__device__ __half g_acth[(size_t)(NKA + 128) * HF];
__device__ __half g_qkvh[(size_t)MROW * QKVW];
__device__ __half g_qkvmed[QKVW];
__device__ __half g_attnh[(size_t)MROW * DM];
__device__ __half g_uh[(size_t)MROW * DM];
__device__ __half g_hh[(size_t)MROW * DM];
__device__ __half g_fmh[(size_t)NTOK * DM];

__device__ __half g_xh[(size_t)NTOK * DM];              // 2*x
__device__ __half g_w13h[(size_t)NE * 2 * HF * DM];     // rows interleaved g/u
__device__ __half g_w2h[(size_t)NE * DM * HF];
__device__ __half g_ipwh[(size_t)QKVW * DM];
__device__ __half g_owh[(size_t)DM * DM];
__device__ __half g_f1h[(size_t)DM * DM];
__device__ __half g_f2h[(size_t)DM * DM];
__device__ __half g_oph[(size_t)DM * DM];

// ---------------- helpers ----------------
__device__ __forceinline__ uint32_t h2u(float a, float b) {
    __half2 h = __floats2half2_rn(a, b);
    return *(uint32_t*)&h;
}

__device__ __forceinline__ void cp16(void* smem, const void* gmem) {
    uint32_t s = (uint32_t)__cvta_generic_to_shared(smem);
    asm volatile("cp.async.cg.shared.global [%0], [%1], 16;" :: "r"(s), "l"(gmem));
}
#define CP_COMMIT() asm volatile("cp.async.commit_group;" ::: "memory")
#define CP_WAIT1()  asm volatile("cp.async.wait_group 1;" ::: "memory")

__device__ __forceinline__ void mma16(float* c, const uint32_t* a, const uint32_t* b) {
    asm volatile(
        "mma.sync.aligned.m16n8k16.row.col.f32.f16.f16.f32 "
        "{%0,%1,%2,%3},{%4,%5,%6,%7},{%8,%9},{%0,%1,%2,%3};"
        : "+f"(c[0]), "+f"(c[1]), "+f"(c[2]), "+f"(c[3])
        : "r"(a[0]), "r"(a[1]), "r"(a[2]), "r"(a[3]), "r"(b[0]), "r"(b[1]));
}

// one 128x128x32 tile: 8 warps, warp tile 64x32, 2 k-steps of 16
__device__ __forceinline__ void mma_tile_h(const __half* As, const __half* Bs,
                                           float acc[4][4][4], int lane, int warpM, int warpN) {
    int lr = lane >> 2, lq = (lane & 3) * 2;
    #pragma unroll
    for (int ks = 0; ks < 2; ks++) {
        int kb = ks * 16 + lq;
        uint32_t a[4][4], b[4][2];
        #pragma unroll
        for (int mf = 0; mf < 4; mf++) {
            int rb = warpM * 64 + mf * 16 + lr;
            a[mf][0] = *(const uint32_t*)(As + rb * 40 + kb);
            a[mf][1] = *(const uint32_t*)(As + (rb + 8) * 40 + kb);
            a[mf][2] = *(const uint32_t*)(As + rb * 40 + kb + 8);
            a[mf][3] = *(const uint32_t*)(As + (rb + 8) * 40 + kb + 8);
        }
        #pragma unroll
        for (int nf = 0; nf < 4; nf++) {
            int cb = warpN * 32 + nf * 8 + lr;
            b[nf][0] = *(const uint32_t*)(Bs + cb * 40 + kb);
            b[nf][1] = *(const uint32_t*)(Bs + cb * 40 + kb + 8);
        }
        #pragma unroll
        for (int mf = 0; mf < 4; mf++)
            #pragma unroll
            for (int nf = 0; nf < 4; nf++)
                mma16(acc[mf][nf], a[mf], b[nf]);
    }
}

// ---------------- generic NT GEMM (fp16, 3-stage cp.async pipeline) ----------------
// RES reads fp16 residual; HOUT: fp16 out, else fp32 out
template<bool BIAS, bool RES, bool GELU, bool HOUT>
__global__ void __launch_bounds__(256) gemm_h(
    const __half* __restrict__ A, const __half* __restrict__ B,
    const float* __restrict__ bias, const __half* __restrict__ res,
    void* __restrict__ Cv, int N, int K)
{
    extern __shared__ __half sm[];
    __half* As = sm;
    __half* Bs = sm + 3 * STGH;
    int tid = threadIdx.x, lane = tid & 31, warp = tid >> 5;
    int warpM = warp >> 2, warpN = warp & 3;
    size_t m0 = (size_t)blockIdx.x * 128;
    int n0 = blockIdx.y * 128;
    const __half* Ab = A + m0 * K;
    const __half* Bb = B + (size_t)n0 * K;
    float acc[4][4][4] = {};
    int r0w = tid >> 2, c8 = (tid & 3) * 8;
    int r1w = r0w + 64;
    int nch = K >> 5;

    #pragma unroll
    for (int p = 0; p < 2; p++) {
        int kk = p * 32;
        cp16(&As[p * STGH + r0w * 40 + c8], Ab + (size_t)r0w * K + kk + c8);
        cp16(&As[p * STGH + r1w * 40 + c8], Ab + (size_t)r1w * K + kk + c8);
        cp16(&Bs[p * STGH + r0w * 40 + c8], Bb + (size_t)r0w * K + kk + c8);
        cp16(&Bs[p * STGH + r1w * 40 + c8], Bb + (size_t)r1w * K + kk + c8);
        CP_COMMIT();
    }

    int s = 0, sl = 2;
    for (int c = 0; c < nch; c++) {
        CP_WAIT1();
        __syncthreads();
        if (c + 2 < nch) {
            int kk = (c + 2) * 32;
            cp16(&As[sl * STGH + r0w * 40 + c8], Ab + (size_t)r0w * K + kk + c8);
            cp16(&As[sl * STGH + r1w * 40 + c8], Ab + (size_t)r1w * K + kk + c8);
            cp16(&Bs[sl * STGH + r0w * 40 + c8], Bb + (size_t)r0w * K + kk + c8);
            cp16(&Bs[sl * STGH + r1w * 40 + c8], Bb + (size_t)r1w * K + kk + c8);
        }
        CP_COMMIT();
        mma_tile_h(As + s * STGH, Bs + s * STGH, acc, lane, warpM, warpN);
        if (++s == 3) s = 0;
        if (++sl == 3) sl = 0;
    }

    int lr = lane >> 2, lc = (lane & 3) * 2;
    #pragma unroll
    for (int mf = 0; mf < 4; mf++)
        #pragma unroll
        for (int h = 0; h < 2; h++) {
            size_t m = m0 + warpM * 64 + mf * 16 + lr + h * 8;
            #pragma unroll
            for (int nf = 0; nf < 4; nf++) {
                int col = n0 + warpN * 32 + nf * 8 + lc;
                float v0 = acc[mf][nf][h * 2], v1 = acc[mf][nf][h * 2 + 1];
                if (BIAS) { v0 += bias[col]; v1 += bias[col + 1]; }
                if (RES) {
                    float2 r2 = __half22float2(*(const __half2*)(res + m * N + col));
                    v0 += r2.x; v1 += r2.y;
                }
                if (GELU) {
                    v0 = 0.5f * v0 * (1.f + erff(v0 * 0.70710678118654752f));
                    v1 = 0.5f * v1 * (1.f + erff(v1 * 0.70710678118654752f));
                }
                if (HOUT) {
                    *(__half2*)((__half*)Cv + m * N + col) = __floats2half2_rn(v0, v1);
                } else {
                    *(float2*)((float*)Cv + m * N + col) = make_float2(v0, v1);
                }
            }
        }
}

// ---------------- step-0 QKV GEMM over expert rows only (row map r -> (r>>1)*3 + (r&1)) ----------------
__global__ void __launch_bounds__(256) gemm_qkv0(const float* __restrict__ bias)
{
    extern __shared__ __half sm[];
    __half* As = sm;
    __half* Bs = sm + 3 * STGH;
    int tid = threadIdx.x, lane = tid & 31, warp = tid >> 5;
    int warpM = warp >> 2, warpN = warp & 3;
    size_t m0 = (size_t)blockIdx.x * 128;
    int n0 = blockIdx.y * 128;
    const int K = DM;
    const __half* Bb = g_ipwh + (size_t)n0 * K;
    float acc[4][4][4] = {};
    int r0w = tid >> 2, c8 = (tid & 3) * 8;
    int r1w = r0w + 64;
    size_t gr0 = ((m0 + r0w) >> 1) * 3 + ((m0 + r0w) & 1);
    size_t gr1 = ((m0 + r1w) >> 1) * 3 + ((m0 + r1w) & 1);
    const __half* a0p = g_tokh + gr0 * K;
    const __half* a1p = g_tokh + gr1 * K;
    int nch = K >> 5;

    #pragma unroll
    for (int p = 0; p < 2; p++) {
        int kk = p * 32;
        cp16(&As[p * STGH + r0w * 40 + c8], a0p + kk + c8);
        cp16(&As[p * STGH + r1w * 40 + c8], a1p + kk + c8);
        cp16(&Bs[p * STGH + r0w * 40 + c8], Bb + (size_t)r0w * K + kk + c8);
        cp16(&Bs[p * STGH + r1w * 40 + c8], Bb + (size_t)r1w * K + kk + c8);
        CP_COMMIT();
    }

    int s = 0, sl = 2;
    for (int c = 0; c < nch; c++) {
        CP_WAIT1();
        __syncthreads();
        if (c + 2 < nch) {
            int kk = (c + 2) * 32;
            cp16(&As[sl * STGH + r0w * 40 + c8], a0p + kk + c8);
            cp16(&As[sl * STGH + r1w * 40 + c8], a1p + kk + c8);
            cp16(&Bs[sl * STGH + r0w * 40 + c8], Bb + (size_t)r0w * K + kk + c8);
            cp16(&Bs[sl * STGH + r1w * 40 + c8], Bb + (size_t)r1w * K + kk + c8);
        }
        CP_COMMIT();
        mma_tile_h(As + s * STGH, Bs + s * STGH, acc, lane, warpM, warpN);
        if (++s == 3) s = 0;
        if (++sl == 3) sl = 0;
    }

    int lr = lane >> 2, lc = (lane & 3) * 2;
    #pragma unroll
    for (int mf = 0; mf < 4; mf++)
        #pragma unroll
        for (int h = 0; h < 2; h++) {
            size_t m = m0 + warpM * 64 + mf * 16 + lr + h * 8;
            size_t gm = (m >> 1) * 3 + (m & 1);
            #pragma unroll
            for (int nf = 0; nf < 4; nf++) {
                int col = n0 + warpN * 32 + nf * 8 + lc;
                float v0 = acc[mf][nf][h * 2] + bias[col];
                float v1 = acc[mf][nf][h * 2 + 1] + bias[col + 1];
                *(__half2*)(g_qkvh + gm * QKVW + col) = __floats2half2_rn(v0, v1);
            }
        }
}

// mediator QKV (one row), warp-per-column
__global__ void __launch_bounds__(256) med_qkv_kernel(const float* __restrict__ bias) {
    int warp = threadIdx.x >> 5, lane = threadIdx.x & 31;
    int col = blockIdx.x * 8 + warp;
    const __half* med = g_tokh + 2 * DM;
    const __half* w = g_ipwh + (size_t)col * DM;
    float sv = 0.f;
    #pragma unroll
    for (int i = 0; i < 24; i++) {
        int d = lane + i * 32;
        sv += __half2float(med[d]) * __half2float(w[d]);
    }
    #pragma unroll
    for (int o = 16; o; o >>= 1) sv += __shfl_xor_sync(0xffffffffu, sv, o);
    if (lane == 0) g_qkvmed[col] = __float2half_rn(sv + bias[col]);
}

// ---------------- expert pass A: fused gu GEMM + SiLU ----------------
__global__ void __launch_bounds__(256) expA_h()
{
    int t = blockIdx.x;
    if (t >= g_ntiles) return;
    extern __shared__ __half sm[];
    __half* As = sm;
    __half* Bs = sm + 3 * STGH;
    __shared__ int tok[128];
    int tid = threadIdx.x, lane = tid & 31, warp = tid >> 5;
    int warpM = warp >> 2, warpN = warp & 3;
    int e = g_tile_e[t], r0 = g_tile_r0[t], rows = g_tile_rows[t];
    int n0 = blockIdx.y * 128;
    if (tid < 128) tok[tid] = (tid < rows) ? (g_idx_list[r0 + tid] >> 1) : 0;
    __syncthreads();
    const __half* Bb = g_w13h + (size_t)e * 2 * HF * DM + (size_t)n0 * DM;
    float acc[4][4][4] = {};
    int r0w = tid >> 2, c8 = (tid & 3) * 8;
    int r1w = r0w + 64;
    const __half* a0p = g_xh + (size_t)tok[r0w] * DM;
    const __half* a1p = g_xh + (size_t)tok[r1w] * DM;
    int nch = DM >> 5;

    #pragma unroll
    for (int p = 0; p < 2; p++) {
        int kk = p * 32;
        cp16(&As[p * STGH + r0w * 40 + c8], a0p + kk + c8);
        cp16(&As[p * STGH + r1w * 40 + c8], a1p + kk + c8);
        cp16(&Bs[p * STGH + r0w * 40 + c8], Bb + (size_t)r0w * DM + kk + c8);
        cp16(&Bs[p * STGH + r1w * 40 + c8], Bb + (size_t)r1w * DM + kk + c8);
        CP_COMMIT();
    }

    int s = 0, sl = 2;
    for (int c = 0; c < nch; c++) {
        CP_WAIT1();
        __syncthreads();
        if (c + 2 < nch) {
            int kk = (c + 2) * 32;
            cp16(&As[sl * STGH + r0w * 40 + c8], a0p + kk + c8);
            cp16(&As[sl * STGH + r1w * 40 + c8], a1p + kk + c8);
            cp16(&Bs[sl * STGH + r0w * 40 + c8], Bb + (size_t)r0w * DM + kk + c8);
            cp16(&Bs[sl * STGH + r1w * 40 + c8], Bb + (size_t)r1w * DM + kk + c8);
        }
        CP_COMMIT();
        mma_tile_h(As + s * STGH, Bs + s * STGH, acc, lane, warpM, warpN);
        if (++s == 3) s = 0;
        if (++sl == 3) sl = 0;
    }

    int lr = lane >> 2, lc = (lane & 3) * 2;
    int hbase = blockIdx.y * 64;
    #pragma unroll
    for (int mf = 0; mf < 4; mf++)
        #pragma unroll
        for (int h = 0; h < 2; h++) {
            int rl = warpM * 64 + mf * 16 + lr + h * 8;
            if (rl < rows) {
                __half* ap = g_acth + (size_t)(r0 + rl) * HF + hbase;
                #pragma unroll
                for (int nf = 0; nf < 4; nf++) {
                    int colt = warpN * 32 + nf * 8 + lc;
                    float g = acc[mf][nf][h * 2];
                    float u = acc[mf][nf][h * 2 + 1];
                    ap[colt >> 1] = __float2half_rn(g / (1.f + expf(-g)) * u);
                }
            }
        }
}

// ---------------- expert pass B ----------------
__global__ void __launch_bounds__(256) expB_h(const float* __restrict__ x)
{
    int t = blockIdx.x;
    if (t >= g_ntiles) return;
    extern __shared__ __half sm[];
    __half* As = sm;
    __half* Bs = sm + 3 * STGH;
    __shared__ int s_asn[128];
    int tid = threadIdx.x, lane = tid & 31, warp = tid >> 5;
    int warpM = warp >> 2, warpN = warp & 3;
    int e = g_tile_e[t], r0 = g_tile_r0[t], rows = g_tile_rows[t];
    int n0 = blockIdx.y * 128;
    if (tid < 128) s_asn[tid] = (tid < rows) ? g_idx_list[r0 + tid] : 0;
    const __half* Ab = g_acth + (size_t)r0 * HF;
    const __half* Bb = g_w2h + (size_t)e * DM * HF + (size_t)n0 * HF;
    float acc[4][4][4] = {};
    int r0w = tid >> 2, c8 = (tid & 3) * 8;
    int r1w = r0w + 64;
    int nch = HF >> 5;

    #pragma unroll
    for (int p = 0; p < 2; p++) {
        int kk = p * 32;
        cp16(&As[p * STGH + r0w * 40 + c8], Ab + (size_t)r0w * HF + kk + c8);
        cp16(&As[p * STGH + r1w * 40 + c8], Ab + (size_t)r1w * HF + kk + c8);
        cp16(&Bs[p * STGH + r0w * 40 + c8], Bb + (size_t)r0w * HF + kk + c8);
        cp16(&Bs[p * STGH + r1w * 40 + c8], Bb + (size_t)r1w * HF + kk + c8);
        CP_COMMIT();
    }

    int s = 0, sl = 2;
    for (int c = 0; c < nch; c++) {
        CP_WAIT1();
        __syncthreads();
        if (c + 2 < nch) {
            int kk = (c + 2) * 32;
            cp16(&As[sl * STGH + r0w * 40 + c8], Ab + (size_t)r0w * HF + kk + c8);
            cp16(&As[sl * STGH + r1w * 40 + c8], Ab + (size_t)r1w * HF + kk + c8);
            cp16(&Bs[sl * STGH + r0w * 40 + c8], Bb + (size_t)r0w * HF + kk + c8);
            cp16(&Bs[sl * STGH + r1w * 40 + c8], Bb + (size_t)r1w * HF + kk + c8);
        }
        CP_COMMIT();
        mma_tile_h(As + s * STGH, Bs + s * STGH, acc, lane, warpM, warpN);
        if (++s == 3) s = 0;
        if (++sl == 3) sl = 0;
    }

    int lr = lane >> 2, lc = (lane & 3) * 2;
    #pragma unroll
    for (int mf = 0; mf < 4; mf++)
        #pragma unroll
        for (int h = 0; h < 2; h++) {
            int rl = warpM * 64 + mf * 16 + lr + h * 8;
            if (rl < rows) {
                int a = s_asn[rl];
                int n = a >> 1, slot = a & 1;
                float kp = g_keep[a];
                const float* xr = x + (size_t)n * DM + n0;
                size_t base = ((size_t)n * 3 + slot) * DM + n0;
                #pragma unroll
                for (int nf = 0; nf < 4; nf++) {
                    int col = warpN * 32 + nf * 8 + lc;
                    float v0 = kp * (xr[col]     + acc[mf][nf][h * 2]);
                    float v1 = kp * (xr[col + 1] + acc[mf][nf][h * 2 + 1]);
                    *(__half2*)(g_tokh + base + col) = __floats2half2_rn(v0, v1);
                }
            }
        }
}

// ---------------- combined cvt: w13 (interleaved) + x (alpha=2) + mediator init ----------------
#define W13_U4 ((size_t)NE * 2 * HF * DM / 8)
#define X_U4   ((size_t)NTOK * DM / 8)
__global__ void cvt_combined_kernel(const float* __restrict__ w13,
                                    const float* __restrict__ x,
                                    const float* __restrict__ mediator) {
    size_t j = (size_t)blockIdx.x * 256 + threadIdx.x;
    if (j < W13_U4) {
        size_t per_e = (size_t)2 * HF * DM / 8;
        size_t e = j / per_e;
        size_t rem = j - e * per_e;
        int rp = (int)(rem / (DM / 8));
        int d8 = (int)(rem % (DM / 8));
        int h = rp >> 1;
        int src = (rp & 1) ? (HF + h) : h;
        const float* sp = w13 + (size_t)e * 2 * HF * DM + (size_t)src * DM + d8 * 8;
        float4 v0 = *(const float4*)sp;
        float4 v1 = *(const float4*)(sp + 4);
        uint4 o;
        o.x = h2u(v0.x, v0.y); o.y = h2u(v0.z, v0.w);
        o.z = h2u(v1.x, v1.y); o.w = h2u(v1.z, v1.w);
        ((uint4*)g_w13h)[j] = o;
    } else if (j < W13_U4 + X_U4) {
        size_t i = j - W13_U4;
        const float* sp = x + i * 8;
        float4 v0 = *(const float4*)sp;
        float4 v1 = *(const float4*)(sp + 4);
        uint4 o;
        o.x = h2u(2.f * v0.x, 2.f * v0.y); o.y = h2u(2.f * v0.z, 2.f * v0.w);
        o.z = h2u(2.f * v1.x, 2.f * v1.y); o.w = h2u(2.f * v1.z, 2.f * v1.w);
        ((uint4*)g_xh)[i] = o;
    } else if (j < W13_U4 + 2 * X_U4) {
        size_t i = j - W13_U4 - X_U4;
        size_t n = i / (DM / 8);
        int d8 = (int)(i % (DM / 8)) * 8;
        const float* sp = mediator + d8;
        float4 v0 = *(const float4*)sp;
        float4 v1 = *(const float4*)(sp + 4);
        size_t base = (n * 3 + 2) * DM + d8;
        uint4 o;
        o.x = h2u(v0.x, v0.y); o.y = h2u(v0.z, v0.w);
        o.z = h2u(v1.x, v1.y); o.w = h2u(v1.z, v1.w);
        *(uint4*)(g_tokh + base) = o;
    }
}

// ---------------- all remaining weight cvts in ONE kernel ----------------
#define W2_U4  ((size_t)NE * DM * HF / 8)
#define IPW_U4 ((size_t)QKVW * DM / 8)
#define DD_U4  ((size_t)DM * DM / 8)
#define CVTW_TOTAL (W2_U4 + IPW_U4 + 4 * DD_U4)
__global__ void cvtw_all_kernel(const float* __restrict__ w2,
                                const float* __restrict__ ipw,
                                const float* __restrict__ ow,
                                const float* __restrict__ f1,
                                const float* __restrict__ f2,
                                const float* __restrict__ op) {
    size_t j = (size_t)blockIdx.x * 256 + threadIdx.x;
    if (j >= CVTW_TOTAL) return;
    const float* src;
    __half* dst;
    size_t i = j;
    if (i < W2_U4) { src = w2; dst = g_w2h; }
    else {
        i -= W2_U4;
        if (i < IPW_U4) { src = ipw; dst = g_ipwh; }
        else {
            i -= IPW_U4;
            if (i < DD_U4) { src = ow; dst = g_owh; }
            else {
                i -= DD_U4;
                if (i < DD_U4) { src = f1; dst = g_f1h; }
                else {
                    i -= DD_U4;
                    if (i < DD_U4) { src = f2; dst = g_f2h; }
                    else { i -= DD_U4; src = op; dst = g_oph; }
                }
            }
        }
    }
    const float* sp = src + i * 8;
    float4 v0 = *(const float4*)sp;
    float4 v1 = *(const float4*)(sp + 4);
    uint4 o;
    o.x = h2u(v0.x, v0.y); o.y = h2u(v0.z, v0.w);
    o.z = h2u(v1.x, v1.y); o.w = h2u(v1.z, v1.w);
    ((uint4*)dst)[i] = o;
}

// ---------------- small kernels ----------------
__global__ void zero_accum_kernel() {
    int t = threadIdx.x;
    if (t < NE) { g_router_sum[t] = 0.f; g_assign_sum[t] = 0.f; g_counts[t] = 0; g_fill[t] = 0; }
    if (t == 0) { g_z2 = 0.f; g_keepcnt = 0; }
}

__global__ void __launch_bounds__(256) gate_kernel(const float* __restrict__ x,
                                                   const float* __restrict__ gw,
                                                   float* __restrict__ out) {
    __shared__ float wsh[NE * DM];
    __shared__ float s_rs[NE], s_as[NE], s_z2s;
    __shared__ int   s_c[NE];
    int tid = threadIdx.x;
    for (int i = tid; i < NE * DM; i += 256) wsh[i] = gw[i];
    if (tid < NE) { s_rs[tid] = 0.f; s_as[tid] = 0.f; s_c[tid] = 0; }
    if (tid == 0) s_z2s = 0.f;
    __syncthreads();
    int warp = tid >> 5, lane = tid & 31;
    int n = blockIdx.x * 8 + warp;
    const float* xr = x + (size_t)n * DM;
    float xv[24];
    #pragma unroll
    for (int i = 0; i < 24; i++) xv[i] = xr[lane + i * 32];
    float l[NE];
    #pragma unroll
    for (int e = 0; e < NE; e++) {
        float sv = 0.f;
        const float* w = wsh + e * DM;
        #pragma unroll
        for (int i = 0; i < 24; i++) sv += xv[i] * w[lane + i * 32];
        #pragma unroll
        for (int o = 16; o; o >>= 1) sv += __shfl_xor_sync(0xffffffffu, sv, o);
        l[e] = sv;
    }
    if (lane == 0) {
        int i1 = 0; float v1 = l[0];
        #pragma unroll
        for (int e = 1; e < NE; e++) if (l[e] > v1) { v1 = l[e]; i1 = e; }
        int i2 = -1; float v2 = -3.4e38f;
        #pragma unroll
        for (int e = 0; e < NE; e++) if (e != i1 && l[e] > v2) { v2 = l[e]; i2 = e; }
        float e2 = expf(v2 - v1);
        float inv = 1.f / (1.f + e2);
        float p1 = inv, p2 = e2 * inv;
        float se = 0.f;
        #pragma unroll
        for (int e = 0; e < NE; e++) se += expf(l[e] - v1);
        float z = v1 + logf(se);
        #pragma unroll
        for (int e = 0; e < NE; e++) atomicAdd(&s_rs[e], expf(l[e] - v1) / se);
        atomicAdd(&s_as[i1], p1);
        atomicAdd(&s_as[i2], p2);
        atomicAdd(&s_z2s, z * z);
        atomicAdd(&s_c[i1], 1);
        atomicAdd(&s_c[i2], 1);
        g_te[2 * n] = i1; g_te[2 * n + 1] = i2;
        g_prio[2 * n] = v1; g_prio[2 * n + 1] = v2;
        g_tpk[2 * n] = p1; g_tpk[2 * n + 1] = p2;
        out[(size_t)NTOK * DM + 1 + 2 * n]     = (float)i1;
        out[(size_t)NTOK * DM + 1 + 2 * n + 1] = (float)i2;
    }
    __syncthreads();
    if (tid < NE) {
        atomicAdd(&g_router_sum[tid], s_rs[tid]);
        atomicAdd(&g_assign_sum[tid], s_as[tid]);
        atomicAdd(&g_counts[tid], s_c[tid]);
    }
    if (tid == 0) atomicAdd(&g_z2, s_z2s);
}

__global__ void build_tiles_kernel() {
    if (threadIdx.x != 0 || blockIdx.x != 0) return;
    int off = 0, nt = 0;
    for (int e = 0; e < NE; e++) {
        g_offsets[e] = off;
        int c = g_counts[e];
        int ntile = (c + 127) >> 7;
        for (int t = 0; t < ntile; t++) {
            g_tile_e[nt] = e;
            g_tile_r0[nt] = off + t * 128;
            int r = c - t * 128;
            g_tile_rows[nt] = r < 128 ? r : 128;
            nt++;
        }
        off += c;
    }
    g_ntiles = nt;
}

__global__ void scatter_kernel() {
    int i = blockIdx.x * 256 + threadIdx.x;
    if (i >= NKA) return;
    int e = g_te[i];
    int p = atomicAdd(&g_fill[e], 1);
    g_idx_list[g_offsets[e] + p] = i;
}

__global__ void keep_kernel() {
    int i = blockIdx.x * 256 + threadIdx.x;
    if (i >= NKA) return;
    int e = g_te[i];
    int kp;
    if (g_counts[e] <= CAPC) {
        kp = 1;
    } else {
        float pi = g_prio[i];
        int rank = 0;
        for (int j = 0; j < NKA; j++) {
            if (g_te[j] == e) {
                float pj = g_prio[j];
                if (pj > pi || (pj == pi && j < i)) rank++;
            }
        }
        kp = (rank < CAPC) ? 1 : 0;
    }
    g_keep[i] = (float)kp;
    atomicAdd(&g_keepcnt, kp);
}

// 2 tokens per block (8 warps), half2-vectorized; MED0: mediator qkv from g_qkvmed
template<bool MED0>
__global__ void __launch_bounds__(256) attn_kernel() {
    int warp = threadIdx.x >> 5, lane = threadIdx.x & 31;
    int n = blockIdx.x * 2 + (warp >> 2);
    int h = warp & 3;
    int hoff = h * 192 + lane * 6;
    float q[3][6], k[3][6], v[3][6];
    #pragma unroll
    for (int li = 0; li < 3; li++) {
        const __half* bp;
        if (MED0 && li == 2) bp = g_qkvmed + hoff;
        else bp = g_qkvh + (size_t)(n * 3 + li) * QKVW + hoff;
        #pragma unroll
        for (int seg = 0; seg < 3; seg++) {
            const __half* mp = bp + seg * DM;
            float2 p0 = __half22float2(*(const __half2*)(mp));
            float2 p1 = __half22float2(*(const __half2*)(mp + 2));
            float2 p2 = __half22float2(*(const __half2*)(mp + 4));
            float* d = (seg == 0) ? q[li] : (seg == 1) ? k[li] : v[li];
            d[0] = p0.x; d[1] = p0.y; d[2] = p1.x; d[3] = p1.y; d[4] = p2.x; d[5] = p2.y;
        }
    }
    const float scale = 0.07216878364870322f;
    float b0 = (g_keep[2 * n]     > 0.5f) ? 0.f : -1e9f;
    float b1 = (g_keep[2 * n + 1] > 0.5f) ? 0.f : -1e9f;
    float s[3][3];
    #pragma unroll
    for (int qi = 0; qi < 3; qi++) {
        #pragma unroll
        for (int kj = 0; kj < 3; kj++) {
            float t = 0.f;
            #pragma unroll
            for (int dd = 0; dd < 6; dd++) t += q[qi][dd] * k[kj][dd];
            #pragma unroll
            for (int o = 16; o; o >>= 1) t += __shfl_xor_sync(0xffffffffu, t, o);
            s[qi][kj] = t * scale;
        }
        s[qi][0] += b0;
        s[qi][1] += b1;
    }
    #pragma unroll
    for (int qi = 0; qi < 3; qi++) {
        float m = fmaxf(s[qi][0], fmaxf(s[qi][1], s[qi][2]));
        float e0 = expf(s[qi][0] - m), e1 = expf(s[qi][1] - m), e2 = expf(s[qi][2] - m);
        float inv = 1.f / (e0 + e1 + e2);
        float a0 = e0 * inv, a1 = e1 * inv, a2 = e2 * inv;
        __half* op = g_attnh + (size_t)(n * 3 + qi) * DM + hoff;
        #pragma unroll
        for (int p = 0; p < 3; p++) {
            float o0 = a0 * v[0][2 * p]     + a1 * v[1][2 * p]     + a2 * v[2][2 * p];
            float o1 = a0 * v[0][2 * p + 1] + a1 * v[1][2 * p + 1] + a2 * v[2][2 * p + 1];
            *(__half2*)(op + 2 * p) = __floats2half2_rn(o0, o1);
        }
    }
}

// rms over fp16 residual stream: tokh = rms(tokh,w1); uh = rms(tokh,w2)
__global__ void rms_dual_kernel(const float* __restrict__ w1, const float* __restrict__ w2) {
    __shared__ float sh[8];
    __shared__ float sscale;
    int m = blockIdx.x, tid = threadIdx.x;
    __half* row = g_tokh + (size_t)m * DM;
    float v0 = __half2float(row[tid]);
    float v1 = __half2float(row[tid + 256]);
    float v2 = __half2float(row[tid + 512]);
    float ss = v0 * v0 + v1 * v1 + v2 * v2;
    #pragma unroll
    for (int o = 16; o; o >>= 1) ss += __shfl_xor_sync(0xffffffffu, ss, o);
    if ((tid & 31) == 0) sh[tid >> 5] = ss;
    __syncthreads();
    if (tid == 0) {
        float t = 0.f;
        #pragma unroll
        for (int i = 0; i < 8; i++) t += sh[i];
        sscale = rsqrtf(t * (1.f / DM) + 1e-6f);
    }
    __syncthreads();
    float s1 = sscale;
    float t0 = v0 * s1 * w1[tid];
    float t1 = v1 * s1 * w1[tid + 256];
    float t2 = v2 * s1 * w1[tid + 512];
    row[tid]       = __float2half_rn(t0);
    row[tid + 256] = __float2half_rn(t1);
    row[tid + 512] = __float2half_rn(t2);
    float ss2 = t0 * t0 + t1 * t1 + t2 * t2;
    #pragma unroll
    for (int o = 16; o; o >>= 1) ss2 += __shfl_xor_sync(0xffffffffu, ss2, o);
    __syncthreads();
    if ((tid & 31) == 0) sh[tid >> 5] = ss2;
    __syncthreads();
    if (tid == 0) {
        float t = 0.f;
        #pragma unroll
        for (int i = 0; i < 8; i++) t += sh[i];
        sscale = rsqrtf(t * (1.f / DM) + 1e-6f);
    }
    __syncthreads();
    float s2 = sscale;
    __half* ur = g_uh + (size_t)m * DM;
    ur[tid]       = __float2half_rn(t0 * s2 * w2[tid]);
    ur[tid + 256] = __float2half_rn(t1 * s2 * w2[tid + 256]);
    ur[tid + 512] = __float2half_rn(t2 * s2 * w2[tid + 512]);
}

// fuse_prep + aux (fp16 token reads)
__global__ void fuse_prep_kernel(const float* __restrict__ fgw, const float* __restrict__ fgb,
                                 float* __restrict__ out) {
    __shared__ float sh[8];
    __shared__ float par[3];
    int n = blockIdx.x, tid = threadIdx.x;
    const __half* med = g_tokh + ((size_t)n * 3 + 2) * DM;
    float s = __half2float(med[tid]) * fgw[tid]
            + __half2float(med[tid + 256]) * fgw[tid + 256]
            + __half2float(med[tid + 512]) * fgw[tid + 512];
    #pragma unroll
    for (int o = 16; o; o >>= 1) s += __shfl_xor_sync(0xffffffffu, s, o);
    if ((tid & 31) == 0) sh[tid >> 5] = s;
    __syncthreads();
    if (tid == 0) {
        float t = 0.f;
        #pragma unroll
        for (int i = 0; i < 8; i++) t += sh[i];
        float g = 1.f / (1.f + expf(-(t + fgb[0])));
        float tp0 = g_tpk[2 * n] * g_keep[2 * n];
        float tp1 = g_tpk[2 * n + 1] * g_keep[2 * n + 1];
        float den = tp0 + tp1;
        par[0] = g;
        par[1] = den > 0.f ? tp0 / den : 0.f;
        par[2] = den > 0.f ? tp1 / den : 0.f;
        if (n == 0) {
            float bal = 0.f;
            for (int e = 0; e < NE; e++)
                bal += (g_router_sum[e] / (float)NTOK) * (g_assign_sum[e] / (float)NTOK);
            bal *= (float)NE;
            out[(size_t)NTOK * DM] = 0.01f * bal + 0.001f * (g_z2 / (float)NTOK)
                + 0.001f * (1.f - (float)g_keepcnt / (float)NKA);
        }
    }
    __syncthreads();
    float g = par[0], w0 = par[1], w1 = par[2];
    const __half* e0 = g_tokh + ((size_t)n * 3 + 0) * DM;
    const __half* e1 = g_tokh + ((size_t)n * 3 + 1) * DM;
    __half* fm = g_fmh + (size_t)n * DM;
    #pragma unroll
    for (int c = 0; c < 3; c++) {
        int d = tid + c * 256;
        float mv = __half2float(med[d]);
        float a = w0 * __half2float(e0[d]) + w1 * __half2float(e1[d]);
        fm[d] = __float2half_rn(g * mv + (1.f - g) * a);
    }
}

// ---------------- launch ----------------
extern "C" void kernel_launch(void* const* d_in, const int* in_sizes, int n_in,
                              void* d_out, int out_size) {
    const float* x          = (const float*)d_in[0];
    const float* gate_w     = (const float*)d_in[1];
    const float* w13        = (const float*)d_in[2];
    const float* w2         = (const float*)d_in[3];
    const float* in_proj_w  = (const float*)d_in[4];
    const float* in_proj_b  = (const float*)d_in[5];
    const float* out_w      = (const float*)d_in[6];
    const float* out_b      = (const float*)d_in[7];
    const float* norm1_w    = (const float*)d_in[8];
    const float* norm2_w    = (const float*)d_in[9];
    const float* ffn_w1     = (const float*)d_in[10];
    const float* ffn_w2     = (const float*)d_in[11];
    const float* mediator   = (const float*)d_in[12];
    const float* fuse_gate_w= (const float*)d_in[13];
    const float* fuse_gate_b= (const float*)d_in[14];
    const float* o_proj_w   = (const float*)d_in[15];
    float* out = (float*)d_out;

    __half *p_tokh, *p_ipwh, *p_owh, *p_f1h, *p_f2h, *p_oph;
    __half *p_qkvh, *p_attnh, *p_uh, *p_hh, *p_fmh;
    cudaGetSymbolAddress((void**)&p_tokh, g_tokh);
    cudaGetSymbolAddress((void**)&p_ipwh, g_ipwh);
    cudaGetSymbolAddress((void**)&p_owh, g_owh);
    cudaGetSymbolAddress((void**)&p_f1h, g_f1h);
    cudaGetSymbolAddress((void**)&p_f2h, g_f2h);
    cudaGetSymbolAddress((void**)&p_oph, g_oph);
    cudaGetSymbolAddress((void**)&p_qkvh, g_qkvh);
    cudaGetSymbolAddress((void**)&p_attnh, g_attnh);
    cudaGetSymbolAddress((void**)&p_uh, g_uh);
    cudaGetSymbolAddress((void**)&p_hh, g_hh);
    cudaGetSymbolAddress((void**)&p_fmh, g_fmh);

    cudaFuncSetAttribute(gemm_h<true,  false, false, true >, cudaFuncAttributeMaxDynamicSharedMemorySize, SMEMB);
    cudaFuncSetAttribute(gemm_h<true,  true,  false, true >, cudaFuncAttributeMaxDynamicSharedMemorySize, SMEMB);
    cudaFuncSetAttribute(gemm_h<false, false, true,  true >, cudaFuncAttributeMaxDynamicSharedMemorySize, SMEMB);
    cudaFuncSetAttribute(gemm_h<false, true,  false, true >, cudaFuncAttributeMaxDynamicSharedMemorySize, SMEMB);
    cudaFuncSetAttribute(gemm_h<false, false, false, false>, cudaFuncAttributeMaxDynamicSharedMemorySize, SMEMB);
    cudaFuncSetAttribute(gemm_qkv0, cudaFuncAttributeMaxDynamicSharedMemorySize, SMEMB);
    cudaFuncSetAttribute(expA_h, cudaFuncAttributeMaxDynamicSharedMemorySize, SMEMB);
    cudaFuncSetAttribute(expB_h, cudaFuncAttributeMaxDynamicSharedMemorySize, SMEMB);

    // fork a side stream inside the capture for the independent cvt work
    cudaStream_t s2;
    cudaStreamCreateWithFlags(&s2, cudaStreamNonBlocking);
    cudaEvent_t evF, evJ;
    cudaEventCreateWithFlags(&evF, cudaEventDisableTiming);
    cudaEventCreateWithFlags(&evJ, cudaEventDisableTiming);

    cudaEventRecord(evF, 0);
    cudaStreamWaitEvent(s2, evF, 0);
    cvt_combined_kernel<<<(int)((W13_U4 + 2 * X_U4 + 255) / 256), 256, 0, s2>>>(w13, x, mediator);
    cvtw_all_kernel<<<(int)((CVTW_TOTAL + 255) / 256), 256, 0, s2>>>(
        w2, in_proj_w, out_w, ffn_w1, ffn_w2, o_proj_w);
    cudaEventRecord(evJ, s2);

    zero_accum_kernel<<<1, 32>>>();
    gate_kernel<<<NTOK / 8, 256>>>(x, gate_w, out);
    build_tiles_kernel<<<1, 1>>>();
    scatter_kernel<<<NKA / 256, 256>>>();
    keep_kernel<<<NKA / 256, 256>>>();

    cudaStreamWaitEvent(0, evJ, 0);

    expA_h<<<dim3(MAXT, 2 * HF / 128), 256, SMEMB>>>();
    expB_h<<<dim3(MAXT, DM / 128), 256, SMEMB>>>(x);

    // ---- step 0: mediator QKV computed once ----
    med_qkv_kernel<<<QKVW / 8, 256>>>(in_proj_b);
    gemm_qkv0<<<dim3(NKA / 128, QKVW / 128), 256, SMEMB>>>(in_proj_b);
    attn_kernel<true><<<NTOK / 2, 256>>>();
    gemm_h<true, true, false, true><<<dim3(MROW / 128, DM / 128), 256, SMEMB>>>(
        p_attnh, p_owh, out_b, p_tokh, p_tokh, DM, DM);
    rms_dual_kernel<<<MROW, 256>>>(norm1_w, norm2_w);
    gemm_h<false, false, true, true><<<dim3(MROW / 128, DM / 128), 256, SMEMB>>>(
        p_uh, p_f1h, nullptr, nullptr, p_hh, DM, DM);
    gemm_h<false, true, false, true><<<dim3(MROW / 128, DM / 128), 256, SMEMB>>>(
        p_hh, p_f2h, nullptr, p_tokh, p_tokh, DM, DM);

    // ---- step 1: full path ----
    gemm_h<true, false, false, true><<<dim3(MROW / 128, QKVW / 128), 256, SMEMB>>>(
        p_tokh, p_ipwh, in_proj_b, nullptr, p_qkvh, QKVW, DM);
    attn_kernel<false><<<NTOK / 2, 256>>>();
    gemm_h<true, true, false, true><<<dim3(MROW / 128, DM / 128), 256, SMEMB>>>(
        p_attnh, p_owh, out_b, p_tokh, p_tokh, DM, DM);
    rms_dual_kernel<<<MROW, 256>>>(norm1_w, norm2_w);
    gemm_h<false, false, true, true><<<dim3(MROW / 128, DM / 128), 256, SMEMB>>>(
        p_uh, p_f1h, nullptr, nullptr, p_hh, DM, DM);
    gemm_h<false, true, false, true><<<dim3(MROW / 128, DM / 128), 256, SMEMB>>>(
        p_hh, p_f2h, nullptr, p_tokh, p_tokh, DM, DM);

    fuse_prep_kernel<<<NTOK, 256>>>(fuse_gate_w, fuse_gate_b, out);
    gemm_h<false, false, false, false><<<dim3(NTOK / 128, DM / 128), 256, SMEMB>>>(
        p_fmh, p_oph, nullptr, nullptr, out, DM, DM);
}